// round 6
// baseline (speedup 1.0000x reference)
#include <cuda_runtime.h>
#include <cuda_bf16.h>
#include <cstdint>

#define NNODES 50000
#define NEDGE  800000
#define ETOT   850000
#define DIM    128
#define NH     4
#define NB     7
#define KDIM   1024
#define NGR    64
#define NCLS   10
#define NLAYER 3

#define MTILES ((NNODES + 127) / 128)   // 391
#define SCAN_BLOCKS ((NNODES + 1023) / 1024)  // 49

// ---------------- device scratch ----------------
__device__ __align__(16) __nv_bfloat16 g_Wh[NLAYER * KDIM * DIM];
__device__ __align__(16) __nv_bfloat16 g_Wl[NLAYER * KDIM * DIM];
__device__ __align__(16) float g_h[NNODES * DIM];
__device__ __align__(16) float g_hl[NNODES * DIM];
__device__ __align__(16) float g_asrc[NNODES * NH];
__device__ __align__(16) float g_adst[NNODES * NH];
__device__ __align__(16) float g_pooled[NGR * DIM];
// CSR
__device__ int g_deg[NNODES];
__device__ int g_ptr[NNODES + 1];
__device__ int g_cur[NNODES];
__device__ int g_csrc[ETOT];
__device__ int g_bsum[SCAN_BLOCKS];
__device__ int g_boff[SCAN_BLOCKS];

// ---------------- helpers ----------------
__device__ __forceinline__ uint32_t smem_u32(const void* p) {
    uint32_t a;
    asm("{ .reg .u64 t; cvta.to.shared.u64 t, %1; cvt.u32.u64 %0, t; }" : "=r"(a) : "l"(p));
    return a;
}

#define SWZ(c, row) (((c) ^ ((row) & 7) ^ (((row) >> 3) & 3)) & 7)

__device__ __forceinline__ void ldsm4(uint32_t a, uint32_t& r0, uint32_t& r1,
                                      uint32_t& r2, uint32_t& r3) {
    asm volatile("ldmatrix.sync.aligned.m8n8.x4.shared.b16 {%0,%1,%2,%3}, [%4];"
                 : "=r"(r0), "=r"(r1), "=r"(r2), "=r"(r3) : "r"(a));
}

__device__ __forceinline__ void mma16816(float* d, const uint32_t* a, const uint32_t* b) {
    asm volatile("mma.sync.aligned.m16n8k16.row.col.f32.bf16.bf16.f32 "
                 "{%0,%1,%2,%3}, {%4,%5,%6,%7}, {%8,%9}, {%0,%1,%2,%3};"
                 : "+f"(d[0]), "+f"(d[1]), "+f"(d[2]), "+f"(d[3])
                 : "r"(a[0]), "r"(a[1]), "r"(a[2]), "r"(a[3]), "r"(b[0]), "r"(b[1]));
}

__device__ __forceinline__ float silu_f(float x) { return x / (1.0f + __expf(-x)); }

// Closed-form cardinal cubic B-splines on uniform grid [-2.5, 2.5], h=0.5.
// u = 2x+5 in [0,10): cell c, frac t. Nonzero bases: out[c-m], m=0..3.
__device__ __forceinline__ void bsplines7(float x, float* out) {
    float u = fmaf(2.0f, x, 5.0f);
    float cf = floorf(u);
    float t = u - cf;
    int c = (u >= 0.0f && u < 10.0f) ? (int)cf : -100;
    float t2 = t * t;
    float t3 = t2 * t;
    float s = 1.0f - t;
    const float i6 = 1.0f / 6.0f;
    float w3 = t3 * i6;                                   // m == 0 (j == c)
    float w2 = fmaf(3.0f, t3 + t, fmaf(3.0f, t2, 1.0f) - 6.0f * t3) * i6; // placeholder
    // compute properly:
    w2 = (-3.0f * t3 + 3.0f * t2 + 3.0f * t + 1.0f) * i6; // m == 1
    float w1 = (3.0f * t3 - 6.0f * t2 + 4.0f) * i6;       // m == 2
    float w0 = s * s * s * i6;                            // m == 3
#pragma unroll
    for (int j = 0; j < 7; j++) {
        int m = c - j;
        float r = (m == 0) ? w3 : (m == 1) ? w2 : (m == 2) ? w1 : (m == 3) ? w0 : 0.0f;
        out[j] = r;
    }
}

__device__ __forceinline__ uint32_t pack_hilo(float a, float b, uint32_t& lo) {
    uint32_t hp;
    asm("cvt.rn.bf16x2.f32 %0, %1, %2;" : "=r"(hp) : "f"(b), "f"(a));
    float ha = __uint_as_float(hp << 16);
    float hb = __uint_as_float(hp & 0xFFFF0000u);
    float la = a - ha, lb = b - hb;
    asm("cvt.rn.bf16x2.f32 %0, %1, %2;" : "=r"(lo) : "f"(lb), "f"(la));
    return hp;
}

// ---------------- CSR build ----------------
__global__ void deg_count_kernel(const int* __restrict__ ei) {
    int e = blockIdx.x * blockDim.x + threadIdx.x;
    if (e >= ETOT) return;
    int d = (e < NEDGE) ? __ldg(&ei[NEDGE + e]) : (e - NEDGE);
    atomicAdd(&g_deg[d], 1);
}

__global__ void scan1_kernel() {
    __shared__ int sh[1024];
    int t = threadIdx.x, b = blockIdx.x;
    int i = b * 1024 + t;
    int v = (i < NNODES) ? g_deg[i] : 0;
    sh[t] = v;
    __syncthreads();
#pragma unroll
    for (int off = 1; off < 1024; off <<= 1) {
        int add = (t >= off) ? sh[t - off] : 0;
        __syncthreads();
        sh[t] += add;
        __syncthreads();
    }
    if (i < NNODES) g_ptr[i] = sh[t] - v;
    if (t == 1023) g_bsum[b] = sh[t];
}

__global__ void scan2_kernel() {
    if (threadIdx.x == 0) {
        int run = 0;
        for (int b = 0; b < SCAN_BLOCKS; b++) { g_boff[b] = run; run += g_bsum[b]; }
        g_ptr[NNODES] = run;
    }
}

__global__ void scan3_kernel() {
    int t = threadIdx.x, b = blockIdx.x;
    int i = b * 1024 + t;
    if (i < NNODES) {
        int p = g_ptr[i] + g_boff[b];
        g_ptr[i] = p;
        g_cur[i] = p;
    }
}

__global__ void scatter_kernel(const int* __restrict__ ei) {
    int e = blockIdx.x * blockDim.x + threadIdx.x;
    if (e >= ETOT) return;
    int s, d;
    if (e < NEDGE) { s = __ldg(&ei[e]); d = __ldg(&ei[NEDGE + e]); }
    else           { s = e - NEDGE; d = s; }
    int pos = atomicAdd(&g_cur[d], 1);
    g_csrc[pos] = s;
}

// ---------------- weight pack (all 3 layers at once) ----------------
__global__ void pack_w_kernel(const float* __restrict__ bw,
                              const float* __restrict__ sw,
                              const float* __restrict__ sc) {
    int idx = blockIdx.x * blockDim.x + threadIdx.x;
    if (idx >= NLAYER * KDIM * DIM) return;
    int l = idx >> 17;                 // / (KDIM*DIM) = 131072
    int rem = idx & (KDIM * DIM - 1);
    int n = rem >> 10, k = rem & 1023;
    int j = k >> 3, f = k & 7;
    const float* bwl = bw + (size_t)l * DIM * DIM;
    const float* swl = sw + (size_t)l * DIM * DIM * NB;
    const float* scl = sc + (size_t)l * DIM * DIM;
    float v;
    if (f == 0) v = bwl[n * DIM + j];
    else        v = swl[(n * DIM + j) * NB + (f - 1)] * scl[n * DIM + j];
    __nv_bfloat16 h = __float2bfloat16_rn(v);
    g_Wh[idx] = h;
    g_Wl[idx] = __float2bfloat16_rn(v - __bfloat162float(h));
}

// ---------------- fused KAN-GEMM (bf16 mma.sync, 3-product split) ----------------
#define SMEM_BYTES 65536

__global__ void __launch_bounds__(256, 2) fkan_gemm_mma(const float* __restrict__ in,
                                                        const float* __restrict__ attS,
                                                        const float* __restrict__ attD,
                                                        const __nv_bfloat16* __restrict__ Wh,
                                                        const __nv_bfloat16* __restrict__ Wl) {
    extern __shared__ char dsm[];
    char* sAh = dsm;
    char* sAl = dsm + 16384;
    char* sBh = dsm + 32768;
    char* sBl = dsm + 49152;

    int tid = threadIdx.x;
    int wid = tid >> 5, lane = tid & 31;
    int m0 = blockIdx.x * 128;
    int warpM = wid & 3, warpN = wid >> 2;

    uint32_t uAh = smem_u32(sAh), uAl = smem_u32(sAl);
    uint32_t uBh = smem_u32(sBh), uBl = smem_u32(sBl);

    float acc[2][8][4];
#pragma unroll
    for (int f = 0; f < 2; f++)
#pragma unroll
        for (int j = 0; j < 8; j++)
#pragma unroll
            for (int q = 0; q < 4; q++) acc[f][j][q] = 0.0f;

    int rowb = tid & 127;
    int cq = (tid >> 7) * 4;
    bool rvalid = (m0 + rowb) < NNODES;
    int tg = lane >> 3, tr = lane & 7;

    for (int cc = 0; cc < 16; cc++) {
        float4 xv4 = rvalid ? *(const float4*)(in + (size_t)(m0 + rowb) * DIM + cc * 8 + cq)
                            : make_float4(0.f, 0.f, 0.f, 0.f);
        const uint4* wsrc_h = (const uint4*)(Wh + rowb * KDIM + cc * 64 + cq * 8);
        const uint4* wsrc_l = (const uint4*)(Wl + rowb * KDIM + cc * 64 + cq * 8);
#pragma unroll
        for (int q = 0; q < 4; q++) {
            float xv = (q == 0) ? xv4.x : (q == 1) ? xv4.y : (q == 2) ? xv4.z : xv4.w;
            float fv[8];
            fv[0] = silu_f(xv);
            bsplines7(xv, fv + 1);
            uint4 uh, ul;
            uh.x = pack_hilo(fv[0], fv[1], ul.x);
            uh.y = pack_hilo(fv[2], fv[3], ul.y);
            uh.z = pack_hilo(fv[4], fv[5], ul.z);
            uh.w = pack_hilo(fv[6], fv[7], ul.w);
            int c = cq + q;
            uint32_t off = rowb * 128 + (SWZ(c, rowb) << 4);
            *(uint4*)(sAh + off) = uh;
            *(uint4*)(sAl + off) = ul;
            *(uint4*)(sBh + off) = wsrc_h[q];
            *(uint4*)(sBl + off) = wsrc_l[q];
        }
        __syncthreads();

#pragma unroll
        for (int ks = 0; ks < 4; ks++) {
            uint32_t ah[2][4], al[2][4];
#pragma unroll
            for (int f = 0; f < 2; f++) {
                int arow = warpM * 32 + f * 16 + (tg & 1) * 8 + tr;
                int acol = ks * 2 + (tg >> 1);
                uint32_t aoff = arow * 128 + (SWZ(acol, arow) << 4);
                ldsm4(uAh + aoff, ah[f][0], ah[f][1], ah[f][2], ah[f][3]);
                ldsm4(uAl + aoff, al[f][0], al[f][1], al[f][2], al[f][3]);
            }
#pragma unroll
            for (int gh = 0; gh < 2; gh++) {
                uint32_t bh[2][4], bl[2][4];
#pragma unroll
                for (int gg = 0; gg < 2; gg++) {
                    int g = gh * 2 + gg;
                    int brow = warpN * 64 + g * 16 + (tg >> 1) * 8 + tr;
                    int bcol = ks * 2 + (tg & 1);
                    uint32_t boff = brow * 128 + (SWZ(bcol, brow) << 4);
                    ldsm4(uBh + boff, bh[gg][0], bh[gg][1], bh[gg][2], bh[gg][3]);
                    ldsm4(uBl + boff, bl[gg][0], bl[gg][1], bl[gg][2], bl[gg][3]);
                }
#pragma unroll
                for (int f = 0; f < 2; f++)
#pragma unroll
                    for (int gg = 0; gg < 2; gg++) {
                        int g = gh * 2 + gg;
                        mma16816(acc[f][2 * g],     ah[f], &bh[gg][0]);
                        mma16816(acc[f][2 * g],     al[f], &bh[gg][0]);
                        mma16816(acc[f][2 * g],     ah[f], &bl[gg][0]);
                        mma16816(acc[f][2 * g + 1], ah[f], &bh[gg][2]);
                        mma16816(acc[f][2 * g + 1], al[f], &bh[gg][2]);
                        mma16816(acc[f][2 * g + 1], ah[f], &bl[gg][2]);
                    }
            }
        }
        __syncthreads();
    }

    // epilogue: store h + fused attention dots
    int qd = lane >> 2, ql = lane & 3;
#pragma unroll
    for (int f = 0; f < 2; f++)
#pragma unroll
        for (int hh = 0; hh < 2; hh++) {
            int row = m0 + warpM * 32 + f * 16 + hh * 8 + qd;
            bool ok = row < NNODES;
            float ps0 = 0.f, pd0 = 0.f, ps1 = 0.f, pd1 = 0.f;
#pragma unroll
            for (int j = 0; j < 8; j++) {
                int col = warpN * 64 + j * 8 + ql * 2;
                float v0 = acc[f][j][hh * 2 + 0];
                float v1 = acc[f][j][hh * 2 + 1];
                if (ok) {
                    float2 st = make_float2(v0, v1);
                    *(float2*)&g_hl[(size_t)row * DIM + col] = st;
                }
                float s0 = __ldg(&attS[col]), s1 = __ldg(&attS[col + 1]);
                float d0 = __ldg(&attD[col]), d1 = __ldg(&attD[col + 1]);
                float ps = v0 * s0 + v1 * s1;
                float pd = v0 * d0 + v1 * d1;
                if (j < 4) { ps0 += ps; pd0 += pd; } else { ps1 += ps; pd1 += pd; }
            }
#pragma unroll
            for (int o = 1; o <= 2; o <<= 1) {
                ps0 += __shfl_xor_sync(0xffffffffu, ps0, o);
                pd0 += __shfl_xor_sync(0xffffffffu, pd0, o);
                ps1 += __shfl_xor_sync(0xffffffffu, ps1, o);
                pd1 += __shfl_xor_sync(0xffffffffu, pd1, o);
            }
            if (ql == 0 && ok) {
                int hbase = warpN * 2;
                g_asrc[row * 4 + hbase]     = ps0;
                g_asrc[row * 4 + hbase + 1] = ps1;
                g_adst[row * 4 + hbase]     = pd0;
                g_adst[row * 4 + hbase + 1] = pd1;
            }
        }
}

// ---------------- fused pull-mode edge phase ----------------
__global__ void __launch_bounds__(256) edge_fused_kernel(const float* __restrict__ bias) {
    int gid = blockIdx.x * blockDim.x + threadIdx.x;
    int n = gid >> 5, lane = gid & 31;
    if (n >= NNODES) return;
    int start = __ldg(&g_ptr[n]);
    int end   = __ldg(&g_ptr[n + 1]);
    int hh = lane >> 3;
    float bd = g_adst[n * 4 + hh];

    float4 acc = make_float4(0.f, 0.f, 0.f, 0.f);
    float sumex = 0.0f;

    for (int j0 = start; j0 < end; j0 += 32) {
        int m = min(32, end - j0);
        int s_pref = (j0 + lane < end) ? __ldg(&g_csrc[j0 + lane]) : 0;
#pragma unroll 4
        for (int i = 0; i < m; i++) {
            int s = __shfl_sync(0xffffffffu, s_pref, i);
            float a = __ldg(&g_asrc[s * 4 + hh]);
            float e = a + bd;
            e = (e > 0.f) ? e : 0.2f * e;
            float ex = __expf(e);
            sumex += ex;
            float4 v = *(const float4*)&g_hl[(size_t)s * DIM + lane * 4];
            acc.x = fmaf(ex, v.x, acc.x);
            acc.y = fmaf(ex, v.y, acc.y);
            acc.z = fmaf(ex, v.z, acc.z);
            acc.w = fmaf(ex, v.w, acc.w);
        }
    }
    float inv = 1.0f / (sumex + 1e-16f);
    float4 b4 = *(const float4*)&bias[lane * 4];
    float4 o;
    o.x = silu_f(acc.x * inv + b4.x);
    o.y = silu_f(acc.y * inv + b4.y);
    o.z = silu_f(acc.z * inv + b4.z);
    o.w = silu_f(acc.w * inv + b4.w);
    *(float4*)&g_h[(size_t)n * DIM + lane * 4] = o;
}

// ---------------- pooling + readout ----------------
__global__ void pool_kernel(const int* __restrict__ batch) {
    int d0 = threadIdx.x;
    int r0 = blockIdx.x * 512;
    if (r0 >= NNODES) return;
    int rend = min(r0 + 512, NNODES);
    int cur = __ldg(&batch[r0]);
    float sum = 0.0f;
    for (int n = r0; n < rend; n++) {
        int g = __ldg(&batch[n]);
        if (g != cur) {
            atomicAdd(&g_pooled[cur * DIM + d0], sum);
            sum = 0.0f;
            cur = g;
        }
        sum += g_h[(size_t)n * DIM + d0];
    }
    atomicAdd(&g_pooled[cur * DIM + d0], sum);
}

__global__ void readout_kernel(const float* __restrict__ bw,
                               const float* __restrict__ sw,
                               const float* __restrict__ sc,
                               float* __restrict__ out) {
    __shared__ float feat[KDIM];
    __shared__ float sred[NCLS * 4];
    int g = blockIdx.x, t = threadIdx.x;
    float xv = g_pooled[g * DIM + t];
    feat[t] = xv / (1.0f + expf(-xv));
    float bs[7];
    bsplines7(xv, bs);
#pragma unroll
    for (int b = 0; b < 7; b++) feat[DIM + t * 7 + b] = bs[b];
    __syncthreads();

    float accv[NCLS];
#pragma unroll
    for (int o = 0; o < NCLS; o++) accv[o] = 0.0f;
#pragma unroll
    for (int kk = 0; kk < 8; kk++) {
        int k = kk * DIM + t;
        float f = feat[k];
        if (k < DIM) {
#pragma unroll
            for (int o = 0; o < NCLS; o++) accv[o] += f * bw[o * DIM + k];
        } else {
            int j = (k - DIM) / 7, b = (k - DIM) % 7;
#pragma unroll
            for (int o = 0; o < NCLS; o++)
                accv[o] += f * sw[o * DIM * NB + j * NB + b] * sc[o * DIM + j];
        }
    }
    int lane = t & 31, warp = t >> 5;
#pragma unroll
    for (int o = 0; o < NCLS; o++) {
        float v = accv[o];
#pragma unroll
        for (int off = 16; off >= 1; off >>= 1) v += __shfl_xor_sync(0xffffffffu, v, off);
        if (lane == 0) sred[o * 4 + warp] = v;
    }
    __syncthreads();
    if (t == 0) {
        float lg[NCLS];
        float mx = -1e30f;
#pragma unroll
        for (int o = 0; o < NCLS; o++) {
            lg[o] = sred[o * 4] + sred[o * 4 + 1] + sred[o * 4 + 2] + sred[o * 4 + 3];
            mx = fmaxf(mx, lg[o]);
        }
        float se = 0.0f;
#pragma unroll
        for (int o = 0; o < NCLS; o++) se += expf(lg[o] - mx);
        float lse = logf(se) + mx;
#pragma unroll
        for (int o = 0; o < NCLS; o++) out[g * NCLS + o] = lg[o] - lse;
    }
}

// ---------------- launch ----------------
extern "C" void kernel_launch(void* const* d_in, const int* in_sizes, int n_in,
                              void* d_out, int out_size) {
    const float* x        = (const float*)d_in[0];
    const int*   ei       = (const int*)d_in[1];
    const int*   batch    = (const int*)d_in[2];
    const float* base_w   = (const float*)d_in[3];
    const float* spline_w = (const float*)d_in[4];
    const float* scaler   = (const float*)d_in[5];
    const float* att_src  = (const float*)d_in[6];
    const float* att_dst  = (const float*)d_in[7];
    const float* bias     = (const float*)d_in[8];
    const float* ro_bw    = (const float*)d_in[9];
    const float* ro_sw    = (const float*)d_in[10];
    const float* ro_sc    = (const float*)d_in[11];
    float* out = (float*)d_out;

    cudaFuncSetAttribute(fkan_gemm_mma, cudaFuncAttributeMaxDynamicSharedMemorySize, SMEM_BYTES);

    float *hbuf = nullptr, *poolp = nullptr;
    int* degp = nullptr;
    __nv_bfloat16 *whp = nullptr, *wlp = nullptr;
    cudaGetSymbolAddress((void**)&hbuf, g_h);
    cudaGetSymbolAddress((void**)&poolp, g_pooled);
    cudaGetSymbolAddress((void**)&degp, g_deg);
    cudaGetSymbolAddress((void**)&whp, g_Wh);
    cudaGetSymbolAddress((void**)&wlp, g_Wl);

    const int E_BLOCKS = (ETOT + 255) / 256;

    // ---- weight pack (all layers) + CSR build ----
    pack_w_kernel<<<(NLAYER * KDIM * DIM + 255) / 256, 256>>>(base_w, spline_w, scaler);
    cudaMemsetAsync(degp, 0, NNODES * sizeof(int));
    deg_count_kernel<<<E_BLOCKS, 256>>>(ei);
    scan1_kernel<<<SCAN_BLOCKS, 1024>>>();
    scan2_kernel<<<1, 32>>>();
    scan3_kernel<<<SCAN_BLOCKS, 1024>>>();
    scatter_kernel<<<E_BLOCKS, 256>>>(ei);

    for (int l = 0; l < NLAYER; l++) {
        const float* in = (l == 0) ? x : hbuf;
        fkan_gemm_mma<<<MTILES, 256, SMEM_BYTES>>>(
            in, att_src + (size_t)l * DIM, att_dst + (size_t)l * DIM,
            whp + (size_t)l * KDIM * DIM, wlp + (size_t)l * KDIM * DIM);
        edge_fused_kernel<<<(NNODES * 32 + 255) / 256, 256>>>(bias + (size_t)l * DIM);
    }
    cudaMemsetAsync(poolp, 0, (size_t)NGR * DIM * sizeof(float));
    pool_kernel<<<(NNODES + 511) / 512, DIM>>>(batch);
    readout_kernel<<<NGR, DIM>>>(ro_bw, ro_sw, ro_sc, out);
}

// round 7
// speedup vs baseline: 1.0361x; 1.0361x over previous
#include <cuda_runtime.h>
#include <cuda_bf16.h>
#include <cstdint>

#define NNODES 50000
#define NEDGE  800000
#define ETOT   850000
#define DIM    128
#define NH     4
#define NB     7
#define KDIM   1024
#define NGR    64
#define NCLS   10
#define NLAYER 3

#define MTILES ((NNODES + 127) / 128)   // 391
#define SCAN_BLOCKS ((NNODES + 1023) / 1024)  // 49

// ---------------- device scratch ----------------
__device__ __align__(16) __nv_bfloat16 g_Wh[NLAYER * KDIM * DIM];
__device__ __align__(16) __nv_bfloat16 g_Wl[NLAYER * KDIM * DIM];
__device__ __align__(16) float g_h[NNODES * DIM];
__device__ __align__(16) float g_hl[NNODES * DIM];
__device__ __align__(16) float g_asrc[NNODES * NH];
__device__ __align__(16) float g_adst[NNODES * NH];
__device__ __align__(16) float g_pooled[NGR * DIM];
// CSR
__device__ int g_deg[NNODES];
__device__ int g_ptr[NNODES + 1];
__device__ int g_cur[NNODES];
__device__ int g_csrc[ETOT];
__device__ int g_bsum[SCAN_BLOCKS];
__device__ int g_boff[SCAN_BLOCKS];

// ---------------- helpers ----------------
__device__ __forceinline__ uint32_t smem_u32(const void* p) {
    uint32_t a;
    asm("{ .reg .u64 t; cvta.to.shared.u64 t, %1; cvt.u32.u64 %0, t; }" : "=r"(a) : "l"(p));
    return a;
}

// 16B-chunk swizzle within a 64B row (4 chunks): conflict-free for stores + ldmatrix
#define SWZ32(c, r) (((c) ^ ((r) >> 1)) & 3)

__device__ __forceinline__ void ldsm4(uint32_t a, uint32_t& r0, uint32_t& r1,
                                      uint32_t& r2, uint32_t& r3) {
    asm volatile("ldmatrix.sync.aligned.m8n8.x4.shared.b16 {%0,%1,%2,%3}, [%4];"
                 : "=r"(r0), "=r"(r1), "=r"(r2), "=r"(r3) : "r"(a));
}

__device__ __forceinline__ void mma16816(float* d, const uint32_t* a, const uint32_t* b) {
    asm volatile("mma.sync.aligned.m16n8k16.row.col.f32.bf16.bf16.f32 "
                 "{%0,%1,%2,%3}, {%4,%5,%6,%7}, {%8,%9}, {%0,%1,%2,%3};"
                 : "+f"(d[0]), "+f"(d[1]), "+f"(d[2]), "+f"(d[3])
                 : "r"(a[0]), "r"(a[1]), "r"(a[2]), "r"(a[3]), "r"(b[0]), "r"(b[1]));
}

__device__ __forceinline__ float silu_f(float x) { return x / (1.0f + __expf(-x)); }

// Closed-form cardinal cubic B-splines on uniform grid [-2.5, 2.5], h=0.5.
__device__ __forceinline__ void bsplines7(float x, float* out) {
    float u = fmaf(2.0f, x, 5.0f);
    float cf = floorf(u);
    float t = u - cf;
    int c = (u >= 0.0f && u < 10.0f) ? (int)cf : -100;
    float t2 = t * t;
    float t3 = t2 * t;
    float s = 1.0f - t;
    const float i6 = 1.0f / 6.0f;
    float w3 = t3 * i6;                                                    // m == 0
    float w2 = fmaf(-3.0f, t3, fmaf(3.0f, t2, fmaf(3.0f, t, 1.0f))) * i6; // m == 1
    float w1 = fmaf(3.0f, t3, fmaf(-6.0f, t2, 4.0f)) * i6;                // m == 2
    float w0 = s * s * s * i6;                                            // m == 3
#pragma unroll
    for (int j = 0; j < 7; j++) {
        int m = c - j;
        out[j] = (m == 0) ? w3 : (m == 1) ? w2 : (m == 2) ? w1 : (m == 3) ? w0 : 0.0f;
    }
}

__device__ __forceinline__ uint32_t pack_hilo(float a, float b, uint32_t& lo) {
    uint32_t hp;
    asm("cvt.rn.bf16x2.f32 %0, %1, %2;" : "=r"(hp) : "f"(b), "f"(a));
    float ha = __uint_as_float(hp << 16);
    float hb = __uint_as_float(hp & 0xFFFF0000u);
    float la = a - ha, lb = b - hb;
    asm("cvt.rn.bf16x2.f32 %0, %1, %2;" : "=r"(lo) : "f"(lb), "f"(la));
    return hp;
}

// ---------------- CSR build ----------------
__global__ void deg_count_kernel(const int* __restrict__ ei) {
    int e = blockIdx.x * blockDim.x + threadIdx.x;
    if (e >= ETOT) return;
    int d = (e < NEDGE) ? __ldg(&ei[NEDGE + e]) : (e - NEDGE);
    atomicAdd(&g_deg[d], 1);
}

__global__ void scan1_kernel() {
    __shared__ int sh[1024];
    int t = threadIdx.x, b = blockIdx.x;
    int i = b * 1024 + t;
    int v = (i < NNODES) ? g_deg[i] : 0;
    sh[t] = v;
    __syncthreads();
#pragma unroll
    for (int off = 1; off < 1024; off <<= 1) {
        int add = (t >= off) ? sh[t - off] : 0;
        __syncthreads();
        sh[t] += add;
        __syncthreads();
    }
    if (i < NNODES) g_ptr[i] = sh[t] - v;
    if (t == 1023) g_bsum[b] = sh[t];
}

__global__ void scan2_kernel() {
    if (threadIdx.x == 0) {
        int run = 0;
        for (int b = 0; b < SCAN_BLOCKS; b++) { g_boff[b] = run; run += g_bsum[b]; }
        g_ptr[NNODES] = run;
    }
}

__global__ void scan3_kernel() {
    int t = threadIdx.x, b = blockIdx.x;
    int i = b * 1024 + t;
    if (i < NNODES) {
        int p = g_ptr[i] + g_boff[b];
        g_ptr[i] = p;
        g_cur[i] = p;
    }
}

__global__ void scatter_kernel(const int* __restrict__ ei) {
    int e = blockIdx.x * blockDim.x + threadIdx.x;
    if (e >= ETOT) return;
    int s, d;
    if (e < NEDGE) { s = __ldg(&ei[e]); d = __ldg(&ei[NEDGE + e]); }
    else           { s = e - NEDGE; d = s; }
    int pos = atomicAdd(&g_cur[d], 1);
    g_csrc[pos] = s;
}

// ---------------- weight pack (all 3 layers) ----------------
__global__ void pack_w_kernel(const float* __restrict__ bw,
                              const float* __restrict__ sw,
                              const float* __restrict__ sc) {
    int idx = blockIdx.x * blockDim.x + threadIdx.x;
    if (idx >= NLAYER * KDIM * DIM) return;
    int l = idx >> 17;
    int rem = idx & (KDIM * DIM - 1);
    int n = rem >> 10, k = rem & 1023;
    int j = k >> 3, f = k & 7;
    const float* bwl = bw + (size_t)l * DIM * DIM;
    const float* swl = sw + (size_t)l * DIM * DIM * NB;
    const float* scl = sc + (size_t)l * DIM * DIM;
    float v;
    if (f == 0) v = bwl[n * DIM + j];
    else        v = swl[(n * DIM + j) * NB + (f - 1)] * scl[n * DIM + j];
    __nv_bfloat16 h = __float2bfloat16_rn(v);
    g_Wh[idx] = h;
    g_Wl[idx] = __float2bfloat16_rn(v - __bfloat162float(h));
}

// ---------------- fused KAN-GEMM: pipelined double-buffered bf16 mma ----------------
// Buffer layout (per 32KB buffer): Ah[0,8K) Al[8K,16K) Bh[16K,24K) Bl[24K,32K)
// Tiles: 128 rows x 32 k (64B/row, 4 swizzled 16B chunks).
#define SMEM_BYTES 65536

__device__ __forceinline__ void build_chunk(const float* __restrict__ in,
                                            const __nv_bfloat16* __restrict__ Wh,
                                            const __nv_bfloat16* __restrict__ Wl,
                                            char* buf, int m0, int tid, int cc, bool rvalid) {
    char* Ah = buf;
    char* Al = buf + 8192;
    char* Bh = buf + 16384;
    char* Bl = buf + 24576;

    // B weights: LDG first (latency hidden behind feature math)
    int n = tid >> 1, half = tid & 1;
    const uint4* wh = (const uint4*)(Wh + (size_t)n * KDIM + cc * 32 + half * 16);
    const uint4* wl = (const uint4*)(Wl + (size_t)n * KDIM + cc * 32 + half * 16);
    uint4 bh0 = wh[0], bh1 = wh[1];
    uint4 bl0 = wl[0], bl1 = wl[1];

    // A features: 2 evals per thread (row, cols jp*2 + {0,1})
    int row = tid & 127, jp = tid >> 7;
    float2 xv2 = rvalid ? *(const float2*)(in + (size_t)(m0 + row) * DIM + cc * 4 + jp * 2)
                        : make_float2(0.f, 0.f);
#pragma unroll
    for (int q = 0; q < 2; q++) {
        float xv = q ? xv2.y : xv2.x;
        float fv[8];
        fv[0] = silu_f(xv);
        bsplines7(xv, fv + 1);
        uint4 uh, ul;
        uh.x = pack_hilo(fv[0], fv[1], ul.x);
        uh.y = pack_hilo(fv[2], fv[3], ul.y);
        uh.z = pack_hilo(fv[4], fv[5], ul.z);
        uh.w = pack_hilo(fv[6], fv[7], ul.w);
        int c = jp * 2 + q;
        uint32_t off = row * 64 + (SWZ32(c, row) << 4);
        *(uint4*)(Ah + off) = uh;
        *(uint4*)(Al + off) = ul;
    }
#pragma unroll
    for (int q = 0; q < 2; q++) {
        int c = half * 2 + q;
        uint32_t off = n * 64 + (SWZ32(c, n) << 4);
        *(uint4*)(Bh + off) = q ? bh1 : bh0;
        *(uint4*)(Bl + off) = q ? bl1 : bl0;
    }
}

__global__ void __launch_bounds__(256, 2) fkan_gemm_mma(const float* __restrict__ in,
                                                        const float* __restrict__ attS,
                                                        const float* __restrict__ attD,
                                                        const __nv_bfloat16* __restrict__ Wh,
                                                        const __nv_bfloat16* __restrict__ Wl) {
    extern __shared__ char dsm[];
    int tid = threadIdx.x;
    int wid = tid >> 5, lane = tid & 31;
    int m0 = blockIdx.x * 128;
    int warpM = wid & 3, warpN = wid >> 2;
    uint32_t ubase = smem_u32(dsm);

    bool rvalid = (m0 + (tid & 127)) < NNODES;
    int tg = lane >> 3, tr = lane & 7;

    float acc[2][8][4];
#pragma unroll
    for (int f = 0; f < 2; f++)
#pragma unroll
        for (int j = 0; j < 8; j++)
#pragma unroll
            for (int q = 0; q < 4; q++) acc[f][j][q] = 0.0f;

    // prologue: build chunk 0 into buffer 0
    build_chunk(in, Wh, Wl, dsm, m0, tid, 0, rvalid);
    __syncthreads();

    for (int cc = 0; cc < 32; cc++) {
        int p = cc & 1;
        uint32_t uAh = ubase + p * 32768;
        uint32_t uAl = uAh + 8192;
        uint32_t uBh = uAh + 16384;
        uint32_t uBl = uAh + 24576;

        // ---- mma for chunk cc (tensor pipe) ----
#pragma unroll
        for (int ks = 0; ks < 2; ks++) {
            uint32_t ah[2][4], al[2][4];
#pragma unroll
            for (int f = 0; f < 2; f++) {
                int arow = warpM * 32 + f * 16 + (tg & 1) * 8 + tr;
                int ac = ks * 2 + (tg >> 1);
                uint32_t aoff = arow * 64 + (SWZ32(ac, arow) << 4);
                ldsm4(uAh + aoff, ah[f][0], ah[f][1], ah[f][2], ah[f][3]);
                ldsm4(uAl + aoff, al[f][0], al[f][1], al[f][2], al[f][3]);
            }
#pragma unroll
            for (int gh = 0; gh < 2; gh++) {
                uint32_t bh[2][4], bl[2][4];
#pragma unroll
                for (int gg = 0; gg < 2; gg++) {
                    int g = gh * 2 + gg;
                    int brow = warpN * 64 + g * 16 + (tg >> 1) * 8 + tr;
                    int bc = ks * 2 + (tg & 1);
                    uint32_t boff = brow * 64 + (SWZ32(bc, brow) << 4);
                    ldsm4(uBh + boff, bh[gg][0], bh[gg][1], bh[gg][2], bh[gg][3]);
                    ldsm4(uBl + boff, bl[gg][0], bl[gg][1], bl[gg][2], bl[gg][3]);
                }
#pragma unroll
                for (int f = 0; f < 2; f++)
#pragma unroll
                    for (int gg = 0; gg < 2; gg++) {
                        int g = gh * 2 + gg;
                        mma16816(acc[f][2 * g],     ah[f], &bh[gg][0]);
                        mma16816(acc[f][2 * g],     al[f], &bh[gg][0]);
                        mma16816(acc[f][2 * g],     ah[f], &bl[gg][0]);
                        mma16816(acc[f][2 * g + 1], ah[f], &bh[gg][2]);
                        mma16816(acc[f][2 * g + 1], al[f], &bh[gg][2]);
                        mma16816(acc[f][2 * g + 1], ah[f], &bl[gg][2]);
                    }
            }
        }

        // ---- build chunk cc+1 into the other buffer (fma pipe, overlaps tensor) ----
        if (cc < 31)
            build_chunk(in, Wh, Wl, dsm + (p ^ 1) * 32768, m0, tid, cc + 1, rvalid);
        __syncthreads();
    }

    // ---- epilogue: store h + fused attention dots ----
    int qd = lane >> 2, ql = lane & 3;
#pragma unroll
    for (int f = 0; f < 2; f++)
#pragma unroll
        for (int hh = 0; hh < 2; hh++) {
            int row = m0 + warpM * 32 + f * 16 + hh * 8 + qd;
            bool ok = row < NNODES;
            float ps0 = 0.f, pd0 = 0.f, ps1 = 0.f, pd1 = 0.f;
#pragma unroll
            for (int j = 0; j < 8; j++) {
                int col = warpN * 64 + j * 8 + ql * 2;
                float v0 = acc[f][j][hh * 2 + 0];
                float v1 = acc[f][j][hh * 2 + 1];
                if (ok) {
                    float2 st = make_float2(v0, v1);
                    *(float2*)&g_hl[(size_t)row * DIM + col] = st;
                }
                float s0 = __ldg(&attS[col]), s1 = __ldg(&attS[col + 1]);
                float d0 = __ldg(&attD[col]), d1 = __ldg(&attD[col + 1]);
                float ps = v0 * s0 + v1 * s1;
                float pd = v0 * d0 + v1 * d1;
                if (j < 4) { ps0 += ps; pd0 += pd; } else { ps1 += ps; pd1 += pd; }
            }
#pragma unroll
            for (int o = 1; o <= 2; o <<= 1) {
                ps0 += __shfl_xor_sync(0xffffffffu, ps0, o);
                pd0 += __shfl_xor_sync(0xffffffffu, pd0, o);
                ps1 += __shfl_xor_sync(0xffffffffu, ps1, o);
                pd1 += __shfl_xor_sync(0xffffffffu, pd1, o);
            }
            if (ql == 0 && ok) {
                int hbase = warpN * 2;
                g_asrc[row * 4 + hbase]     = ps0;
                g_asrc[row * 4 + hbase + 1] = ps1;
                g_adst[row * 4 + hbase]     = pd0;
                g_adst[row * 4 + hbase + 1] = pd1;
            }
        }
}

// ---------------- fused pull-mode edge phase ----------------
__global__ void __launch_bounds__(256) edge_fused_kernel(const float* __restrict__ bias) {
    int gid = blockIdx.x * blockDim.x + threadIdx.x;
    int n = gid >> 5, lane = gid & 31;
    if (n >= NNODES) return;
    int start = __ldg(&g_ptr[n]);
    int end   = __ldg(&g_ptr[n + 1]);
    int hh = lane >> 3;
    float bd = g_adst[n * 4 + hh];

    float4 acc = make_float4(0.f, 0.f, 0.f, 0.f);
    float sumex = 0.0f;

    for (int j0 = start; j0 < end; j0 += 32) {
        int m = min(32, end - j0);
        int s_pref = (j0 + lane < end) ? __ldg(&g_csrc[j0 + lane]) : 0;
#pragma unroll 4
        for (int i = 0; i < m; i++) {
            int s = __shfl_sync(0xffffffffu, s_pref, i);
            float a = __ldg(&g_asrc[s * 4 + hh]);
            float e = a + bd;
            e = (e > 0.f) ? e : 0.2f * e;
            float ex = __expf(e);
            sumex += ex;
            float4 v = *(const float4*)&g_hl[(size_t)s * DIM + lane * 4];
            acc.x = fmaf(ex, v.x, acc.x);
            acc.y = fmaf(ex, v.y, acc.y);
            acc.z = fmaf(ex, v.z, acc.z);
            acc.w = fmaf(ex, v.w, acc.w);
        }
    }
    float inv = 1.0f / (sumex + 1e-16f);
    float4 b4 = *(const float4*)&bias[lane * 4];
    float4 o;
    o.x = silu_f(acc.x * inv + b4.x);
    o.y = silu_f(acc.y * inv + b4.y);
    o.z = silu_f(acc.z * inv + b4.z);
    o.w = silu_f(acc.w * inv + b4.w);
    *(float4*)&g_h[(size_t)n * DIM + lane * 4] = o;
}

// ---------------- pooling + readout ----------------
__global__ void pool_kernel(const int* __restrict__ batch) {
    int d0 = threadIdx.x;
    int r0 = blockIdx.x * 512;
    if (r0 >= NNODES) return;
    int rend = min(r0 + 512, NNODES);
    int cur = __ldg(&batch[r0]);
    float sum = 0.0f;
    for (int n = r0; n < rend; n++) {
        int g = __ldg(&batch[n]);
        if (g != cur) {
            atomicAdd(&g_pooled[cur * DIM + d0], sum);
            sum = 0.0f;
            cur = g;
        }
        sum += g_h[(size_t)n * DIM + d0];
    }
    atomicAdd(&g_pooled[cur * DIM + d0], sum);
}

__global__ void readout_kernel(const float* __restrict__ bw,
                               const float* __restrict__ sw,
                               const float* __restrict__ sc,
                               float* __restrict__ out) {
    __shared__ float feat[KDIM];
    __shared__ float sred[NCLS * 4];
    int g = blockIdx.x, t = threadIdx.x;
    float xv = g_pooled[g * DIM + t];
    feat[t] = xv / (1.0f + expf(-xv));
    float bs[7];
    bsplines7(xv, bs);
#pragma unroll
    for (int b = 0; b < 7; b++) feat[DIM + t * 7 + b] = bs[b];
    __syncthreads();

    float accv[NCLS];
#pragma unroll
    for (int o = 0; o < NCLS; o++) accv[o] = 0.0f;
#pragma unroll
    for (int kk = 0; kk < 8; kk++) {
        int k = kk * DIM + t;
        float f = feat[k];
        if (k < DIM) {
#pragma unroll
            for (int o = 0; o < NCLS; o++) accv[o] += f * bw[o * DIM + k];
        } else {
            int j = (k - DIM) / 7, b = (k - DIM) % 7;
#pragma unroll
            for (int o = 0; o < NCLS; o++)
                accv[o] += f * sw[o * DIM * NB + j * NB + b] * sc[o * DIM + j];
        }
    }
    int lane = t & 31, warp = t >> 5;
#pragma unroll
    for (int o = 0; o < NCLS; o++) {
        float v = accv[o];
#pragma unroll
        for (int off = 16; off >= 1; off >>= 1) v += __shfl_xor_sync(0xffffffffu, v, off);
        if (lane == 0) sred[o * 4 + warp] = v;
    }
    __syncthreads();
    if (t == 0) {
        float lg[NCLS];
        float mx = -1e30f;
#pragma unroll
        for (int o = 0; o < NCLS; o++) {
            lg[o] = sred[o * 4] + sred[o * 4 + 1] + sred[o * 4 + 2] + sred[o * 4 + 3];
            mx = fmaxf(mx, lg[o]);
        }
        float se = 0.0f;
#pragma unroll
        for (int o = 0; o < NCLS; o++) se += expf(lg[o] - mx);
        float lse = logf(se) + mx;
#pragma unroll
        for (int o = 0; o < NCLS; o++) out[g * NCLS + o] = lg[o] - lse;
    }
}

// ---------------- launch ----------------
extern "C" void kernel_launch(void* const* d_in, const int* in_sizes, int n_in,
                              void* d_out, int out_size) {
    const float* x        = (const float*)d_in[0];
    const int*   ei       = (const int*)d_in[1];
    const int*   batch    = (const int*)d_in[2];
    const float* base_w   = (const float*)d_in[3];
    const float* spline_w = (const float*)d_in[4];
    const float* scaler   = (const float*)d_in[5];
    const float* att_src  = (const float*)d_in[6];
    const float* att_dst  = (const float*)d_in[7];
    const float* bias     = (const float*)d_in[8];
    const float* ro_bw    = (const float*)d_in[9];
    const float* ro_sw    = (const float*)d_in[10];
    const float* ro_sc    = (const float*)d_in[11];
    float* out = (float*)d_out;

    cudaFuncSetAttribute(fkan_gemm_mma, cudaFuncAttributeMaxDynamicSharedMemorySize, SMEM_BYTES);

    float *hbuf = nullptr, *poolp = nullptr;
    int* degp = nullptr;
    __nv_bfloat16 *whp = nullptr, *wlp = nullptr;
    cudaGetSymbolAddress((void**)&hbuf, g_h);
    cudaGetSymbolAddress((void**)&poolp, g_pooled);
    cudaGetSymbolAddress((void**)&degp, g_deg);
    cudaGetSymbolAddress((void**)&whp, g_Wh);
    cudaGetSymbolAddress((void**)&wlp, g_Wl);

    const int E_BLOCKS = (ETOT + 255) / 256;

    pack_w_kernel<<<(NLAYER * KDIM * DIM + 255) / 256, 256>>>(base_w, spline_w, scaler);
    cudaMemsetAsync(degp, 0, NNODES * sizeof(int));
    deg_count_kernel<<<E_BLOCKS, 256>>>(ei);
    scan1_kernel<<<SCAN_BLOCKS, 1024>>>();
    scan2_kernel<<<1, 32>>>();
    scan3_kernel<<<SCAN_BLOCKS, 1024>>>();
    scatter_kernel<<<E_BLOCKS, 256>>>(ei);

    for (int l = 0; l < NLAYER; l++) {
        const float* in = (l == 0) ? x : hbuf;
        fkan_gemm_mma<<<MTILES, 256, SMEM_BYTES>>>(
            in, att_src + (size_t)l * DIM, att_dst + (size_t)l * DIM,
            whp + (size_t)l * KDIM * DIM, wlp + (size_t)l * KDIM * DIM);
        edge_fused_kernel<<<(NNODES * 32 + 255) / 256, 256>>>(bias + (size_t)l * DIM);
    }
    cudaMemsetAsync(poolp, 0, (size_t)NGR * DIM * sizeof(float));
    pool_kernel<<<(NNODES + 511) / 512, DIM>>>(batch);
    readout_kernel<<<NGR, DIM>>>(ro_bw, ro_sw, ro_sc, out);
}

// round 8
// speedup vs baseline: 1.2353x; 1.1923x over previous
#include <cuda_runtime.h>
#include <cuda_bf16.h>
#include <cstdint>

#define NNODES 50000
#define NEDGE  800000
#define ETOT   850000
#define DIM    128
#define NH     4
#define NB     7
#define KDIM   1024
#define NGR    64
#define NCLS   10
#define NLAYER 3

#define MTILES ((NNODES + 127) / 128)   // 391
#define SCAN_BLOCKS ((NNODES + 1023) / 1024)  // 49

// ---------------- device scratch ----------------
__device__ __align__(16) __nv_bfloat16 g_Wh[KDIM * DIM];
__device__ __align__(16) __nv_bfloat16 g_Wl[KDIM * DIM];
__device__ __align__(16) float g_h[NNODES * DIM];
__device__ __align__(16) float g_hl[NNODES * DIM];
__device__ __align__(16) float g_asrc[NNODES * NH];
__device__ __align__(16) float g_adst[NNODES * NH];
__device__ __align__(16) float g_pooled[NGR * DIM];
// CSR
__device__ int g_deg[NNODES];
__device__ int g_ptr[NNODES + 1];
__device__ int g_cur[NNODES];
__device__ int g_csrc[ETOT];
__device__ int g_bsum[SCAN_BLOCKS];
__device__ int g_boff[SCAN_BLOCKS];

// ---------------- helpers ----------------
__device__ __forceinline__ uint32_t smem_u32(const void* p) {
    uint32_t a;
    asm("{ .reg .u64 t; cvta.to.shared.u64 t, %1; cvt.u32.u64 %0, t; }" : "=r"(a) : "l"(p));
    return a;
}

// 16B-chunk swizzle within a 64B row (4 chunks): conflict-free for stores + ldmatrix
#define SWZ32(c, r) (((c) ^ ((r) >> 1)) & 3)

__device__ __forceinline__ void ldsm4(uint32_t a, uint32_t& r0, uint32_t& r1,
                                      uint32_t& r2, uint32_t& r3) {
    asm volatile("ldmatrix.sync.aligned.m8n8.x4.shared.b16 {%0,%1,%2,%3}, [%4];"
                 : "=r"(r0), "=r"(r1), "=r"(r2), "=r"(r3) : "r"(a));
}

__device__ __forceinline__ void mma16816(float* d, const uint32_t* a, const uint32_t* b) {
    asm volatile("mma.sync.aligned.m16n8k16.row.col.f32.bf16.bf16.f32 "
                 "{%0,%1,%2,%3}, {%4,%5,%6,%7}, {%8,%9}, {%0,%1,%2,%3};"
                 : "+f"(d[0]), "+f"(d[1]), "+f"(d[2]), "+f"(d[3])
                 : "r"(a[0]), "r"(a[1]), "r"(a[2]), "r"(a[3]), "r"(b[0]), "r"(b[1]));
}

__device__ __forceinline__ float silu_f(float x) { return x / (1.0f + __expf(-x)); }

// Cubic B-splines on uniform grid g[t] = 0.5*t - 2.5 (Cox-de Boor recursion,
// straight-line FFMA-friendly — measured faster than the select-chain closed form)
__device__ __forceinline__ void bsplines7(float x, float* out) {
    float b0[10];
#pragma unroll
    for (int i = 0; i < 10; i++) {
        float g0 = 0.5f * (float)i - 2.5f;
        b0[i] = (x >= g0 && x < g0 + 0.5f) ? 1.0f : 0.0f;
    }
    float b1[9];
#pragma unroll
    for (int i = 0; i < 9; i++) {
        float gi = 0.5f * (float)i - 2.5f;
        b1[i] = (x - gi) * 2.0f * b0[i] + ((gi + 1.0f) - x) * 2.0f * b0[i + 1];
    }
    float b2[8];
#pragma unroll
    for (int i = 0; i < 8; i++) {
        float gi = 0.5f * (float)i - 2.5f;
        b2[i] = (x - gi) * b1[i] + ((gi + 1.5f) - x) * b1[i + 1];
    }
#pragma unroll
    for (int i = 0; i < 7; i++) {
        float gi = 0.5f * (float)i - 2.5f;
        out[i] = ((x - gi) * b2[i] + ((gi + 2.0f) - x) * b2[i + 1]) * (1.0f / 1.5f);
    }
}

__device__ __forceinline__ uint32_t pack_hilo(float a, float b, uint32_t& lo) {
    uint32_t hp;
    asm("cvt.rn.bf16x2.f32 %0, %1, %2;" : "=r"(hp) : "f"(b), "f"(a));
    float ha = __uint_as_float(hp << 16);
    float hb = __uint_as_float(hp & 0xFFFF0000u);
    float la = a - ha, lb = b - hb;
    asm("cvt.rn.bf16x2.f32 %0, %1, %2;" : "=r"(lo) : "f"(lb), "f"(la));
    return hp;
}

// ---------------- CSR build ----------------
__global__ void deg_count_kernel(const int* __restrict__ ei) {
    int e = blockIdx.x * blockDim.x + threadIdx.x;
    if (e >= ETOT) return;
    int d = (e < NEDGE) ? __ldg(&ei[NEDGE + e]) : (e - NEDGE);
    atomicAdd(&g_deg[d], 1);
}

__global__ void scan1_kernel() {
    __shared__ int sh[1024];
    int t = threadIdx.x, b = blockIdx.x;
    int i = b * 1024 + t;
    int v = (i < NNODES) ? g_deg[i] : 0;
    sh[t] = v;
    __syncthreads();
#pragma unroll
    for (int off = 1; off < 1024; off <<= 1) {
        int add = (t >= off) ? sh[t - off] : 0;
        __syncthreads();
        sh[t] += add;
        __syncthreads();
    }
    if (i < NNODES) g_ptr[i] = sh[t] - v;
    if (t == 1023) g_bsum[b] = sh[t];
}

__global__ void scan2_kernel() {
    if (threadIdx.x == 0) {
        int run = 0;
        for (int b = 0; b < SCAN_BLOCKS; b++) { g_boff[b] = run; run += g_bsum[b]; }
        g_ptr[NNODES] = run;
    }
}

__global__ void scan3_kernel() {
    int t = threadIdx.x, b = blockIdx.x;
    int i = b * 1024 + t;
    if (i < NNODES) {
        int p = g_ptr[i] + g_boff[b];
        g_ptr[i] = p;
        g_cur[i] = p;
    }
}

__global__ void scatter_kernel(const int* __restrict__ ei) {
    int e = blockIdx.x * blockDim.x + threadIdx.x;
    if (e >= ETOT) return;
    int s, d;
    if (e < NEDGE) { s = __ldg(&ei[e]); d = __ldg(&ei[NEDGE + e]); }
    else           { s = e - NEDGE; d = s; }
    int pos = atomicAdd(&g_cur[d], 1);
    g_csrc[pos] = s;
}

// ---------------- weight pack (per layer, L2-warming right before the GEMM) ----------------
__global__ void pack_w_kernel(const float* __restrict__ bw,
                              const float* __restrict__ sw,
                              const float* __restrict__ sc) {
    int idx = blockIdx.x * blockDim.x + threadIdx.x;
    if (idx >= KDIM * DIM) return;
    int n = idx >> 10, k = idx & 1023;
    int j = k >> 3, f = k & 7;
    float v;
    if (f == 0) v = bw[n * DIM + j];
    else        v = sw[(n * DIM + j) * NB + (f - 1)] * sc[n * DIM + j];
    __nv_bfloat16 h = __float2bfloat16_rn(v);
    g_Wh[idx] = h;
    g_Wl[idx] = __float2bfloat16_rn(v - __bfloat162float(h));
}

// ---------------- fused KAN-GEMM: pipelined double-buffered bf16 mma ----------------
// Buffer layout (per 32KB buffer): Ah[0,8K) Al[8K,16K) Bh[16K,24K) Bl[24K,32K)
// Tiles: 128 rows x 32 k (64B/row, 4 swizzled 16B chunks).
#define SMEM_BYTES 65536

__device__ __forceinline__ void build_chunk(const float* __restrict__ in,
                                            char* buf, int m0, int tid, int cc, bool rvalid) {
    char* Ah = buf;
    char* Al = buf + 8192;
    char* Bh = buf + 16384;
    char* Bl = buf + 24576;

    // B weights: LDG first (latency hidden behind feature math)
    int n = tid >> 1, half = tid & 1;
    const uint4* wh = (const uint4*)(g_Wh + (size_t)n * KDIM + cc * 32 + half * 16);
    const uint4* wl = (const uint4*)(g_Wl + (size_t)n * KDIM + cc * 32 + half * 16);
    uint4 bh0 = wh[0], bh1 = wh[1];
    uint4 bl0 = wl[0], bl1 = wl[1];

    // A features: 2 evals per thread (row, cols jp*2 + {0,1})
    int row = tid & 127, jp = tid >> 7;
    float2 xv2 = rvalid ? *(const float2*)(in + (size_t)(m0 + row) * DIM + cc * 4 + jp * 2)
                        : make_float2(0.f, 0.f);
#pragma unroll
    for (int q = 0; q < 2; q++) {
        float xv = q ? xv2.y : xv2.x;
        float fv[8];
        fv[0] = silu_f(xv);
        bsplines7(xv, fv + 1);
        uint4 uh, ul;
        uh.x = pack_hilo(fv[0], fv[1], ul.x);
        uh.y = pack_hilo(fv[2], fv[3], ul.y);
        uh.z = pack_hilo(fv[4], fv[5], ul.z);
        uh.w = pack_hilo(fv[6], fv[7], ul.w);
        int c = jp * 2 + q;
        uint32_t off = row * 64 + (SWZ32(c, row) << 4);
        *(uint4*)(Ah + off) = uh;
        *(uint4*)(Al + off) = ul;
    }
#pragma unroll
    for (int q = 0; q < 2; q++) {
        int c = half * 2 + q;
        uint32_t off = n * 64 + (SWZ32(c, n) << 4);
        *(uint4*)(Bh + off) = q ? bh1 : bh0;
        *(uint4*)(Bl + off) = q ? bl1 : bl0;
    }
}

__global__ void __launch_bounds__(256, 2) fkan_gemm_mma(const float* __restrict__ in,
                                                        const float* __restrict__ attS,
                                                        const float* __restrict__ attD) {
    extern __shared__ char dsm[];
    int tid = threadIdx.x;
    int wid = tid >> 5, lane = tid & 31;
    int m0 = blockIdx.x * 128;
    int warpM = wid & 3, warpN = wid >> 2;
    uint32_t ubase = smem_u32(dsm);

    bool rvalid = (m0 + (tid & 127)) < NNODES;
    int tg = lane >> 3, tr = lane & 7;

    float acc[2][8][4];
#pragma unroll
    for (int f = 0; f < 2; f++)
#pragma unroll
        for (int j = 0; j < 8; j++)
#pragma unroll
            for (int q = 0; q < 4; q++) acc[f][j][q] = 0.0f;

    // prologue: build chunk 0 into buffer 0
    build_chunk(in, dsm, m0, tid, 0, rvalid);
    __syncthreads();

    for (int cc = 0; cc < 32; cc++) {
        int p = cc & 1;
        uint32_t uAh = ubase + p * 32768;
        uint32_t uAl = uAh + 8192;
        uint32_t uBh = uAh + 16384;
        uint32_t uBl = uAh + 24576;

        // ---- mma for chunk cc (tensor pipe) ----
#pragma unroll
        for (int ks = 0; ks < 2; ks++) {
            uint32_t ah[2][4], al[2][4];
#pragma unroll
            for (int f = 0; f < 2; f++) {
                int arow = warpM * 32 + f * 16 + (tg & 1) * 8 + tr;
                int ac = ks * 2 + (tg >> 1);
                uint32_t aoff = arow * 64 + (SWZ32(ac, arow) << 4);
                ldsm4(uAh + aoff, ah[f][0], ah[f][1], ah[f][2], ah[f][3]);
                ldsm4(uAl + aoff, al[f][0], al[f][1], al[f][2], al[f][3]);
            }
#pragma unroll
            for (int gh = 0; gh < 2; gh++) {
                uint32_t bh[2][4], bl[2][4];
#pragma unroll
                for (int gg = 0; gg < 2; gg++) {
                    int g = gh * 2 + gg;
                    int brow = warpN * 64 + g * 16 + (tg >> 1) * 8 + tr;
                    int bc = ks * 2 + (tg & 1);
                    uint32_t boff = brow * 64 + (SWZ32(bc, brow) << 4);
                    ldsm4(uBh + boff, bh[gg][0], bh[gg][1], bh[gg][2], bh[gg][3]);
                    ldsm4(uBl + boff, bl[gg][0], bl[gg][1], bl[gg][2], bl[gg][3]);
                }
#pragma unroll
                for (int f = 0; f < 2; f++)
#pragma unroll
                    for (int gg = 0; gg < 2; gg++) {
                        int g = gh * 2 + gg;
                        mma16816(acc[f][2 * g],     ah[f], &bh[gg][0]);
                        mma16816(acc[f][2 * g],     al[f], &bh[gg][0]);
                        mma16816(acc[f][2 * g],     ah[f], &bl[gg][0]);
                        mma16816(acc[f][2 * g + 1], ah[f], &bh[gg][2]);
                        mma16816(acc[f][2 * g + 1], al[f], &bh[gg][2]);
                        mma16816(acc[f][2 * g + 1], ah[f], &bl[gg][2]);
                    }
            }
        }

        // ---- build chunk cc+1 into the other buffer (fma pipe, overlaps tensor) ----
        if (cc < 31)
            build_chunk(in, dsm + (p ^ 1) * 32768, m0, tid, cc + 1, rvalid);
        __syncthreads();
    }

    // ---- epilogue: store h + fused attention dots ----
    int qd = lane >> 2, ql = lane & 3;
#pragma unroll
    for (int f = 0; f < 2; f++)
#pragma unroll
        for (int hh = 0; hh < 2; hh++) {
            int row = m0 + warpM * 32 + f * 16 + hh * 8 + qd;
            bool ok = row < NNODES;
            float ps0 = 0.f, pd0 = 0.f, ps1 = 0.f, pd1 = 0.f;
#pragma unroll
            for (int j = 0; j < 8; j++) {
                int col = warpN * 64 + j * 8 + ql * 2;
                float v0 = acc[f][j][hh * 2 + 0];
                float v1 = acc[f][j][hh * 2 + 1];
                if (ok) {
                    float2 st = make_float2(v0, v1);
                    *(float2*)&g_hl[(size_t)row * DIM + col] = st;
                }
                float s0 = __ldg(&attS[col]), s1 = __ldg(&attS[col + 1]);
                float d0 = __ldg(&attD[col]), d1 = __ldg(&attD[col + 1]);
                float ps = v0 * s0 + v1 * s1;
                float pd = v0 * d0 + v1 * d1;
                if (j < 4) { ps0 += ps; pd0 += pd; } else { ps1 += ps; pd1 += pd; }
            }
#pragma unroll
            for (int o = 1; o <= 2; o <<= 1) {
                ps0 += __shfl_xor_sync(0xffffffffu, ps0, o);
                pd0 += __shfl_xor_sync(0xffffffffu, pd0, o);
                ps1 += __shfl_xor_sync(0xffffffffu, ps1, o);
                pd1 += __shfl_xor_sync(0xffffffffu, pd1, o);
            }
            if (ql == 0 && ok) {
                int hbase = warpN * 2;
                g_asrc[row * 4 + hbase]     = ps0;
                g_asrc[row * 4 + hbase + 1] = ps1;
                g_adst[row * 4 + hbase]     = pd0;
                g_adst[row * 4 + hbase + 1] = pd1;
            }
        }
}

// ---------------- fused pull-mode edge phase ----------------
__global__ void __launch_bounds__(256) edge_fused_kernel(const float* __restrict__ bias) {
    int gid = blockIdx.x * blockDim.x + threadIdx.x;
    int n = gid >> 5, lane = gid & 31;
    if (n >= NNODES) return;
    int start = __ldg(&g_ptr[n]);
    int end   = __ldg(&g_ptr[n + 1]);
    int hh = lane >> 3;
    float bd = g_adst[n * 4 + hh];

    float4 acc = make_float4(0.f, 0.f, 0.f, 0.f);
    float sumex = 0.0f;

    for (int j0 = start; j0 < end; j0 += 32) {
        int m = min(32, end - j0);
        int s_pref = (j0 + lane < end) ? __ldg(&g_csrc[j0 + lane]) : 0;
#pragma unroll 4
        for (int i = 0; i < m; i++) {
            int s = __shfl_sync(0xffffffffu, s_pref, i);
            float a = __ldg(&g_asrc[s * 4 + hh]);
            float e = a + bd;
            e = (e > 0.f) ? e : 0.2f * e;
            float ex = __expf(e);
            sumex += ex;
            float4 v = *(const float4*)&g_hl[(size_t)s * DIM + lane * 4];
            acc.x = fmaf(ex, v.x, acc.x);
            acc.y = fmaf(ex, v.y, acc.y);
            acc.z = fmaf(ex, v.z, acc.z);
            acc.w = fmaf(ex, v.w, acc.w);
        }
    }
    float inv = 1.0f / (sumex + 1e-16f);
    float4 b4 = *(const float4*)&bias[lane * 4];
    float4 o;
    o.x = silu_f(acc.x * inv + b4.x);
    o.y = silu_f(acc.y * inv + b4.y);
    o.z = silu_f(acc.z * inv + b4.z);
    o.w = silu_f(acc.w * inv + b4.w);
    *(float4*)&g_h[(size_t)n * DIM + lane * 4] = o;
}

// ---------------- pooling + readout ----------------
__global__ void pool_kernel(const int* __restrict__ batch) {
    int d0 = threadIdx.x;
    int r0 = blockIdx.x * 512;
    if (r0 >= NNODES) return;
    int rend = min(r0 + 512, NNODES);
    int cur = __ldg(&batch[r0]);
    float sum = 0.0f;
    for (int n = r0; n < rend; n++) {
        int g = __ldg(&batch[n]);
        if (g != cur) {
            atomicAdd(&g_pooled[cur * DIM + d0], sum);
            sum = 0.0f;
            cur = g;
        }
        sum += g_h[(size_t)n * DIM + d0];
    }
    atomicAdd(&g_pooled[cur * DIM + d0], sum);
}

__global__ void readout_kernel(const float* __restrict__ bw,
                               const float* __restrict__ sw,
                               const float* __restrict__ sc,
                               float* __restrict__ out) {
    __shared__ float feat[KDIM];
    __shared__ float sred[NCLS * 4];
    int g = blockIdx.x, t = threadIdx.x;
    float xv = g_pooled[g * DIM + t];
    feat[t] = xv / (1.0f + expf(-xv));
    float bs[7];
    bsplines7(xv, bs);
#pragma unroll
    for (int b = 0; b < 7; b++) feat[DIM + t * 7 + b] = bs[b];
    __syncthreads();

    float accv[NCLS];
#pragma unroll
    for (int o = 0; o < NCLS; o++) accv[o] = 0.0f;
#pragma unroll
    for (int kk = 0; kk < 8; kk++) {
        int k = kk * DIM + t;
        float f = feat[k];
        if (k < DIM) {
#pragma unroll
            for (int o = 0; o < NCLS; o++) accv[o] += f * bw[o * DIM + k];
        } else {
            int j = (k - DIM) / 7, b = (k - DIM) % 7;
#pragma unroll
            for (int o = 0; o < NCLS; o++)
                accv[o] += f * sw[o * DIM * NB + j * NB + b] * sc[o * DIM + j];
        }
    }
    int lane = t & 31, warp = t >> 5;
#pragma unroll
    for (int o = 0; o < NCLS; o++) {
        float v = accv[o];
#pragma unroll
        for (int off = 16; off >= 1; off >>= 1) v += __shfl_xor_sync(0xffffffffu, v, off);
        if (lane == 0) sred[o * 4 + warp] = v;
    }
    __syncthreads();
    if (t == 0) {
        float lg[NCLS];
        float mx = -1e30f;
#pragma unroll
        for (int o = 0; o < NCLS; o++) {
            lg[o] = sred[o * 4] + sred[o * 4 + 1] + sred[o * 4 + 2] + sred[o * 4 + 3];
            mx = fmaxf(mx, lg[o]);
        }
        float se = 0.0f;
#pragma unroll
        for (int o = 0; o < NCLS; o++) se += expf(lg[o] - mx);
        float lse = logf(se) + mx;
#pragma unroll
        for (int o = 0; o < NCLS; o++) out[g * NCLS + o] = lg[o] - lse;
    }
}

// ---------------- launch ----------------
extern "C" void kernel_launch(void* const* d_in, const int* in_sizes, int n_in,
                              void* d_out, int out_size) {
    const float* x        = (const float*)d_in[0];
    const int*   ei       = (const int*)d_in[1];
    const int*   batch    = (const int*)d_in[2];
    const float* base_w   = (const float*)d_in[3];
    const float* spline_w = (const float*)d_in[4];
    const float* scaler   = (const float*)d_in[5];
    const float* att_src  = (const float*)d_in[6];
    const float* att_dst  = (const float*)d_in[7];
    const float* bias     = (const float*)d_in[8];
    const float* ro_bw    = (const float*)d_in[9];
    const float* ro_sw    = (const float*)d_in[10];
    const float* ro_sc    = (const float*)d_in[11];
    float* out = (float*)d_out;

    cudaFuncSetAttribute(fkan_gemm_mma, cudaFuncAttributeMaxDynamicSharedMemorySize, SMEM_BYTES);

    float *hbuf = nullptr, *poolp = nullptr;
    int* degp = nullptr;
    cudaGetSymbolAddress((void**)&hbuf, g_h);
    cudaGetSymbolAddress((void**)&poolp, g_pooled);
    cudaGetSymbolAddress((void**)&degp, g_deg);

    const int E_BLOCKS = (ETOT + 255) / 256;

    // ---- CSR build (once per run) ----
    cudaMemsetAsync(degp, 0, NNODES * sizeof(int));
    deg_count_kernel<<<E_BLOCKS, 256>>>(ei);
    scan1_kernel<<<SCAN_BLOCKS, 1024>>>();
    scan2_kernel<<<1, 32>>>();
    scan3_kernel<<<SCAN_BLOCKS, 1024>>>();
    scatter_kernel<<<E_BLOCKS, 256>>>(ei);

    for (int l = 0; l < NLAYER; l++) {
        const float* in = (l == 0) ? x : hbuf;
        pack_w_kernel<<<(KDIM * DIM + 255) / 256, 256>>>(
            base_w + (size_t)l * DIM * DIM,
            spline_w + (size_t)l * DIM * DIM * NB,
            scaler + (size_t)l * DIM * DIM);
        fkan_gemm_mma<<<MTILES, 256, SMEM_BYTES>>>(
            in, att_src + (size_t)l * DIM, att_dst + (size_t)l * DIM);
        edge_fused_kernel<<<(NNODES * 32 + 255) / 256, 256>>>(bias + (size_t)l * DIM);
    }
    cudaMemsetAsync(poolp, 0, (size_t)NGR * DIM * sizeof(float));
    pool_kernel<<<(NNODES + 511) / 512, DIM>>>(batch);
    readout_kernel<<<NGR, DIM>>>(ro_bw, ro_sw, ro_sc, out);
}

// round 9
// speedup vs baseline: 1.2357x; 1.0003x over previous
#include <cuda_runtime.h>
#include <cuda_bf16.h>
#include <cstdint>

#define NNODES 50000
#define NEDGE  800000
#define ETOT   850000
#define DIM    128
#define NH     4
#define NB     7
#define KDIM   1024
#define NGR    64
#define NCLS   10
#define NLAYER 3

#define MTILES ((NNODES + 127) / 128)   // 391
#define SCAN_BLOCKS ((NNODES + 1023) / 1024)  // 49

// ---------------- device scratch ----------------
__device__ __align__(16) __nv_bfloat16 g_Wh[KDIM * DIM];
__device__ __align__(16) __nv_bfloat16 g_Wl[KDIM * DIM];
__device__ __align__(16) float g_h[NNODES * DIM];
__device__ __align__(16) float g_hl[NNODES * DIM];
__device__ __align__(16) float g_asrc[NNODES * NH];
__device__ __align__(16) float g_adst[NNODES * NH];
__device__ __align__(16) float g_pooled[NGR * DIM];
// CSR
__device__ int g_deg[NNODES];
__device__ int g_ptr[NNODES + 1];
__device__ int g_cur[NNODES];
__device__ int g_csrc[ETOT];
__device__ int g_bsum[SCAN_BLOCKS];
__device__ int g_boff[SCAN_BLOCKS];

// ---------------- helpers ----------------
__device__ __forceinline__ uint32_t smem_u32(const void* p) {
    uint32_t a;
    asm("{ .reg .u64 t; cvta.to.shared.u64 t, %1; cvt.u32.u64 %0, t; }" : "=r"(a) : "l"(p));
    return a;
}

// 16B-chunk swizzle within a 64B row (4 chunks): conflict-free for stores + ldmatrix
#define SWZ32(c, r) (((c) ^ ((r) >> 1)) & 3)

__device__ __forceinline__ void ldsm4(uint32_t a, uint32_t& r0, uint32_t& r1,
                                      uint32_t& r2, uint32_t& r3) {
    asm volatile("ldmatrix.sync.aligned.m8n8.x4.shared.b16 {%0,%1,%2,%3}, [%4];"
                 : "=r"(r0), "=r"(r1), "=r"(r2), "=r"(r3) : "r"(a));
}

__device__ __forceinline__ void mma16816(float* d, const uint32_t* a, const uint32_t* b) {
    asm volatile("mma.sync.aligned.m16n8k16.row.col.f32.bf16.bf16.f32 "
                 "{%0,%1,%2,%3}, {%4,%5,%6,%7}, {%8,%9}, {%0,%1,%2,%3};"
                 : "+f"(d[0]), "+f"(d[1]), "+f"(d[2]), "+f"(d[3])
                 : "r"(a[0]), "r"(a[1]), "r"(a[2]), "r"(a[3]), "r"(b[0]), "r"(b[1]));
}

__device__ __forceinline__ float silu_f(float x) { return x / (1.0f + __expf(-x)); }

// Cubic B-splines (Cox-de Boor recursion) — used only in small readout kernel.
__device__ __forceinline__ void bsplines7(float x, float* out) {
    float b0[10];
#pragma unroll
    for (int i = 0; i < 10; i++) {
        float g0 = 0.5f * (float)i - 2.5f;
        b0[i] = (x >= g0 && x < g0 + 0.5f) ? 1.0f : 0.0f;
    }
    float b1[9];
#pragma unroll
    for (int i = 0; i < 9; i++) {
        float gi = 0.5f * (float)i - 2.5f;
        b1[i] = (x - gi) * 2.0f * b0[i] + ((gi + 1.0f) - x) * 2.0f * b0[i + 1];
    }
    float b2[8];
#pragma unroll
    for (int i = 0; i < 8; i++) {
        float gi = 0.5f * (float)i - 2.5f;
        b2[i] = (x - gi) * b1[i] + ((gi + 1.5f) - x) * b1[i + 1];
    }
#pragma unroll
    for (int i = 0; i < 7; i++) {
        float gi = 0.5f * (float)i - 2.5f;
        out[i] = ((x - gi) * b2[i] + ((gi + 2.0f) - x) * b2[i + 1]) * (1.0f / 1.5f);
    }
}

// ---------------- CSR build ----------------
__global__ void deg_count_kernel(const int* __restrict__ ei) {
    int e = blockIdx.x * blockDim.x + threadIdx.x;
    if (e >= ETOT) return;
    int d = (e < NEDGE) ? __ldg(&ei[NEDGE + e]) : (e - NEDGE);
    atomicAdd(&g_deg[d], 1);
}

__global__ void scan1_kernel() {
    __shared__ int sh[1024];
    int t = threadIdx.x, b = blockIdx.x;
    int i = b * 1024 + t;
    int v = (i < NNODES) ? g_deg[i] : 0;
    sh[t] = v;
    __syncthreads();
#pragma unroll
    for (int off = 1; off < 1024; off <<= 1) {
        int add = (t >= off) ? sh[t - off] : 0;
        __syncthreads();
        sh[t] += add;
        __syncthreads();
    }
    if (i < NNODES) g_ptr[i] = sh[t] - v;
    if (t == 1023) g_bsum[b] = sh[t];
}

__global__ void scan2_kernel() {
    if (threadIdx.x == 0) {
        int run = 0;
        for (int b = 0; b < SCAN_BLOCKS; b++) { g_boff[b] = run; run += g_bsum[b]; }
        g_ptr[NNODES] = run;
    }
}

__global__ void scan3_kernel() {
    int t = threadIdx.x, b = blockIdx.x;
    int i = b * 1024 + t;
    if (i < NNODES) {
        int p = g_ptr[i] + g_boff[b];
        g_ptr[i] = p;
        g_cur[i] = p;
    }
}

__global__ void scatter_kernel(const int* __restrict__ ei) {
    int e = blockIdx.x * blockDim.x + threadIdx.x;
    if (e >= ETOT) return;
    int s, d;
    if (e < NEDGE) { s = __ldg(&ei[e]); d = __ldg(&ei[NEDGE + e]); }
    else           { s = e - NEDGE; d = s; }
    int pos = atomicAdd(&g_cur[d], 1);
    g_csrc[pos] = s;
}

// ---------------- weight pack (per layer) ----------------
__global__ void pack_w_kernel(const float* __restrict__ bw,
                              const float* __restrict__ sw,
                              const float* __restrict__ sc) {
    int idx = blockIdx.x * blockDim.x + threadIdx.x;
    if (idx >= KDIM * DIM) return;
    int n = idx >> 10, k = idx & 1023;
    int j = k >> 3, f = k & 7;
    float v;
    if (f == 0) v = bw[n * DIM + j];
    else        v = sw[(n * DIM + j) * NB + (f - 1)] * sc[n * DIM + j];
    __nv_bfloat16 h = __float2bfloat16_rn(v);
    g_Wh[idx] = h;
    g_Wl[idx] = __float2bfloat16_rn(v - __bfloat162float(h));
}

// ---------------- fused KAN-GEMM: pipelined double-buffered bf16 mma ----------------
// Buffer layout (per 32KB buffer): Ah[0,8K) Al[8K,16K) Bh[16K,24K) Bl[24K,32K)
// Tiles: 128 rows x 32 k (64B/row, 4 swizzled 16B chunks).
#define SMEM_BYTES 65536

__device__ __forceinline__ void build_chunk(const float* __restrict__ in,
                                            char* buf, int m0, int tid, int cc, bool rvalid) {
    char* Ah = buf;
    char* Al = buf + 8192;
    char* Bh = buf + 16384;
    char* Bl = buf + 24576;

    // B weights: LDG first (latency hidden behind feature math)
    int n = tid >> 1, half = tid & 1;
    const uint4* wh = (const uint4*)(g_Wh + (size_t)n * KDIM + cc * 32 + half * 16);
    const uint4* wl = (const uint4*)(g_Wl + (size_t)n * KDIM + cc * 32 + half * 16);
    uint4 bh0 = wh[0], bh1 = wh[1];
    uint4 bl0 = wl[0], bl1 = wl[1];

    // A features: 2 evals per thread (row, cols jp*2 + {0,1}).
    // Closed-form cardinal cubic B-spline with direct scatter of the <=4
    // nonzero bases — no select chain, no packing of zeros.
    int row = tid & 127, jp = tid >> 7;
    float2 xv2 = rvalid ? *(const float2*)(in + (size_t)(m0 + row) * DIM + cc * 4 + jp * 2)
                        : make_float2(0.f, 0.f);
#pragma unroll
    for (int q = 0; q < 2; q++) {
        float xv = q ? xv2.y : xv2.x;
        int cch = jp * 2 + q;
        uint32_t off = row * 64 + (SWZ32(cch, row) << 4);

        // silu hi/lo
        float sv = silu_f(xv);
        __nv_bfloat16 sh_ = __float2bfloat16_rn(sv);
        __nv_bfloat16 sl_ = __float2bfloat16_rn(sv - __bfloat162float(sh_));
        // zero-fill chunk with silu in slot 0
        *(uint4*)(Ah + off) = make_uint4((uint32_t)__bfloat16_as_ushort(sh_), 0u, 0u, 0u);
        *(uint4*)(Al + off) = make_uint4((uint32_t)__bfloat16_as_ushort(sl_), 0u, 0u, 0u);

        // spline cell + 4 weights
        float u = fmaf(2.0f, xv, 5.0f);
        float cf = floorf(u);
        float t = u - cf;
        bool inr = (u >= 0.0f) && (u < 10.0f);
        int c = (int)cf;
        float t2 = t * t, t3 = t2 * t, s1 = 1.0f - t;
        const float i6 = 1.0f / 6.0f;
        float w[4];
        w[0] = t3 * i6;                                                    // j == c
        w[1] = fmaf(-3.0f, t3, fmaf(3.0f, t2, fmaf(3.0f, t, 1.0f))) * i6; // j == c-1
        w[2] = fmaf(3.0f, t3, fmaf(-6.0f, t2, 4.0f)) * i6;                // j == c-2
        w[3] = s1 * s1 * s1 * i6;                                         // j == c-3
#pragma unroll
        for (int m = 0; m < 4; m++) {
            int j = c - m;
            __nv_bfloat16 wh_ = __float2bfloat16_rn(w[m]);
            __nv_bfloat16 wl_ = __float2bfloat16_rn(w[m] - __bfloat162float(wh_));
            if (inr && j >= 0 && j <= 6) {
                *(uint16_t*)(Ah + off + 2 * (j + 1)) = __bfloat16_as_ushort(wh_);
                *(uint16_t*)(Al + off + 2 * (j + 1)) = __bfloat16_as_ushort(wl_);
            }
        }
    }
#pragma unroll
    for (int q = 0; q < 2; q++) {
        int c = half * 2 + q;
        uint32_t off = n * 64 + (SWZ32(c, n) << 4);
        *(uint4*)(Bh + off) = q ? bh1 : bh0;
        *(uint4*)(Bl + off) = q ? bl1 : bl0;
    }
}

__global__ void __launch_bounds__(256, 2) fkan_gemm_mma(const float* __restrict__ in,
                                                        const float* __restrict__ attS,
                                                        const float* __restrict__ attD) {
    extern __shared__ char dsm[];
    int tid = threadIdx.x;
    int wid = tid >> 5, lane = tid & 31;
    int m0 = blockIdx.x * 128;
    int warpM = wid & 3, warpN = wid >> 2;
    uint32_t ubase = smem_u32(dsm);

    bool rvalid = (m0 + (tid & 127)) < NNODES;
    int tg = lane >> 3, tr = lane & 7;

    float acc[2][8][4];
#pragma unroll
    for (int f = 0; f < 2; f++)
#pragma unroll
        for (int j = 0; j < 8; j++)
#pragma unroll
            for (int q = 0; q < 4; q++) acc[f][j][q] = 0.0f;

    // prologue: build chunk 0 into buffer 0
    build_chunk(in, dsm, m0, tid, 0, rvalid);
    __syncthreads();

    for (int cc = 0; cc < 32; cc++) {
        int p = cc & 1;
        uint32_t uAh = ubase + p * 32768;
        uint32_t uAl = uAh + 8192;
        uint32_t uBh = uAh + 16384;
        uint32_t uBl = uAh + 24576;

        // ---- mma for chunk cc (tensor pipe) ----
#pragma unroll
        for (int ks = 0; ks < 2; ks++) {
            uint32_t ah[2][4], al[2][4];
#pragma unroll
            for (int f = 0; f < 2; f++) {
                int arow = warpM * 32 + f * 16 + (tg & 1) * 8 + tr;
                int ac = ks * 2 + (tg >> 1);
                uint32_t aoff = arow * 64 + (SWZ32(ac, arow) << 4);
                ldsm4(uAh + aoff, ah[f][0], ah[f][1], ah[f][2], ah[f][3]);
                ldsm4(uAl + aoff, al[f][0], al[f][1], al[f][2], al[f][3]);
            }
#pragma unroll
            for (int gh = 0; gh < 2; gh++) {
                uint32_t bh[2][4], bl[2][4];
#pragma unroll
                for (int gg = 0; gg < 2; gg++) {
                    int g = gh * 2 + gg;
                    int brow = warpN * 64 + g * 16 + (tg >> 1) * 8 + tr;
                    int bc = ks * 2 + (tg & 1);
                    uint32_t boff = brow * 64 + (SWZ32(bc, brow) << 4);
                    ldsm4(uBh + boff, bh[gg][0], bh[gg][1], bh[gg][2], bh[gg][3]);
                    ldsm4(uBl + boff, bl[gg][0], bl[gg][1], bl[gg][2], bl[gg][3]);
                }
#pragma unroll
                for (int f = 0; f < 2; f++)
#pragma unroll
                    for (int gg = 0; gg < 2; gg++) {
                        int g = gh * 2 + gg;
                        mma16816(acc[f][2 * g],     ah[f], &bh[gg][0]);
                        mma16816(acc[f][2 * g],     al[f], &bh[gg][0]);
                        mma16816(acc[f][2 * g],     ah[f], &bl[gg][0]);
                        mma16816(acc[f][2 * g + 1], ah[f], &bh[gg][2]);
                        mma16816(acc[f][2 * g + 1], al[f], &bh[gg][2]);
                        mma16816(acc[f][2 * g + 1], ah[f], &bl[gg][2]);
                    }
            }
        }

        // ---- build chunk cc+1 into the other buffer (fma pipe, overlaps tensor) ----
        if (cc < 31)
            build_chunk(in, dsm + (p ^ 1) * 32768, m0, tid, cc + 1, rvalid);
        __syncthreads();
    }

    // ---- epilogue: store h + fused attention dots ----
    int qd = lane >> 2, ql = lane & 3;
#pragma unroll
    for (int f = 0; f < 2; f++)
#pragma unroll
        for (int hh = 0; hh < 2; hh++) {
            int row = m0 + warpM * 32 + f * 16 + hh * 8 + qd;
            bool ok = row < NNODES;
            float ps0 = 0.f, pd0 = 0.f, ps1 = 0.f, pd1 = 0.f;
#pragma unroll
            for (int j = 0; j < 8; j++) {
                int col = warpN * 64 + j * 8 + ql * 2;
                float v0 = acc[f][j][hh * 2 + 0];
                float v1 = acc[f][j][hh * 2 + 1];
                if (ok) {
                    float2 st = make_float2(v0, v1);
                    *(float2*)&g_hl[(size_t)row * DIM + col] = st;
                }
                float s0 = __ldg(&attS[col]), s1 = __ldg(&attS[col + 1]);
                float d0 = __ldg(&attD[col]), d1 = __ldg(&attD[col + 1]);
                float ps = v0 * s0 + v1 * s1;
                float pd = v0 * d0 + v1 * d1;
                if (j < 4) { ps0 += ps; pd0 += pd; } else { ps1 += ps; pd1 += pd; }
            }
#pragma unroll
            for (int o = 1; o <= 2; o <<= 1) {
                ps0 += __shfl_xor_sync(0xffffffffu, ps0, o);
                pd0 += __shfl_xor_sync(0xffffffffu, pd0, o);
                ps1 += __shfl_xor_sync(0xffffffffu, ps1, o);
                pd1 += __shfl_xor_sync(0xffffffffu, pd1, o);
            }
            if (ql == 0 && ok) {
                int hbase = warpN * 2;
                g_asrc[row * 4 + hbase]     = ps0;
                g_asrc[row * 4 + hbase + 1] = ps1;
                g_adst[row * 4 + hbase]     = pd0;
                g_adst[row * 4 + hbase + 1] = pd1;
            }
        }
}

// ---------------- fused pull-mode edge phase ----------------
__global__ void __launch_bounds__(256) edge_fused_kernel(const float* __restrict__ bias) {
    int gid = blockIdx.x * blockDim.x + threadIdx.x;
    int n = gid >> 5, lane = gid & 31;
    if (n >= NNODES) return;
    int start = __ldg(&g_ptr[n]);
    int end   = __ldg(&g_ptr[n + 1]);
    int hh = lane >> 3;
    float bd = g_adst[n * 4 + hh];

    float4 acc = make_float4(0.f, 0.f, 0.f, 0.f);
    float sumex = 0.0f;

    for (int j0 = start; j0 < end; j0 += 32) {
        int m = min(32, end - j0);
        int s_pref = (j0 + lane < end) ? __ldg(&g_csrc[j0 + lane]) : 0;
#pragma unroll 4
        for (int i = 0; i < m; i++) {
            int s = __shfl_sync(0xffffffffu, s_pref, i);
            float a = __ldg(&g_asrc[s * 4 + hh]);
            float e = a + bd;
            e = (e > 0.f) ? e : 0.2f * e;
            float ex = __expf(e);
            sumex += ex;
            float4 v = *(const float4*)&g_hl[(size_t)s * DIM + lane * 4];
            acc.x = fmaf(ex, v.x, acc.x);
            acc.y = fmaf(ex, v.y, acc.y);
            acc.z = fmaf(ex, v.z, acc.z);
            acc.w = fmaf(ex, v.w, acc.w);
        }
    }
    float inv = 1.0f / (sumex + 1e-16f);
    float4 b4 = *(const float4*)&bias[lane * 4];
    float4 o;
    o.x = silu_f(acc.x * inv + b4.x);
    o.y = silu_f(acc.y * inv + b4.y);
    o.z = silu_f(acc.z * inv + b4.z);
    o.w = silu_f(acc.w * inv + b4.w);
    *(float4*)&g_h[(size_t)n * DIM + lane * 4] = o;
}

// ---------------- pooling + readout ----------------
__global__ void pool_kernel(const int* __restrict__ batch) {
    int d0 = threadIdx.x;
    int r0 = blockIdx.x * 512;
    if (r0 >= NNODES) return;
    int rend = min(r0 + 512, NNODES);
    int cur = __ldg(&batch[r0]);
    float sum = 0.0f;
    for (int n = r0; n < rend; n++) {
        int g = __ldg(&batch[n]);
        if (g != cur) {
            atomicAdd(&g_pooled[cur * DIM + d0], sum);
            sum = 0.0f;
            cur = g;
        }
        sum += g_h[(size_t)n * DIM + d0];
    }
    atomicAdd(&g_pooled[cur * DIM + d0], sum);
}

__global__ void readout_kernel(const float* __restrict__ bw,
                               const float* __restrict__ sw,
                               const float* __restrict__ sc,
                               float* __restrict__ out) {
    __shared__ float feat[KDIM];
    __shared__ float sred[NCLS * 4];
    int g = blockIdx.x, t = threadIdx.x;
    float xv = g_pooled[g * DIM + t];
    feat[t] = xv / (1.0f + expf(-xv));
    float bs[7];
    bsplines7(xv, bs);
#pragma unroll
    for (int b = 0; b < 7; b++) feat[DIM + t * 7 + b] = bs[b];
    __syncthreads();

    float accv[NCLS];
#pragma unroll
    for (int o = 0; o < NCLS; o++) accv[o] = 0.0f;
#pragma unroll
    for (int kk = 0; kk < 8; kk++) {
        int k = kk * DIM + t;
        float f = feat[k];
        if (k < DIM) {
#pragma unroll
            for (int o = 0; o < NCLS; o++) accv[o] += f * bw[o * DIM + k];
        } else {
            int j = (k - DIM) / 7, b = (k - DIM) % 7;
#pragma unroll
            for (int o = 0; o < NCLS; o++)
                accv[o] += f * sw[o * DIM * NB + j * NB + b] * sc[o * DIM + j];
        }
    }
    int lane = t & 31, warp = t >> 5;
#pragma unroll
    for (int o = 0; o < NCLS; o++) {
        float v = accv[o];
#pragma unroll
        for (int off = 16; off >= 1; off >>= 1) v += __shfl_xor_sync(0xffffffffu, v, off);
        if (lane == 0) sred[o * 4 + warp] = v;
    }
    __syncthreads();
    if (t == 0) {
        float lg[NCLS];
        float mx = -1e30f;
#pragma unroll
        for (int o = 0; o < NCLS; o++) {
            lg[o] = sred[o * 4] + sred[o * 4 + 1] + sred[o * 4 + 2] + sred[o * 4 + 3];
            mx = fmaxf(mx, lg[o]);
        }
        float se = 0.0f;
#pragma unroll
        for (int o = 0; o < NCLS; o++) se += expf(lg[o] - mx);
        float lse = logf(se) + mx;
#pragma unroll
        for (int o = 0; o < NCLS; o++) out[g * NCLS + o] = lg[o] - lse;
    }
}

// ---------------- launch ----------------
extern "C" void kernel_launch(void* const* d_in, const int* in_sizes, int n_in,
                              void* d_out, int out_size) {
    const float* x        = (const float*)d_in[0];
    const int*   ei       = (const int*)d_in[1];
    const int*   batch    = (const int*)d_in[2];
    const float* base_w   = (const float*)d_in[3];
    const float* spline_w = (const float*)d_in[4];
    const float* scaler   = (const float*)d_in[5];
    const float* att_src  = (const float*)d_in[6];
    const float* att_dst  = (const float*)d_in[7];
    const float* bias     = (const float*)d_in[8];
    const float* ro_bw    = (const float*)d_in[9];
    const float* ro_sw    = (const float*)d_in[10];
    const float* ro_sc    = (const float*)d_in[11];
    float* out = (float*)d_out;

    cudaFuncSetAttribute(fkan_gemm_mma, cudaFuncAttributeMaxDynamicSharedMemorySize, SMEM_BYTES);

    float *hbuf = nullptr, *poolp = nullptr;
    int* degp = nullptr;
    cudaGetSymbolAddress((void**)&hbuf, g_h);
    cudaGetSymbolAddress((void**)&poolp, g_pooled);
    cudaGetSymbolAddress((void**)&degp, g_deg);

    const int E_BLOCKS = (ETOT + 255) / 256;

    // ---- CSR build (once per run) ----
    cudaMemsetAsync(degp, 0, NNODES * sizeof(int));
    deg_count_kernel<<<E_BLOCKS, 256>>>(ei);
    scan1_kernel<<<SCAN_BLOCKS, 1024>>>();
    scan2_kernel<<<1, 32>>>();
    scan3_kernel<<<SCAN_BLOCKS, 1024>>>();
    scatter_kernel<<<E_BLOCKS, 256>>>(ei);

    for (int l = 0; l < NLAYER; l++) {
        const float* in = (l == 0) ? x : hbuf;
        pack_w_kernel<<<(KDIM * DIM + 255) / 256, 256>>>(
            base_w + (size_t)l * DIM * DIM,
            spline_w + (size_t)l * DIM * DIM * NB,
            scaler + (size_t)l * DIM * DIM);
        fkan_gemm_mma<<<MTILES, 256, SMEM_BYTES>>>(
            in, att_src + (size_t)l * DIM, att_dst + (size_t)l * DIM);
        edge_fused_kernel<<<(NNODES * 32 + 255) / 256, 256>>>(bias + (size_t)l * DIM);
    }
    cudaMemsetAsync(poolp, 0, (size_t)NGR * DIM * sizeof(float));
    pool_kernel<<<(NNODES + 511) / 512, DIM>>>(batch);
    readout_kernel<<<NGR, DIM>>>(ro_bw, ro_sw, ro_sc, out);
}

// round 10
// speedup vs baseline: 1.2783x; 1.0344x over previous
#include <cuda_runtime.h>
#include <cuda_bf16.h>
#include <cstdint>

#define NNODES 50000
#define NEDGE  800000
#define ETOT   850000
#define DIM    128
#define NH     4
#define NB     7
#define KDIM   1024
#define NGR    64
#define NCLS   10
#define NLAYER 3

#define MTILES ((NNODES + 127) / 128)   // 391
#define SCAN_BLOCKS ((NNODES + 1023) / 1024)  // 49

// ---------------- device scratch ----------------
__device__ __align__(16) __nv_bfloat16 g_Wh[NLAYER * KDIM * DIM];
__device__ __align__(16) __nv_bfloat16 g_Wl[NLAYER * KDIM * DIM];
__device__ __align__(16) float g_h[NNODES * DIM];
__device__ __align__(16) float g_hl[NNODES * DIM];
__device__ __align__(16) float g_asrc[NNODES * NH];
__device__ __align__(16) float g_adst[NNODES * NH];
__device__ __align__(16) float g_pooled[NGR * DIM];
// CSR
__device__ int g_deg[NNODES];
__device__ int g_ptr[NNODES + 1];
__device__ int g_cur[NNODES];
__device__ int g_csrc[ETOT];
__device__ int g_bsum[SCAN_BLOCKS];
__device__ int g_boff[SCAN_BLOCKS];

// ---------------- helpers ----------------
__device__ __forceinline__ uint32_t smem_u32(const void* p) {
    uint32_t a;
    asm("{ .reg .u64 t; cvta.to.shared.u64 t, %1; cvt.u32.u64 %0, t; }" : "=r"(a) : "l"(p));
    return a;
}

// 16B-chunk swizzle within a 64B row (4 chunks): conflict-free for stores + ldmatrix
#define SWZ32(c, r) (((c) ^ ((r) >> 1)) & 3)

__device__ __forceinline__ void ldsm4(uint32_t a, uint32_t& r0, uint32_t& r1,
                                      uint32_t& r2, uint32_t& r3) {
    asm volatile("ldmatrix.sync.aligned.m8n8.x4.shared.b16 {%0,%1,%2,%3}, [%4];"
                 : "=r"(r0), "=r"(r1), "=r"(r2), "=r"(r3) : "r"(a));
}

__device__ __forceinline__ void mma16816(float* d, const uint32_t* a, const uint32_t* b) {
    asm volatile("mma.sync.aligned.m16n8k16.row.col.f32.bf16.bf16.f32 "
                 "{%0,%1,%2,%3}, {%4,%5,%6,%7}, {%8,%9}, {%0,%1,%2,%3};"
                 : "+f"(d[0]), "+f"(d[1]), "+f"(d[2]), "+f"(d[3])
                 : "r"(a[0]), "r"(a[1]), "r"(a[2]), "r"(a[3]), "r"(b[0]), "r"(b[1]));
}

__device__ __forceinline__ float silu_f(float x) { return x / (1.0f + __expf(-x)); }

// Cubic B-splines (Cox-de Boor recursion) — used only in small readout kernel.
__device__ __forceinline__ void bsplines7(float x, float* out) {
    float b0[10];
#pragma unroll
    for (int i = 0; i < 10; i++) {
        float g0 = 0.5f * (float)i - 2.5f;
        b0[i] = (x >= g0 && x < g0 + 0.5f) ? 1.0f : 0.0f;
    }
    float b1[9];
#pragma unroll
    for (int i = 0; i < 9; i++) {
        float gi = 0.5f * (float)i - 2.5f;
        b1[i] = (x - gi) * 2.0f * b0[i] + ((gi + 1.0f) - x) * 2.0f * b0[i + 1];
    }
    float b2[8];
#pragma unroll
    for (int i = 0; i < 8; i++) {
        float gi = 0.5f * (float)i - 2.5f;
        b2[i] = (x - gi) * b1[i] + ((gi + 1.5f) - x) * b1[i + 1];
    }
#pragma unroll
    for (int i = 0; i < 7; i++) {
        float gi = 0.5f * (float)i - 2.5f;
        out[i] = ((x - gi) * b2[i] + ((gi + 2.0f) - x) * b2[i + 1]) * (1.0f / 1.5f);
    }
}

// ---------------- CSR build ----------------
__global__ void deg_count_kernel(const int* __restrict__ ei) {
    int e = blockIdx.x * blockDim.x + threadIdx.x;
    if (e >= ETOT) return;
    int d = (e < NEDGE) ? __ldg(&ei[NEDGE + e]) : (e - NEDGE);
    atomicAdd(&g_deg[d], 1);
}

__global__ void scan1_kernel() {
    __shared__ int sh[1024];
    int t = threadIdx.x, b = blockIdx.x;
    int i = b * 1024 + t;
    int v = (i < NNODES) ? g_deg[i] : 0;
    sh[t] = v;
    __syncthreads();
#pragma unroll
    for (int off = 1; off < 1024; off <<= 1) {
        int add = (t >= off) ? sh[t - off] : 0;
        __syncthreads();
        sh[t] += add;
        __syncthreads();
    }
    if (i < NNODES) g_ptr[i] = sh[t] - v;
    if (t == 1023) g_bsum[b] = sh[t];
}

__global__ void scan2_kernel() {
    if (threadIdx.x == 0) {
        int run = 0;
        for (int b = 0; b < SCAN_BLOCKS; b++) { g_boff[b] = run; run += g_bsum[b]; }
        g_ptr[NNODES] = run;
    }
}

__global__ void scan3_kernel() {
    int t = threadIdx.x, b = blockIdx.x;
    int i = b * 1024 + t;
    if (i < NNODES) {
        int p = g_ptr[i] + g_boff[b];
        g_ptr[i] = p;
        g_cur[i] = p;
    }
}

__global__ void scatter_kernel(const int* __restrict__ ei) {
    int e = blockIdx.x * blockDim.x + threadIdx.x;
    if (e >= ETOT) return;
    int s, d;
    if (e < NEDGE) { s = __ldg(&ei[e]); d = __ldg(&ei[NEDGE + e]); }
    else           { s = e - NEDGE; d = s; }
    int pos = atomicAdd(&g_cur[d], 1);
    g_csrc[pos] = s;
}

// ---------------- weight pack (all 3 layers, once) ----------------
__global__ void pack_w_kernel(const float* __restrict__ bw,
                              const float* __restrict__ sw,
                              const float* __restrict__ sc) {
    int idx = blockIdx.x * blockDim.x + threadIdx.x;
    if (idx >= NLAYER * KDIM * DIM) return;
    int l = idx >> 17;
    int rem = idx & (KDIM * DIM - 1);
    int n = rem >> 10, k = rem & 1023;
    int j = k >> 3, f = k & 7;
    const float* bwl = bw + (size_t)l * DIM * DIM;
    const float* swl = sw + (size_t)l * DIM * DIM * NB;
    const float* scl = sc + (size_t)l * DIM * DIM;
    float v;
    if (f == 0) v = bwl[n * DIM + j];
    else        v = swl[(n * DIM + j) * NB + (f - 1)] * scl[n * DIM + j];
    __nv_bfloat16 h = __float2bfloat16_rn(v);
    g_Wh[idx] = h;
    g_Wl[idx] = __float2bfloat16_rn(v - __bfloat162float(h));
}

// ---------------- fused KAN-GEMM: pipelined double-buffered bf16 mma ----------------
// Buffer layout (per 32KB buffer): Ah[0,8K) Al[8K,16K) Bh[16K,24K) Bl[24K,32K)
// Tiles: 128 rows x 32 k (64B/row, 4 swizzled 16B chunks).
#define SMEM_BYTES 65536

__device__ __forceinline__ void build_chunk(const float* __restrict__ in,
                                            const __nv_bfloat16* __restrict__ Wh,
                                            const __nv_bfloat16* __restrict__ Wl,
                                            char* buf, int m0, int tid, int cc, bool rvalid) {
    char* Ah = buf;
    char* Al = buf + 8192;
    char* Bh = buf + 16384;
    char* Bl = buf + 24576;

    // B weights: LDG first (latency hidden behind feature math)
    int n = tid >> 1, half = tid & 1;
    const uint4* wh = (const uint4*)(Wh + (size_t)n * KDIM + cc * 32 + half * 16);
    const uint4* wl = (const uint4*)(Wl + (size_t)n * KDIM + cc * 32 + half * 16);
    uint4 bh0 = wh[0], bh1 = wh[1];
    uint4 bl0 = wl[0], bl1 = wl[1];

    // A features: 2 evals per thread. Closed-form cardinal cubic B-spline with
    // direct scatter of the <=4 nonzero bases.
    int row = tid & 127, jp = tid >> 7;
    float2 xv2 = rvalid ? *(const float2*)(in + (size_t)(m0 + row) * DIM + cc * 4 + jp * 2)
                        : make_float2(0.f, 0.f);
#pragma unroll
    for (int q = 0; q < 2; q++) {
        float xv = q ? xv2.y : xv2.x;
        int cch = jp * 2 + q;
        uint32_t off = row * 64 + (SWZ32(cch, row) << 4);

        // silu hi/lo
        float sv = silu_f(xv);
        __nv_bfloat16 sh_ = __float2bfloat16_rn(sv);
        __nv_bfloat16 sl_ = __float2bfloat16_rn(sv - __bfloat162float(sh_));
        *(uint4*)(Ah + off) = make_uint4((uint32_t)__bfloat16_as_ushort(sh_), 0u, 0u, 0u);
        *(uint4*)(Al + off) = make_uint4((uint32_t)__bfloat16_as_ushort(sl_), 0u, 0u, 0u);

        // spline cell + 4 weights
        float u = fmaf(2.0f, xv, 5.0f);
        float cf = floorf(u);
        float t = u - cf;
        bool inr = (u >= 0.0f) && (u < 10.0f);
        int c = (int)cf;
        float t2 = t * t, t3 = t2 * t, s1 = 1.0f - t;
        const float i6 = 1.0f / 6.0f;
        float w[4];
        w[0] = t3 * i6;
        w[1] = fmaf(-3.0f, t3, fmaf(3.0f, t2, fmaf(3.0f, t, 1.0f))) * i6;
        w[2] = fmaf(3.0f, t3, fmaf(-6.0f, t2, 4.0f)) * i6;
        w[3] = s1 * s1 * s1 * i6;
#pragma unroll
        for (int m = 0; m < 4; m++) {
            int j = c - m;
            __nv_bfloat16 wh_ = __float2bfloat16_rn(w[m]);
            __nv_bfloat16 wl_ = __float2bfloat16_rn(w[m] - __bfloat162float(wh_));
            if (inr && j >= 0 && j <= 6) {
                *(uint16_t*)(Ah + off + 2 * (j + 1)) = __bfloat16_as_ushort(wh_);
                *(uint16_t*)(Al + off + 2 * (j + 1)) = __bfloat16_as_ushort(wl_);
            }
        }
    }
#pragma unroll
    for (int q = 0; q < 2; q++) {
        int c = half * 2 + q;
        uint32_t off = n * 64 + (SWZ32(c, n) << 4);
        *(uint4*)(Bh + off) = q ? bh1 : bh0;
        *(uint4*)(Bl + off) = q ? bl1 : bl0;
    }
}

__global__ void __launch_bounds__(256, 2) fkan_gemm_mma(const float* __restrict__ in,
                                                        const float* __restrict__ attS,
                                                        const float* __restrict__ attD,
                                                        const __nv_bfloat16* __restrict__ Wh,
                                                        const __nv_bfloat16* __restrict__ Wl) {
    extern __shared__ char dsm[];
    int tid = threadIdx.x;
    int wid = tid >> 5, lane = tid & 31;
    int m0 = blockIdx.x * 128;
    int warpM = wid & 3, warpN = wid >> 2;
    uint32_t ubase = smem_u32(dsm);

    bool rvalid = (m0 + (tid & 127)) < NNODES;
    int tg = lane >> 3, tr = lane & 7;

    float acc[2][8][4];
#pragma unroll
    for (int f = 0; f < 2; f++)
#pragma unroll
        for (int j = 0; j < 8; j++)
#pragma unroll
            for (int q = 0; q < 4; q++) acc[f][j][q] = 0.0f;

    // prologue: build chunk 0 into buffer 0
    build_chunk(in, Wh, Wl, dsm, m0, tid, 0, rvalid);
    __syncthreads();

    for (int cc = 0; cc < 32; cc++) {
        int p = cc & 1;
        uint32_t uAh = ubase + p * 32768;
        uint32_t uAl = uAh + 8192;
        uint32_t uBh = uAh + 16384;
        uint32_t uBl = uAh + 24576;

        // ---- mma for chunk cc (tensor pipe) ----
#pragma unroll
        for (int ks = 0; ks < 2; ks++) {
            uint32_t ah[2][4], al[2][4];
#pragma unroll
            for (int f = 0; f < 2; f++) {
                int arow = warpM * 32 + f * 16 + (tg & 1) * 8 + tr;
                int ac = ks * 2 + (tg >> 1);
                uint32_t aoff = arow * 64 + (SWZ32(ac, arow) << 4);
                ldsm4(uAh + aoff, ah[f][0], ah[f][1], ah[f][2], ah[f][3]);
                ldsm4(uAl + aoff, al[f][0], al[f][1], al[f][2], al[f][3]);
            }
#pragma unroll
            for (int gh = 0; gh < 2; gh++) {
                uint32_t bh[2][4], bl[2][4];
#pragma unroll
                for (int gg = 0; gg < 2; gg++) {
                    int g = gh * 2 + gg;
                    int brow = warpN * 64 + g * 16 + (tg >> 1) * 8 + tr;
                    int bc = ks * 2 + (tg & 1);
                    uint32_t boff = brow * 64 + (SWZ32(bc, brow) << 4);
                    ldsm4(uBh + boff, bh[gg][0], bh[gg][1], bh[gg][2], bh[gg][3]);
                    ldsm4(uBl + boff, bl[gg][0], bl[gg][1], bl[gg][2], bl[gg][3]);
                }
#pragma unroll
                for (int f = 0; f < 2; f++)
#pragma unroll
                    for (int gg = 0; gg < 2; gg++) {
                        int g = gh * 2 + gg;
                        mma16816(acc[f][2 * g],     ah[f], &bh[gg][0]);
                        mma16816(acc[f][2 * g],     al[f], &bh[gg][0]);
                        mma16816(acc[f][2 * g],     ah[f], &bl[gg][0]);
                        mma16816(acc[f][2 * g + 1], ah[f], &bh[gg][2]);
                        mma16816(acc[f][2 * g + 1], al[f], &bh[gg][2]);
                        mma16816(acc[f][2 * g + 1], ah[f], &bl[gg][2]);
                    }
            }
        }

        // ---- build chunk cc+1 into the other buffer (fma pipe, overlaps tensor) ----
        if (cc < 31)
            build_chunk(in, Wh, Wl, dsm + (p ^ 1) * 32768, m0, tid, cc + 1, rvalid);
        __syncthreads();
    }

    // ---- epilogue: store h + fused attention dots ----
    int qd = lane >> 2, ql = lane & 3;
#pragma unroll
    for (int f = 0; f < 2; f++)
#pragma unroll
        for (int hh = 0; hh < 2; hh++) {
            int row = m0 + warpM * 32 + f * 16 + hh * 8 + qd;
            bool ok = row < NNODES;
            float ps0 = 0.f, pd0 = 0.f, ps1 = 0.f, pd1 = 0.f;
#pragma unroll
            for (int j = 0; j < 8; j++) {
                int col = warpN * 64 + j * 8 + ql * 2;
                float v0 = acc[f][j][hh * 2 + 0];
                float v1 = acc[f][j][hh * 2 + 1];
                if (ok) {
                    float2 st = make_float2(v0, v1);
                    *(float2*)&g_hl[(size_t)row * DIM + col] = st;
                }
                float s0 = __ldg(&attS[col]), s1 = __ldg(&attS[col + 1]);
                float d0 = __ldg(&attD[col]), d1 = __ldg(&attD[col + 1]);
                float ps = v0 * s0 + v1 * s1;
                float pd = v0 * d0 + v1 * d1;
                if (j < 4) { ps0 += ps; pd0 += pd; } else { ps1 += ps; pd1 += pd; }
            }
#pragma unroll
            for (int o = 1; o <= 2; o <<= 1) {
                ps0 += __shfl_xor_sync(0xffffffffu, ps0, o);
                pd0 += __shfl_xor_sync(0xffffffffu, pd0, o);
                ps1 += __shfl_xor_sync(0xffffffffu, ps1, o);
                pd1 += __shfl_xor_sync(0xffffffffu, pd1, o);
            }
            if (ql == 0 && ok) {
                int hbase = warpN * 2;
                g_asrc[row * 4 + hbase]     = ps0;
                g_asrc[row * 4 + hbase + 1] = ps1;
                g_adst[row * 4 + hbase]     = pd0;
                g_adst[row * 4 + hbase + 1] = pd1;
            }
        }
}

// ---------------- fused pull-mode edge phase ----------------
__global__ void __launch_bounds__(256) edge_fused_kernel(const float* __restrict__ bias) {
    int gid = blockIdx.x * blockDim.x + threadIdx.x;
    int n = gid >> 5, lane = gid & 31;
    if (n >= NNODES) return;
    int start = __ldg(&g_ptr[n]);
    int end   = __ldg(&g_ptr[n + 1]);
    int hh = lane >> 3;
    float bd = g_adst[n * 4 + hh];

    float4 acc = make_float4(0.f, 0.f, 0.f, 0.f);
    float sumex = 0.0f;

    for (int j0 = start; j0 < end; j0 += 32) {
        int m = min(32, end - j0);
        int s_pref = (j0 + lane < end) ? __ldg(&g_csrc[j0 + lane]) : 0;
#pragma unroll 4
        for (int i = 0; i < m; i++) {
            int s = __shfl_sync(0xffffffffu, s_pref, i);
            float a = __ldg(&g_asrc[s * 4 + hh]);
            float e = a + bd;
            e = (e > 0.f) ? e : 0.2f * e;
            float ex = __expf(e);
            sumex += ex;
            float4 v = *(const float4*)&g_hl[(size_t)s * DIM + lane * 4];
            acc.x = fmaf(ex, v.x, acc.x);
            acc.y = fmaf(ex, v.y, acc.y);
            acc.z = fmaf(ex, v.z, acc.z);
            acc.w = fmaf(ex, v.w, acc.w);
        }
    }
    float inv = 1.0f / (sumex + 1e-16f);
    float4 b4 = *(const float4*)&bias[lane * 4];
    float4 o;
    o.x = silu_f(acc.x * inv + b4.x);
    o.y = silu_f(acc.y * inv + b4.y);
    o.z = silu_f(acc.z * inv + b4.z);
    o.w = silu_f(acc.w * inv + b4.w);
    *(float4*)&g_h[(size_t)n * DIM + lane * 4] = o;
}

// ---------------- pooling + readout ----------------
__global__ void pool_kernel(const int* __restrict__ batch) {
    int d0 = threadIdx.x;
    int r0 = blockIdx.x * 512;
    if (r0 >= NNODES) return;
    int rend = min(r0 + 512, NNODES);
    int cur = __ldg(&batch[r0]);
    float sum = 0.0f;
    for (int n = r0; n < rend; n++) {
        int g = __ldg(&batch[n]);
        if (g != cur) {
            atomicAdd(&g_pooled[cur * DIM + d0], sum);
            sum = 0.0f;
            cur = g;
        }
        sum += g_h[(size_t)n * DIM + d0];
    }
    atomicAdd(&g_pooled[cur * DIM + d0], sum);
}

__global__ void readout_kernel(const float* __restrict__ bw,
                               const float* __restrict__ sw,
                               const float* __restrict__ sc,
                               float* __restrict__ out) {
    __shared__ float feat[KDIM];
    __shared__ float sred[NCLS * 4];
    int g = blockIdx.x, t = threadIdx.x;
    float xv = g_pooled[g * DIM + t];
    feat[t] = xv / (1.0f + expf(-xv));
    float bs[7];
    bsplines7(xv, bs);
#pragma unroll
    for (int b = 0; b < 7; b++) feat[DIM + t * 7 + b] = bs[b];
    __syncthreads();

    float accv[NCLS];
#pragma unroll
    for (int o = 0; o < NCLS; o++) accv[o] = 0.0f;
#pragma unroll
    for (int kk = 0; kk < 8; kk++) {
        int k = kk * DIM + t;
        float f = feat[k];
        if (k < DIM) {
#pragma unroll
            for (int o = 0; o < NCLS; o++) accv[o] += f * bw[o * DIM + k];
        } else {
            int j = (k - DIM) / 7, b = (k - DIM) % 7;
#pragma unroll
            for (int o = 0; o < NCLS; o++)
                accv[o] += f * sw[o * DIM * NB + j * NB + b] * sc[o * DIM + j];
        }
    }
    int lane = t & 31, warp = t >> 5;
#pragma unroll
    for (int o = 0; o < NCLS; o++) {
        float v = accv[o];
#pragma unroll
        for (int off = 16; off >= 1; off >>= 1) v += __shfl_xor_sync(0xffffffffu, v, off);
        if (lane == 0) sred[o * 4 + warp] = v;
    }
    __syncthreads();
    if (t == 0) {
        float lg[NCLS];
        float mx = -1e30f;
#pragma unroll
        for (int o = 0; o < NCLS; o++) {
            lg[o] = sred[o * 4] + sred[o * 4 + 1] + sred[o * 4 + 2] + sred[o * 4 + 3];
            mx = fmaxf(mx, lg[o]);
        }
        float se = 0.0f;
#pragma unroll
        for (int o = 0; o < NCLS; o++) se += expf(lg[o] - mx);
        float lse = logf(se) + mx;
#pragma unroll
        for (int o = 0; o < NCLS; o++) out[g * NCLS + o] = lg[o] - lse;
    }
}

// ---------------- launch ----------------
extern "C" void kernel_launch(void* const* d_in, const int* in_sizes, int n_in,
                              void* d_out, int out_size) {
    const float* x        = (const float*)d_in[0];
    const int*   ei       = (const int*)d_in[1];
    const int*   batch    = (const int*)d_in[2];
    const float* base_w   = (const float*)d_in[3];
    const float* spline_w = (const float*)d_in[4];
    const float* scaler   = (const float*)d_in[5];
    const float* att_src  = (const float*)d_in[6];
    const float* att_dst  = (const float*)d_in[7];
    const float* bias     = (const float*)d_in[8];
    const float* ro_bw    = (const float*)d_in[9];
    const float* ro_sw    = (const float*)d_in[10];
    const float* ro_sc    = (const float*)d_in[11];
    float* out = (float*)d_out;

    cudaFuncSetAttribute(fkan_gemm_mma, cudaFuncAttributeMaxDynamicSharedMemorySize, SMEM_BYTES);

    float *hbuf = nullptr, *poolp = nullptr;
    int* degp = nullptr;
    __nv_bfloat16 *whp = nullptr, *wlp = nullptr;
    cudaGetSymbolAddress((void**)&hbuf, g_h);
    cudaGetSymbolAddress((void**)&poolp, g_pooled);
    cudaGetSymbolAddress((void**)&degp, g_deg);
    cudaGetSymbolAddress((void**)&whp, g_Wh);
    cudaGetSymbolAddress((void**)&wlp, g_Wl);

    // side stream + events (created once, on the uncaptured correctness call;
    // reused inside graph capture as a fork/join — no allocation thereafter)
    static cudaStream_t s_side = nullptr;
    static cudaEvent_t ev_fork = nullptr, ev_join = nullptr;
    if (s_side == nullptr) {
        cudaStreamCreateWithFlags(&s_side, cudaStreamNonBlocking);
        cudaEventCreateWithFlags(&ev_fork, cudaEventDisableTiming);
        cudaEventCreateWithFlags(&ev_join, cudaEventDisableTiming);
    }

    const int E_BLOCKS = (ETOT + 255) / 256;

    // ---- fork: CSR build + pooled zero on side stream ----
    cudaEventRecord(ev_fork, 0);
    cudaStreamWaitEvent(s_side, ev_fork, 0);
    cudaMemsetAsync(degp, 0, NNODES * sizeof(int), s_side);
    deg_count_kernel<<<E_BLOCKS, 256, 0, s_side>>>(ei);
    scan1_kernel<<<SCAN_BLOCKS, 1024, 0, s_side>>>();
    scan2_kernel<<<1, 32, 0, s_side>>>();
    scan3_kernel<<<SCAN_BLOCKS, 1024, 0, s_side>>>();
    scatter_kernel<<<E_BLOCKS, 256, 0, s_side>>>(ei);
    cudaMemsetAsync(poolp, 0, (size_t)NGR * DIM * sizeof(float), s_side);
    cudaEventRecord(ev_join, s_side);

    // ---- main stream: pack all layers, layer-0 GEMM (independent of CSR) ----
    pack_w_kernel<<<(NLAYER * KDIM * DIM + 255) / 256, 256>>>(base_w, spline_w, scaler);
    fkan_gemm_mma<<<MTILES, 256, SMEM_BYTES>>>(
        x, att_src, att_dst, whp, wlp);

    // join: edge phase needs the CSR
    cudaStreamWaitEvent(0, ev_join, 0);
    edge_fused_kernel<<<(NNODES * 32 + 255) / 256, 256>>>(bias);

    for (int l = 1; l < NLAYER; l++) {
        fkan_gemm_mma<<<MTILES, 256, SMEM_BYTES>>>(
            hbuf, att_src + (size_t)l * DIM, att_dst + (size_t)l * DIM,
            whp + (size_t)l * KDIM * DIM, wlp + (size_t)l * KDIM * DIM);
        edge_fused_kernel<<<(NNODES * 32 + 255) / 256, 256>>>(bias + (size_t)l * DIM);
    }
    pool_kernel<<<(NNODES + 511) / 512, DIM>>>(batch);
    readout_kernel<<<NGR, DIM>>>(ro_bw, ro_sw, ro_sc, out);
}

// round 11
// speedup vs baseline: 1.4265x; 1.1159x over previous
#include <cuda_runtime.h>
#include <cuda_fp16.h>
#include <cstdint>

#define NNODES 50000
#define NEDGE  800000
#define ETOT   850000
#define DIM    128
#define NH     4
#define NB     7
#define KDIM   1024
#define NGR    64
#define NCLS   10
#define NLAYER 3

#define MTILES ((NNODES + 127) / 128)   // 391
#define SCAN_BLOCKS ((NNODES + 1023) / 1024)  // 49

// ---------------- device scratch ----------------
__device__ __align__(16) __half g_W16[NLAYER * KDIM * DIM];   // packed fp16 weights [l][n][k]
__device__ __align__(16) float g_h[NNODES * DIM];
__device__ __align__(16) float g_hl[NNODES * DIM];
__device__ __align__(16) float g_asrc[NNODES * NH];
__device__ __align__(16) float g_adst[NNODES * NH];
__device__ __align__(16) float g_pooled[NGR * DIM];
// CSR
__device__ int g_deg[NNODES];
__device__ int g_ptr[NNODES + 1];
__device__ int g_cur[NNODES];
__device__ int g_csrc[ETOT];
__device__ int g_bsum[SCAN_BLOCKS];
__device__ int g_boff[SCAN_BLOCKS];

// ---------------- helpers ----------------
__device__ __forceinline__ uint32_t smem_u32(const void* p) {
    uint32_t a;
    asm("{ .reg .u64 t; cvta.to.shared.u64 t, %1; cvt.u32.u64 %0, t; }" : "=r"(a) : "l"(p));
    return a;
}

// 16B-chunk swizzle within a 64B row (4 chunks): conflict-free for stores + ldmatrix
#define SWZ32(c, r) (((c) ^ ((r) >> 1)) & 3)

__device__ __forceinline__ void ldsm4(uint32_t a, uint32_t& r0, uint32_t& r1,
                                      uint32_t& r2, uint32_t& r3) {
    asm volatile("ldmatrix.sync.aligned.m8n8.x4.shared.b16 {%0,%1,%2,%3}, [%4];"
                 : "=r"(r0), "=r"(r1), "=r"(r2), "=r"(r3) : "r"(a));
}

__device__ __forceinline__ void mma16816(float* d, const uint32_t* a, const uint32_t* b) {
    asm volatile("mma.sync.aligned.m16n8k16.row.col.f32.f16.f16.f32 "
                 "{%0,%1,%2,%3}, {%4,%5,%6,%7}, {%8,%9}, {%0,%1,%2,%3};"
                 : "+f"(d[0]), "+f"(d[1]), "+f"(d[2]), "+f"(d[3])
                 : "r"(a[0]), "r"(a[1]), "r"(a[2]), "r"(a[3]), "r"(b[0]), "r"(b[1]));
}

__device__ __forceinline__ float silu_f(float x) { return x / (1.0f + __expf(-x)); }

// Cubic B-splines (Cox-de Boor recursion) — used only in small readout kernel.
__device__ __forceinline__ void bsplines7(float x, float* out) {
    float b0[10];
#pragma unroll
    for (int i = 0; i < 10; i++) {
        float g0 = 0.5f * (float)i - 2.5f;
        b0[i] = (x >= g0 && x < g0 + 0.5f) ? 1.0f : 0.0f;
    }
    float b1[9];
#pragma unroll
    for (int i = 0; i < 9; i++) {
        float gi = 0.5f * (float)i - 2.5f;
        b1[i] = (x - gi) * 2.0f * b0[i] + ((gi + 1.0f) - x) * 2.0f * b0[i + 1];
    }
    float b2[8];
#pragma unroll
    for (int i = 0; i < 8; i++) {
        float gi = 0.5f * (float)i - 2.5f;
        b2[i] = (x - gi) * b1[i] + ((gi + 1.5f) - x) * b1[i + 1];
    }
#pragma unroll
    for (int i = 0; i < 7; i++) {
        float gi = 0.5f * (float)i - 2.5f;
        out[i] = ((x - gi) * b2[i] + ((gi + 2.0f) - x) * b2[i + 1]) * (1.0f / 1.5f);
    }
}

// pack (a,b) to f16x2 hi (low half = a), residual to f16x2 lo
__device__ __forceinline__ uint32_t pack_hilo_f16(float a, float b, uint32_t& lo) {
    uint32_t hp;
    asm("cvt.rn.f16x2.f32 %0, %1, %2;" : "=r"(hp) : "f"(b), "f"(a));
    float ha = __half2float(__ushort_as_half((unsigned short)(hp & 0xFFFFu)));
    float hb = __half2float(__ushort_as_half((unsigned short)(hp >> 16)));
    float la = a - ha, lb = b - hb;
    asm("cvt.rn.f16x2.f32 %0, %1, %2;" : "=r"(lo) : "f"(lb), "f"(la));
    return hp;
}

// ---------------- CSR build ----------------
__global__ void deg_count_kernel(const int* __restrict__ ei) {
    int e = blockIdx.x * blockDim.x + threadIdx.x;
    if (e >= ETOT) return;
    int d = (e < NEDGE) ? __ldg(&ei[NEDGE + e]) : (e - NEDGE);
    atomicAdd(&g_deg[d], 1);
}

__global__ void scan1_kernel() {
    __shared__ int sh[1024];
    int t = threadIdx.x, b = blockIdx.x;
    int i = b * 1024 + t;
    int v = (i < NNODES) ? g_deg[i] : 0;
    sh[t] = v;
    __syncthreads();
#pragma unroll
    for (int off = 1; off < 1024; off <<= 1) {
        int add = (t >= off) ? sh[t - off] : 0;
        __syncthreads();
        sh[t] += add;
        __syncthreads();
    }
    if (i < NNODES) g_ptr[i] = sh[t] - v;
    if (t == 1023) g_bsum[b] = sh[t];
}

__global__ void scan2_kernel() {
    if (threadIdx.x == 0) {
        int run = 0;
        for (int b = 0; b < SCAN_BLOCKS; b++) { g_boff[b] = run; run += g_bsum[b]; }
        g_ptr[NNODES] = run;
    }
}

__global__ void scan3_kernel() {
    int t = threadIdx.x, b = blockIdx.x;
    int i = b * 1024 + t;
    if (i < NNODES) {
        int p = g_ptr[i] + g_boff[b];
        g_ptr[i] = p;
        g_cur[i] = p;
    }
}

__global__ void scatter_kernel(const int* __restrict__ ei) {
    int e = blockIdx.x * blockDim.x + threadIdx.x;
    if (e >= ETOT) return;
    int s, d;
    if (e < NEDGE) { s = __ldg(&ei[e]); d = __ldg(&ei[NEDGE + e]); }
    else           { s = e - NEDGE; d = s; }
    int pos = atomicAdd(&g_cur[d], 1);
    g_csrc[pos] = s;
}

// ---------------- weight pack (all 3 layers, once, fp16) ----------------
__global__ void pack_w_kernel(const float* __restrict__ bw,
                              const float* __restrict__ sw,
                              const float* __restrict__ sc) {
    int idx = blockIdx.x * blockDim.x + threadIdx.x;
    if (idx >= NLAYER * KDIM * DIM) return;
    int l = idx >> 17;
    int rem = idx & (KDIM * DIM - 1);
    int n = rem >> 10, k = rem & 1023;
    int j = k >> 3, f = k & 7;
    const float* bwl = bw + (size_t)l * DIM * DIM;
    const float* swl = sw + (size_t)l * DIM * DIM * NB;
    const float* scl = sc + (size_t)l * DIM * DIM;
    float v;
    if (f == 0) v = bwl[n * DIM + j];
    else        v = swl[(n * DIM + j) * NB + (f - 1)] * scl[n * DIM + j];
    g_W16[idx] = __float2half_rn(v);
}

// ---------------- fused KAN-GEMM: pipelined double-buffered fp16 mma (2-product A-split) ----
// Buffer layout (per 24KB buffer): Ah[0,8K) Al[8K,16K) Bh[16K,24K)
// Tiles: 128 rows x 32 k (64B/row, 4 swizzled 16B chunks).
#define SMEM_BYTES 49152

__device__ __forceinline__ void build_chunk(const float* __restrict__ in,
                                            const __half* __restrict__ W16,
                                            char* buf, int m0, int tid, int cc, bool rvalid) {
    char* Ah = buf;
    char* Al = buf + 8192;
    char* Bh = buf + 16384;

    // B weights: LDG first (latency hidden behind feature math)
    int n = tid >> 1, half = tid & 1;
    const uint4* wh = (const uint4*)(W16 + (size_t)n * KDIM + cc * 32 + half * 16);
    uint4 bh0 = wh[0], bh1 = wh[1];

    // A features: 2 evals per thread (row, cols jp*2 + {0,1}), fp16 hi/lo
    int row = tid & 127, jp = tid >> 7;
    float2 xv2 = rvalid ? *(const float2*)(in + (size_t)(m0 + row) * DIM + cc * 4 + jp * 2)
                        : make_float2(0.f, 0.f);
#pragma unroll
    for (int q = 0; q < 2; q++) {
        float xv = q ? xv2.y : xv2.x;
        float fv[8];
        fv[0] = silu_f(xv);
        bsplines7(xv, fv + 1);
        uint4 uh, ul;
        uh.x = pack_hilo_f16(fv[0], fv[1], ul.x);
        uh.y = pack_hilo_f16(fv[2], fv[3], ul.y);
        uh.z = pack_hilo_f16(fv[4], fv[5], ul.z);
        uh.w = pack_hilo_f16(fv[6], fv[7], ul.w);
        int c = jp * 2 + q;
        uint32_t off = row * 64 + (SWZ32(c, row) << 4);
        *(uint4*)(Ah + off) = uh;
        *(uint4*)(Al + off) = ul;
    }
#pragma unroll
    for (int q = 0; q < 2; q++) {
        int c = half * 2 + q;
        uint32_t off = n * 64 + (SWZ32(c, n) << 4);
        *(uint4*)(Bh + off) = q ? bh1 : bh0;
    }
}

__global__ void __launch_bounds__(256, 2) fkan_gemm_mma(const float* __restrict__ in,
                                                        const float* __restrict__ attS,
                                                        const float* __restrict__ attD,
                                                        const __half* __restrict__ W16) {
    extern __shared__ char dsm[];
    int tid = threadIdx.x;
    int wid = tid >> 5, lane = tid & 31;
    int m0 = blockIdx.x * 128;
    int warpM = wid & 3, warpN = wid >> 2;
    uint32_t ubase = smem_u32(dsm);

    bool rvalid = (m0 + (tid & 127)) < NNODES;
    int tg = lane >> 3, tr = lane & 7;

    float acc[2][8][4];
#pragma unroll
    for (int f = 0; f < 2; f++)
#pragma unroll
        for (int j = 0; j < 8; j++)
#pragma unroll
            for (int q = 0; q < 4; q++) acc[f][j][q] = 0.0f;

    // prologue: build chunk 0 into buffer 0
    build_chunk(in, W16, dsm, m0, tid, 0, rvalid);
    __syncthreads();

    for (int cc = 0; cc < 32; cc++) {
        int p = cc & 1;
        uint32_t uAh = ubase + p * 24576;
        uint32_t uAl = uAh + 8192;
        uint32_t uBh = uAh + 16384;

        // ---- mma for chunk cc (tensor pipe) ----
#pragma unroll
        for (int ks = 0; ks < 2; ks++) {
            uint32_t ah[2][4], al[2][4];
#pragma unroll
            for (int f = 0; f < 2; f++) {
                int arow = warpM * 32 + f * 16 + (tg & 1) * 8 + tr;
                int ac = ks * 2 + (tg >> 1);
                uint32_t aoff = arow * 64 + (SWZ32(ac, arow) << 4);
                ldsm4(uAh + aoff, ah[f][0], ah[f][1], ah[f][2], ah[f][3]);
                ldsm4(uAl + aoff, al[f][0], al[f][1], al[f][2], al[f][3]);
            }
#pragma unroll
            for (int gh = 0; gh < 2; gh++) {
                uint32_t bh[2][4];
#pragma unroll
                for (int gg = 0; gg < 2; gg++) {
                    int g = gh * 2 + gg;
                    int brow = warpN * 64 + g * 16 + (tg >> 1) * 8 + tr;
                    int bc = ks * 2 + (tg & 1);
                    uint32_t boff = brow * 64 + (SWZ32(bc, brow) << 4);
                    ldsm4(uBh + boff, bh[gg][0], bh[gg][1], bh[gg][2], bh[gg][3]);
                }
#pragma unroll
                for (int f = 0; f < 2; f++)
#pragma unroll
                    for (int gg = 0; gg < 2; gg++) {
                        int g = gh * 2 + gg;
                        mma16816(acc[f][2 * g],     ah[f], &bh[gg][0]);
                        mma16816(acc[f][2 * g],     al[f], &bh[gg][0]);
                        mma16816(acc[f][2 * g + 1], ah[f], &bh[gg][2]);
                        mma16816(acc[f][2 * g + 1], al[f], &bh[gg][2]);
                    }
            }
        }

        // ---- build chunk cc+1 into the other buffer (fma pipe, overlaps tensor) ----
        if (cc < 31)
            build_chunk(in, W16, dsm + (p ^ 1) * 24576, m0, tid, cc + 1, rvalid);
        __syncthreads();
    }

    // ---- epilogue: store h + fused attention dots ----
    int qd = lane >> 2, ql = lane & 3;
#pragma unroll
    for (int f = 0; f < 2; f++)
#pragma unroll
        for (int hh = 0; hh < 2; hh++) {
            int row = m0 + warpM * 32 + f * 16 + hh * 8 + qd;
            bool ok = row < NNODES;
            float ps0 = 0.f, pd0 = 0.f, ps1 = 0.f, pd1 = 0.f;
#pragma unroll
            for (int j = 0; j < 8; j++) {
                int col = warpN * 64 + j * 8 + ql * 2;
                float v0 = acc[f][j][hh * 2 + 0];
                float v1 = acc[f][j][hh * 2 + 1];
                if (ok) {
                    float2 st = make_float2(v0, v1);
                    *(float2*)&g_hl[(size_t)row * DIM + col] = st;
                }
                float s0 = __ldg(&attS[col]), s1 = __ldg(&attS[col + 1]);
                float d0 = __ldg(&attD[col]), d1 = __ldg(&attD[col + 1]);
                float ps = v0 * s0 + v1 * s1;
                float pd = v0 * d0 + v1 * d1;
                if (j < 4) { ps0 += ps; pd0 += pd; } else { ps1 += ps; pd1 += pd; }
            }
#pragma unroll
            for (int o = 1; o <= 2; o <<= 1) {
                ps0 += __shfl_xor_sync(0xffffffffu, ps0, o);
                pd0 += __shfl_xor_sync(0xffffffffu, pd0, o);
                ps1 += __shfl_xor_sync(0xffffffffu, ps1, o);
                pd1 += __shfl_xor_sync(0xffffffffu, pd1, o);
            }
            if (ql == 0 && ok) {
                int hbase = warpN * 2;
                g_asrc[row * 4 + hbase]     = ps0;
                g_asrc[row * 4 + hbase + 1] = ps1;
                g_adst[row * 4 + hbase]     = pd0;
                g_adst[row * 4 + hbase + 1] = pd1;
            }
        }
}

// ---------------- fused pull-mode edge phase ----------------
__global__ void __launch_bounds__(256) edge_fused_kernel(const float* __restrict__ bias) {
    int gid = blockIdx.x * blockDim.x + threadIdx.x;
    int n = gid >> 5, lane = gid & 31;
    if (n >= NNODES) return;
    int start = __ldg(&g_ptr[n]);
    int end   = __ldg(&g_ptr[n + 1]);
    int hh = lane >> 3;
    float bd = g_adst[n * 4 + hh];

    float4 acc = make_float4(0.f, 0.f, 0.f, 0.f);
    float sumex = 0.0f;

    for (int j0 = start; j0 < end; j0 += 32) {
        int m = min(32, end - j0);
        int s_pref = (j0 + lane < end) ? __ldg(&g_csrc[j0 + lane]) : 0;
#pragma unroll 4
        for (int i = 0; i < m; i++) {
            int s = __shfl_sync(0xffffffffu, s_pref, i);
            float a = __ldg(&g_asrc[s * 4 + hh]);
            float e = a + bd;
            e = (e > 0.f) ? e : 0.2f * e;
            float ex = __expf(e);
            sumex += ex;
            float4 v = *(const float4*)&g_hl[(size_t)s * DIM + lane * 4];
            acc.x = fmaf(ex, v.x, acc.x);
            acc.y = fmaf(ex, v.y, acc.y);
            acc.z = fmaf(ex, v.z, acc.z);
            acc.w = fmaf(ex, v.w, acc.w);
        }
    }
    float inv = 1.0f / (sumex + 1e-16f);
    float4 b4 = *(const float4*)&bias[lane * 4];
    float4 o;
    o.x = silu_f(acc.x * inv + b4.x);
    o.y = silu_f(acc.y * inv + b4.y);
    o.z = silu_f(acc.z * inv + b4.z);
    o.w = silu_f(acc.w * inv + b4.w);
    *(float4*)&g_h[(size_t)n * DIM + lane * 4] = o;
}

// ---------------- pooling + readout ----------------
__global__ void pool_kernel(const int* __restrict__ batch) {
    int d0 = threadIdx.x;
    int r0 = blockIdx.x * 512;
    if (r0 >= NNODES) return;
    int rend = min(r0 + 512, NNODES);
    int cur = __ldg(&batch[r0]);
    float sum = 0.0f;
    for (int n = r0; n < rend; n++) {
        int g = __ldg(&batch[n]);
        if (g != cur) {
            atomicAdd(&g_pooled[cur * DIM + d0], sum);
            sum = 0.0f;
            cur = g;
        }
        sum += g_h[(size_t)n * DIM + d0];
    }
    atomicAdd(&g_pooled[cur * DIM + d0], sum);
}

__global__ void readout_kernel(const float* __restrict__ bw,
                               const float* __restrict__ sw,
                               const float* __restrict__ sc,
                               float* __restrict__ out) {
    __shared__ float feat[KDIM];
    __shared__ float sred[NCLS * 4];
    int g = blockIdx.x, t = threadIdx.x;
    float xv = g_pooled[g * DIM + t];
    feat[t] = xv / (1.0f + expf(-xv));
    float bs[7];
    bsplines7(xv, bs);
#pragma unroll
    for (int b = 0; b < 7; b++) feat[DIM + t * 7 + b] = bs[b];
    __syncthreads();

    float accv[NCLS];
#pragma unroll
    for (int o = 0; o < NCLS; o++) accv[o] = 0.0f;
#pragma unroll
    for (int kk = 0; kk < 8; kk++) {
        int k = kk * DIM + t;
        float f = feat[k];
        if (k < DIM) {
#pragma unroll
            for (int o = 0; o < NCLS; o++) accv[o] += f * bw[o * DIM + k];
        } else {
            int j = (k - DIM) / 7, b = (k - DIM) % 7;
#pragma unroll
            for (int o = 0; o < NCLS; o++)
                accv[o] += f * sw[o * DIM * NB + j * NB + b] * sc[o * DIM + j];
        }
    }
    int lane = t & 31, warp = t >> 5;
#pragma unroll
    for (int o = 0; o < NCLS; o++) {
        float v = accv[o];
#pragma unroll
        for (int off = 16; off >= 1; off >>= 1) v += __shfl_xor_sync(0xffffffffu, v, off);
        if (lane == 0) sred[o * 4 + warp] = v;
    }
    __syncthreads();
    if (t == 0) {
        float lg[NCLS];
        float mx = -1e30f;
#pragma unroll
        for (int o = 0; o < NCLS; o++) {
            lg[o] = sred[o * 4] + sred[o * 4 + 1] + sred[o * 4 + 2] + sred[o * 4 + 3];
            mx = fmaxf(mx, lg[o]);
        }
        float se = 0.0f;
#pragma unroll
        for (int o = 0; o < NCLS; o++) se += expf(lg[o] - mx);
        float lse = logf(se) + mx;
#pragma unroll
        for (int o = 0; o < NCLS; o++) out[g * NCLS + o] = lg[o] - lse;
    }
}

// ---------------- launch ----------------
extern "C" void kernel_launch(void* const* d_in, const int* in_sizes, int n_in,
                              void* d_out, int out_size) {
    const float* x        = (const float*)d_in[0];
    const int*   ei       = (const int*)d_in[1];
    const int*   batch    = (const int*)d_in[2];
    const float* base_w   = (const float*)d_in[3];
    const float* spline_w = (const float*)d_in[4];
    const float* scaler   = (const float*)d_in[5];
    const float* att_src  = (const float*)d_in[6];
    const float* att_dst  = (const float*)d_in[7];
    const float* bias     = (const float*)d_in[8];
    const float* ro_bw    = (const float*)d_in[9];
    const float* ro_sw    = (const float*)d_in[10];
    const float* ro_sc    = (const float*)d_in[11];
    float* out = (float*)d_out;

    cudaFuncSetAttribute(fkan_gemm_mma, cudaFuncAttributeMaxDynamicSharedMemorySize, SMEM_BYTES);

    float *hbuf = nullptr, *poolp = nullptr;
    int* degp = nullptr;
    __half* wp = nullptr;
    cudaGetSymbolAddress((void**)&hbuf, g_h);
    cudaGetSymbolAddress((void**)&poolp, g_pooled);
    cudaGetSymbolAddress((void**)&degp, g_deg);
    cudaGetSymbolAddress((void**)&wp, g_W16);

    // side stream + events (created once, on the uncaptured correctness call;
    // reused inside graph capture as a fork/join — no allocation thereafter)
    static cudaStream_t s_side = nullptr;
    static cudaEvent_t ev_fork = nullptr, ev_join = nullptr;
    if (s_side == nullptr) {
        cudaStreamCreateWithFlags(&s_side, cudaStreamNonBlocking);
        cudaEventCreateWithFlags(&ev_fork, cudaEventDisableTiming);
        cudaEventCreateWithFlags(&ev_join, cudaEventDisableTiming);
    }

    const int E_BLOCKS = (ETOT + 255) / 256;

    // ---- fork: CSR build + pooled zero on side stream ----
    cudaEventRecord(ev_fork, 0);
    cudaStreamWaitEvent(s_side, ev_fork, 0);
    cudaMemsetAsync(degp, 0, NNODES * sizeof(int), s_side);
    deg_count_kernel<<<E_BLOCKS, 256, 0, s_side>>>(ei);
    scan1_kernel<<<SCAN_BLOCKS, 1024, 0, s_side>>>();
    scan2_kernel<<<1, 32, 0, s_side>>>();
    scan3_kernel<<<SCAN_BLOCKS, 1024, 0, s_side>>>();
    scatter_kernel<<<E_BLOCKS, 256, 0, s_side>>>(ei);
    cudaMemsetAsync(poolp, 0, (size_t)NGR * DIM * sizeof(float), s_side);
    cudaEventRecord(ev_join, s_side);

    // ---- main stream: pack all layers, layer-0 GEMM (independent of CSR) ----
    pack_w_kernel<<<(NLAYER * KDIM * DIM + 255) / 256, 256>>>(base_w, spline_w, scaler);
    fkan_gemm_mma<<<MTILES, 256, SMEM_BYTES>>>(x, att_src, att_dst, wp);

    // join: edge phase needs the CSR
    cudaStreamWaitEvent(0, ev_join, 0);
    edge_fused_kernel<<<(NNODES * 32 + 255) / 256, 256>>>(bias);

    for (int l = 1; l < NLAYER; l++) {
        fkan_gemm_mma<<<MTILES, 256, SMEM_BYTES>>>(
            hbuf, att_src + (size_t)l * DIM, att_dst + (size_t)l * DIM,
            wp + (size_t)l * KDIM * DIM);
        edge_fused_kernel<<<(NNODES * 32 + 255) / 256, 256>>>(bias + (size_t)l * DIM);
    }
    pool_kernel<<<(NNODES + 511) / 512, DIM>>>(batch);
    readout_kernel<<<NGR, DIM>>>(ro_bw, ro_sw, ro_sc, out);
}

// round 12
// speedup vs baseline: 1.4415x; 1.0105x over previous
#include <cuda_runtime.h>
#include <cuda_fp16.h>
#include <cstdint>

#define NNODES 50000
#define NEDGE  800000
#define ETOT   850000
#define DIM    128
#define NH     4
#define NB     7
#define KDIM   1024
#define NGR    64
#define NCLS   10
#define NLAYER 3

#define MTILES ((NNODES + 127) / 128)   // 391
#define SCAN_BLOCKS ((NNODES + 1023) / 1024)  // 49

// ---------------- device scratch ----------------
__device__ __align__(16) __half g_W16[NLAYER * KDIM * DIM];   // packed fp16 weights [l][n][k]
__device__ __align__(16) float g_h[NNODES * DIM];
__device__ __align__(16) __half g_hl16[NNODES * DIM];         // GEMM output, fp16 (edge gather)
__device__ __align__(16) float g_asrc[NNODES * NH];
__device__ __align__(16) float g_adst[NNODES * NH];
__device__ __align__(16) float g_pooled[NGR * DIM];
// CSR
__device__ int g_deg[NNODES];
__device__ int g_ptr[NNODES + 1];
__device__ int g_cur[NNODES];
__device__ int g_csrc[ETOT];
__device__ int g_bsum[SCAN_BLOCKS];
__device__ int g_boff[SCAN_BLOCKS];

// ---------------- helpers ----------------
__device__ __forceinline__ uint32_t smem_u32(const void* p) {
    uint32_t a;
    asm("{ .reg .u64 t; cvta.to.shared.u64 t, %1; cvt.u32.u64 %0, t; }" : "=r"(a) : "l"(p));
    return a;
}

// 16B-chunk swizzle within a 64B row (4 chunks): conflict-free for stores + ldmatrix
#define SWZ32(c, r) (((c) ^ ((r) >> 1)) & 3)

__device__ __forceinline__ void ldsm4(uint32_t a, uint32_t& r0, uint32_t& r1,
                                      uint32_t& r2, uint32_t& r3) {
    asm volatile("ldmatrix.sync.aligned.m8n8.x4.shared.b16 {%0,%1,%2,%3}, [%4];"
                 : "=r"(r0), "=r"(r1), "=r"(r2), "=r"(r3) : "r"(a));
}

__device__ __forceinline__ void mma16816(float* d, const uint32_t* a, const uint32_t* b) {
    asm volatile("mma.sync.aligned.m16n8k16.row.col.f32.f16.f16.f32 "
                 "{%0,%1,%2,%3}, {%4,%5,%6,%7}, {%8,%9}, {%0,%1,%2,%3};"
                 : "+f"(d[0]), "+f"(d[1]), "+f"(d[2]), "+f"(d[3])
                 : "r"(a[0]), "r"(a[1]), "r"(a[2]), "r"(a[3]), "r"(b[0]), "r"(b[1]));
}

__device__ __forceinline__ float silu_f(float x) { return x / (1.0f + __expf(-x)); }

// Cubic B-splines (Cox-de Boor recursion) — used only in small readout kernel.
__device__ __forceinline__ void bsplines7(float x, float* out) {
    float b0[10];
#pragma unroll
    for (int i = 0; i < 10; i++) {
        float g0 = 0.5f * (float)i - 2.5f;
        b0[i] = (x >= g0 && x < g0 + 0.5f) ? 1.0f : 0.0f;
    }
    float b1[9];
#pragma unroll
    for (int i = 0; i < 9; i++) {
        float gi = 0.5f * (float)i - 2.5f;
        b1[i] = (x - gi) * 2.0f * b0[i] + ((gi + 1.0f) - x) * 2.0f * b0[i + 1];
    }
    float b2[8];
#pragma unroll
    for (int i = 0; i < 8; i++) {
        float gi = 0.5f * (float)i - 2.5f;
        b2[i] = (x - gi) * b1[i] + ((gi + 1.5f) - x) * b1[i + 1];
    }
#pragma unroll
    for (int i = 0; i < 7; i++) {
        float gi = 0.5f * (float)i - 2.5f;
        out[i] = ((x - gi) * b2[i] + ((gi + 2.0f) - x) * b2[i + 1]) * (1.0f / 1.5f);
    }
}

// pack (a,b) to f16x2 hi (low half = a), residual to f16x2 lo
__device__ __forceinline__ uint32_t pack_hilo_f16(float a, float b, uint32_t& lo) {
    uint32_t hp;
    asm("cvt.rn.f16x2.f32 %0, %1, %2;" : "=r"(hp) : "f"(b), "f"(a));
    float ha = __half2float(__ushort_as_half((unsigned short)(hp & 0xFFFFu)));
    float hb = __half2float(__ushort_as_half((unsigned short)(hp >> 16)));
    float la = a - ha, lb = b - hb;
    asm("cvt.rn.f16x2.f32 %0, %1, %2;" : "=r"(lo) : "f"(lb), "f"(la));
    return hp;
}

// ---------------- CSR build ----------------
__global__ void deg_count_kernel(const int* __restrict__ ei) {
    int e = blockIdx.x * blockDim.x + threadIdx.x;
    if (e >= ETOT) return;
    int d = (e < NEDGE) ? __ldg(&ei[NEDGE + e]) : (e - NEDGE);
    atomicAdd(&g_deg[d], 1);
}

__global__ void scan1_kernel() {
    __shared__ int sh[1024];
    int t = threadIdx.x, b = blockIdx.x;
    int i = b * 1024 + t;
    int v = (i < NNODES) ? g_deg[i] : 0;
    sh[t] = v;
    __syncthreads();
#pragma unroll
    for (int off = 1; off < 1024; off <<= 1) {
        int add = (t >= off) ? sh[t - off] : 0;
        __syncthreads();
        sh[t] += add;
        __syncthreads();
    }
    if (i < NNODES) g_ptr[i] = sh[t] - v;
    if (t == 1023) g_bsum[b] = sh[t];
}

__global__ void scan2_kernel() {
    if (threadIdx.x == 0) {
        int run = 0;
        for (int b = 0; b < SCAN_BLOCKS; b++) { g_boff[b] = run; run += g_bsum[b]; }
        g_ptr[NNODES] = run;
    }
}

__global__ void scan3_kernel() {
    int t = threadIdx.x, b = blockIdx.x;
    int i = b * 1024 + t;
    if (i < NNODES) {
        int p = g_ptr[i] + g_boff[b];
        g_ptr[i] = p;
        g_cur[i] = p;
    }
}

__global__ void scatter_kernel(const int* __restrict__ ei) {
    int e = blockIdx.x * blockDim.x + threadIdx.x;
    if (e >= ETOT) return;
    int s, d;
    if (e < NEDGE) { s = __ldg(&ei[e]); d = __ldg(&ei[NEDGE + e]); }
    else           { s = e - NEDGE; d = s; }
    int pos = atomicAdd(&g_cur[d], 1);
    g_csrc[pos] = s;
}

// ---------------- weight pack (all 3 layers, once, fp16) ----------------
__global__ void pack_w_kernel(const float* __restrict__ bw,
                              const float* __restrict__ sw,
                              const float* __restrict__ sc) {
    int idx = blockIdx.x * blockDim.x + threadIdx.x;
    if (idx >= NLAYER * KDIM * DIM) return;
    int l = idx >> 17;
    int rem = idx & (KDIM * DIM - 1);
    int n = rem >> 10, k = rem & 1023;
    int j = k >> 3, f = k & 7;
    const float* bwl = bw + (size_t)l * DIM * DIM;
    const float* swl = sw + (size_t)l * DIM * DIM * NB;
    const float* scl = sc + (size_t)l * DIM * DIM;
    float v;
    if (f == 0) v = bwl[n * DIM + j];
    else        v = swl[(n * DIM + j) * NB + (f - 1)] * scl[n * DIM + j];
    g_W16[idx] = __float2half_rn(v);
}

// ---------------- fused KAN-GEMM: pipelined double-buffered fp16 mma (2-product A-split) ----
// Buffer layout (per 24KB buffer): Ah[0,8K) Al[8K,16K) Bh[16K,24K)
// Tiles: 128 rows x 32 k (64B/row, 4 swizzled 16B chunks).
#define SMEM_BYTES 49152

__device__ __forceinline__ void build_chunk(const float* __restrict__ in,
                                            const __half* __restrict__ W16,
                                            char* buf, int m0, int tid, int cc, bool rvalid) {
    char* Ah = buf;
    char* Al = buf + 8192;
    char* Bh = buf + 16384;

    // B weights: LDG first (latency hidden behind feature math)
    int n = tid >> 1, half = tid & 1;
    const uint4* wh = (const uint4*)(W16 + (size_t)n * KDIM + cc * 32 + half * 16);
    uint4 bh0 = wh[0], bh1 = wh[1];

    // A features: 2 evals per thread (row, cols jp*2 + {0,1}), fp16 hi/lo
    int row = tid & 127, jp = tid >> 7;
    float2 xv2 = rvalid ? *(const float2*)(in + (size_t)(m0 + row) * DIM + cc * 4 + jp * 2)
                        : make_float2(0.f, 0.f);
#pragma unroll
    for (int q = 0; q < 2; q++) {
        float xv = q ? xv2.y : xv2.x;
        float fv[8];
        fv[0] = silu_f(xv);
        bsplines7(xv, fv + 1);
        uint4 uh, ul;
        uh.x = pack_hilo_f16(fv[0], fv[1], ul.x);
        uh.y = pack_hilo_f16(fv[2], fv[3], ul.y);
        uh.z = pack_hilo_f16(fv[4], fv[5], ul.z);
        uh.w = pack_hilo_f16(fv[6], fv[7], ul.w);
        int c = jp * 2 + q;
        uint32_t off = row * 64 + (SWZ32(c, row) << 4);
        *(uint4*)(Ah + off) = uh;
        *(uint4*)(Al + off) = ul;
    }
#pragma unroll
    for (int q = 0; q < 2; q++) {
        int c = half * 2 + q;
        uint32_t off = n * 64 + (SWZ32(c, n) << 4);
        *(uint4*)(Bh + off) = q ? bh1 : bh0;
    }
}

__global__ void __launch_bounds__(256, 2) fkan_gemm_mma(const float* __restrict__ in,
                                                        const float* __restrict__ attS,
                                                        const float* __restrict__ attD,
                                                        const __half* __restrict__ W16) {
    extern __shared__ char dsm[];
    int tid = threadIdx.x;
    int wid = tid >> 5, lane = tid & 31;
    int m0 = blockIdx.x * 128;
    int warpM = wid & 3, warpN = wid >> 2;
    uint32_t ubase = smem_u32(dsm);

    bool rvalid = (m0 + (tid & 127)) < NNODES;
    int tg = lane >> 3, tr = lane & 7;

    float acc[2][8][4];
#pragma unroll
    for (int f = 0; f < 2; f++)
#pragma unroll
        for (int j = 0; j < 8; j++)
#pragma unroll
            for (int q = 0; q < 4; q++) acc[f][j][q] = 0.0f;

    // prologue: build chunk 0 into buffer 0
    build_chunk(in, W16, dsm, m0, tid, 0, rvalid);
    __syncthreads();

    for (int cc = 0; cc < 32; cc++) {
        int p = cc & 1;
        uint32_t uAh = ubase + p * 24576;
        uint32_t uAl = uAh + 8192;
        uint32_t uBh = uAh + 16384;

        // ---- mma for chunk cc (tensor pipe) ----
#pragma unroll
        for (int ks = 0; ks < 2; ks++) {
            uint32_t ah[2][4], al[2][4];
#pragma unroll
            for (int f = 0; f < 2; f++) {
                int arow = warpM * 32 + f * 16 + (tg & 1) * 8 + tr;
                int ac = ks * 2 + (tg >> 1);
                uint32_t aoff = arow * 64 + (SWZ32(ac, arow) << 4);
                ldsm4(uAh + aoff, ah[f][0], ah[f][1], ah[f][2], ah[f][3]);
                ldsm4(uAl + aoff, al[f][0], al[f][1], al[f][2], al[f][3]);
            }
#pragma unroll
            for (int gh = 0; gh < 2; gh++) {
                uint32_t bh[2][4];
#pragma unroll
                for (int gg = 0; gg < 2; gg++) {
                    int g = gh * 2 + gg;
                    int brow = warpN * 64 + g * 16 + (tg >> 1) * 8 + tr;
                    int bc = ks * 2 + (tg & 1);
                    uint32_t boff = brow * 64 + (SWZ32(bc, brow) << 4);
                    ldsm4(uBh + boff, bh[gg][0], bh[gg][1], bh[gg][2], bh[gg][3]);
                }
#pragma unroll
                for (int f = 0; f < 2; f++)
#pragma unroll
                    for (int gg = 0; gg < 2; gg++) {
                        int g = gh * 2 + gg;
                        mma16816(acc[f][2 * g],     ah[f], &bh[gg][0]);
                        mma16816(acc[f][2 * g],     al[f], &bh[gg][0]);
                        mma16816(acc[f][2 * g + 1], ah[f], &bh[gg][2]);
                        mma16816(acc[f][2 * g + 1], al[f], &bh[gg][2]);
                    }
            }
        }

        // ---- build chunk cc+1 into the other buffer (fma pipe, overlaps tensor) ----
        if (cc < 31)
            build_chunk(in, W16, dsm + (p ^ 1) * 24576, m0, tid, cc + 1, rvalid);
        __syncthreads();
    }

    // ---- epilogue: store h (fp16) + fused attention dots (fp32 regs) ----
    int qd = lane >> 2, ql = lane & 3;
#pragma unroll
    for (int f = 0; f < 2; f++)
#pragma unroll
        for (int hh = 0; hh < 2; hh++) {
            int row = m0 + warpM * 32 + f * 16 + hh * 8 + qd;
            bool ok = row < NNODES;
            float ps0 = 0.f, pd0 = 0.f, ps1 = 0.f, pd1 = 0.f;
#pragma unroll
            for (int j = 0; j < 8; j++) {
                int col = warpN * 64 + j * 8 + ql * 2;
                float v0 = acc[f][j][hh * 2 + 0];
                float v1 = acc[f][j][hh * 2 + 1];
                if (ok) {
                    __half2 hv = __floats2half2_rn(v0, v1);
                    *(__half2*)&g_hl16[(size_t)row * DIM + col] = hv;
                }
                float s0 = __ldg(&attS[col]), s1 = __ldg(&attS[col + 1]);
                float d0 = __ldg(&attD[col]), d1 = __ldg(&attD[col + 1]);
                float ps = v0 * s0 + v1 * s1;
                float pd = v0 * d0 + v1 * d1;
                if (j < 4) { ps0 += ps; pd0 += pd; } else { ps1 += ps; pd1 += pd; }
            }
#pragma unroll
            for (int o = 1; o <= 2; o <<= 1) {
                ps0 += __shfl_xor_sync(0xffffffffu, ps0, o);
                pd0 += __shfl_xor_sync(0xffffffffu, pd0, o);
                ps1 += __shfl_xor_sync(0xffffffffu, ps1, o);
                pd1 += __shfl_xor_sync(0xffffffffu, pd1, o);
            }
            if (ql == 0 && ok) {
                int hbase = warpN * 2;
                g_asrc[row * 4 + hbase]     = ps0;
                g_asrc[row * 4 + hbase + 1] = ps1;
                g_adst[row * 4 + hbase]     = pd0;
                g_adst[row * 4 + hbase + 1] = pd1;
            }
        }
}

// ---------------- fused pull-mode edge phase (fp16 h gather) ----------------
__global__ void __launch_bounds__(256) edge_fused_kernel(const float* __restrict__ bias) {
    int gid = blockIdx.x * blockDim.x + threadIdx.x;
    int n = gid >> 5, lane = gid & 31;
    if (n >= NNODES) return;
    int start = __ldg(&g_ptr[n]);
    int end   = __ldg(&g_ptr[n + 1]);
    int hh = lane >> 3;
    float bd = g_adst[n * 4 + hh];

    float4 acc = make_float4(0.f, 0.f, 0.f, 0.f);
    float sumex = 0.0f;

    for (int j0 = start; j0 < end; j0 += 32) {
        int m = min(32, end - j0);
        int s_pref = (j0 + lane < end) ? __ldg(&g_csrc[j0 + lane]) : 0;
#pragma unroll 4
        for (int i = 0; i < m; i++) {
            int s = __shfl_sync(0xffffffffu, s_pref, i);
            float a = __ldg(&g_asrc[s * 4 + hh]);
            float e = a + bd;
            e = (e > 0.f) ? e : 0.2f * e;
            float ex = __expf(e);
            sumex += ex;
            uint2 hv = *(const uint2*)&g_hl16[(size_t)s * DIM + lane * 4];
            float2 p0 = __half22float2(*(const __half2*)&hv.x);
            float2 p1 = __half22float2(*(const __half2*)&hv.y);
            acc.x = fmaf(ex, p0.x, acc.x);
            acc.y = fmaf(ex, p0.y, acc.y);
            acc.z = fmaf(ex, p1.x, acc.z);
            acc.w = fmaf(ex, p1.y, acc.w);
        }
    }
    float inv = 1.0f / (sumex + 1e-16f);
    float4 b4 = *(const float4*)&bias[lane * 4];
    float4 o;
    o.x = silu_f(acc.x * inv + b4.x);
    o.y = silu_f(acc.y * inv + b4.y);
    o.z = silu_f(acc.z * inv + b4.z);
    o.w = silu_f(acc.w * inv + b4.w);
    *(float4*)&g_h[(size_t)n * DIM + lane * 4] = o;
}

// ---------------- pooling + readout ----------------
__global__ void pool_kernel(const int* __restrict__ batch) {
    int d0 = threadIdx.x;
    int r0 = blockIdx.x * 512;
    if (r0 >= NNODES) return;
    int rend = min(r0 + 512, NNODES);
    int cur = __ldg(&batch[r0]);
    float sum = 0.0f;
    for (int n = r0; n < rend; n++) {
        int g = __ldg(&batch[n]);
        if (g != cur) {
            atomicAdd(&g_pooled[cur * DIM + d0], sum);
            sum = 0.0f;
            cur = g;
        }
        sum += g_h[(size_t)n * DIM + d0];
    }
    atomicAdd(&g_pooled[cur * DIM + d0], sum);
}

__global__ void readout_kernel(const float* __restrict__ bw,
                               const float* __restrict__ sw,
                               const float* __restrict__ sc,
                               float* __restrict__ out) {
    __shared__ float feat[KDIM];
    __shared__ float sred[NCLS * 4];
    int g = blockIdx.x, t = threadIdx.x;
    float xv = g_pooled[g * DIM + t];
    feat[t] = xv / (1.0f + expf(-xv));
    float bs[7];
    bsplines7(xv, bs);
#pragma unroll
    for (int b = 0; b < 7; b++) feat[DIM + t * 7 + b] = bs[b];
    __syncthreads();

    float accv[NCLS];
#pragma unroll
    for (int o = 0; o < NCLS; o++) accv[o] = 0.0f;
#pragma unroll
    for (int kk = 0; kk < 8; kk++) {
        int k = kk * DIM + t;
        float f = feat[k];
        if (k < DIM) {
#pragma unroll
            for (int o = 0; o < NCLS; o++) accv[o] += f * bw[o * DIM + k];
        } else {
            int j = (k - DIM) / 7, b = (k - DIM) % 7;
#pragma unroll
            for (int o = 0; o < NCLS; o++)
                accv[o] += f * sw[o * DIM * NB + j * NB + b] * sc[o * DIM + j];
        }
    }
    int lane = t & 31, warp = t >> 5;
#pragma unroll
    for (int o = 0; o < NCLS; o++) {
        float v = accv[o];
#pragma unroll
        for (int off = 16; off >= 1; off >>= 1) v += __shfl_xor_sync(0xffffffffu, v, off);
        if (lane == 0) sred[o * 4 + warp] = v;
    }
    __syncthreads();
    if (t == 0) {
        float lg[NCLS];
        float mx = -1e30f;
#pragma unroll
        for (int o = 0; o < NCLS; o++) {
            lg[o] = sred[o * 4] + sred[o * 4 + 1] + sred[o * 4 + 2] + sred[o * 4 + 3];
            mx = fmaxf(mx, lg[o]);
        }
        float se = 0.0f;
#pragma unroll
        for (int o = 0; o < NCLS; o++) se += expf(lg[o] - mx);
        float lse = logf(se) + mx;
#pragma unroll
        for (int o = 0; o < NCLS; o++) out[g * NCLS + o] = lg[o] - lse;
    }
}

// ---------------- launch ----------------
extern "C" void kernel_launch(void* const* d_in, const int* in_sizes, int n_in,
                              void* d_out, int out_size) {
    const float* x        = (const float*)d_in[0];
    const int*   ei       = (const int*)d_in[1];
    const int*   batch    = (const int*)d_in[2];
    const float* base_w   = (const float*)d_in[3];
    const float* spline_w = (const float*)d_in[4];
    const float* scaler   = (const float*)d_in[5];
    const float* att_src  = (const float*)d_in[6];
    const float* att_dst  = (const float*)d_in[7];
    const float* bias     = (const float*)d_in[8];
    const float* ro_bw    = (const float*)d_in[9];
    const float* ro_sw    = (const float*)d_in[10];
    const float* ro_sc    = (const float*)d_in[11];
    float* out = (float*)d_out;

    cudaFuncSetAttribute(fkan_gemm_mma, cudaFuncAttributeMaxDynamicSharedMemorySize, SMEM_BYTES);

    float *hbuf = nullptr, *poolp = nullptr;
    int* degp = nullptr;
    __half* wp = nullptr;
    cudaGetSymbolAddress((void**)&hbuf, g_h);
    cudaGetSymbolAddress((void**)&poolp, g_pooled);
    cudaGetSymbolAddress((void**)&degp, g_deg);
    cudaGetSymbolAddress((void**)&wp, g_W16);

    // side stream + events (created once, on the uncaptured correctness call;
    // reused inside graph capture as a fork/join — no allocation thereafter)
    static cudaStream_t s_side = nullptr;
    static cudaEvent_t ev_fork = nullptr, ev_join = nullptr;
    if (s_side == nullptr) {
        cudaStreamCreateWithFlags(&s_side, cudaStreamNonBlocking);
        cudaEventCreateWithFlags(&ev_fork, cudaEventDisableTiming);
        cudaEventCreateWithFlags(&ev_join, cudaEventDisableTiming);
    }

    const int E_BLOCKS = (ETOT + 255) / 256;

    // ---- fork: CSR build + pooled zero on side stream ----
    cudaEventRecord(ev_fork, 0);
    cudaStreamWaitEvent(s_side, ev_fork, 0);
    cudaMemsetAsync(degp, 0, NNODES * sizeof(int), s_side);
    deg_count_kernel<<<E_BLOCKS, 256, 0, s_side>>>(ei);
    scan1_kernel<<<SCAN_BLOCKS, 1024, 0, s_side>>>();
    scan2_kernel<<<1, 32, 0, s_side>>>();
    scan3_kernel<<<SCAN_BLOCKS, 1024, 0, s_side>>>();
    scatter_kernel<<<E_BLOCKS, 256, 0, s_side>>>(ei);
    cudaMemsetAsync(poolp, 0, (size_t)NGR * DIM * sizeof(float), s_side);
    cudaEventRecord(ev_join, s_side);

    // ---- main stream: pack all layers, layer-0 GEMM (independent of CSR) ----
    pack_w_kernel<<<(NLAYER * KDIM * DIM + 255) / 256, 256>>>(base_w, spline_w, scaler);
    fkan_gemm_mma<<<MTILES, 256, SMEM_BYTES>>>(x, att_src, att_dst, wp);

    // join: edge phase needs the CSR
    cudaStreamWaitEvent(0, ev_join, 0);
    edge_fused_kernel<<<(NNODES * 32 + 255) / 256, 256>>>(bias);

    for (int l = 1; l < NLAYER; l++) {
        fkan_gemm_mma<<<MTILES, 256, SMEM_BYTES>>>(
            hbuf, att_src + (size_t)l * DIM, att_dst + (size_t)l * DIM,
            wp + (size_t)l * KDIM * DIM);
        edge_fused_kernel<<<(NNODES * 32 + 255) / 256, 256>>>(bias + (size_t)l * DIM);
    }
    pool_kernel<<<(NNODES + 511) / 512, DIM>>>(batch);
    readout_kernel<<<NGR, DIM>>>(ro_bw, ro_sw, ro_sc, out);
}

// round 13
// speedup vs baseline: 1.6214x; 1.1248x over previous
#include <cuda_runtime.h>
#include <cuda_fp16.h>
#include <cstdint>

#define NNODES 50000
#define NEDGE  800000
#define ETOT   850000
#define DIM    128
#define NH     4
#define NB     7
#define KDIM   1024
#define NGR    64
#define NCLS   10
#define NLAYER 3

#define MTILES ((NNODES + 127) / 128)   // 391
#define SCAN_BLOCKS ((NNODES + 1023) / 1024)  // 49

// ---------------- device scratch ----------------
__device__ __align__(16) __half g_W16[NLAYER * KDIM * DIM];   // packed fp16 weights [l][n][k]
__device__ __align__(16) float g_h[NNODES * DIM];
__device__ __align__(16) __half g_hl16[NNODES * DIM];         // GEMM output, fp16 (edge gather)
__device__ __align__(16) float g_asrc[NNODES * NH];
__device__ __align__(16) float g_adst[NNODES * NH];
__device__ __align__(16) float g_pooled[NGR * DIM];
// CSR
__device__ int g_deg[NNODES];
__device__ int g_ptr[NNODES + 1];
__device__ int g_cur[NNODES];
__device__ int g_csrc[ETOT];
__device__ int g_bsum[SCAN_BLOCKS];
__device__ int g_boff[SCAN_BLOCKS];

// ---------------- helpers ----------------
__device__ __forceinline__ uint32_t smem_u32(const void* p) {
    uint32_t a;
    asm("{ .reg .u64 t; cvta.to.shared.u64 t, %1; cvt.u32.u64 %0, t; }" : "=r"(a) : "l"(p));
    return a;
}

// 16B-chunk swizzle within a 64B row (4 chunks): conflict-free for stores + ldmatrix
#define SWZ32(c, r) (((c) ^ ((r) >> 1)) & 3)

__device__ __forceinline__ void ldsm4(uint32_t a, uint32_t& r0, uint32_t& r1,
                                      uint32_t& r2, uint32_t& r3) {
    asm volatile("ldmatrix.sync.aligned.m8n8.x4.shared.b16 {%0,%1,%2,%3}, [%4];"
                 : "=r"(r0), "=r"(r1), "=r"(r2), "=r"(r3) : "r"(a));
}

__device__ __forceinline__ void mma16816(float* d, const uint32_t* a, const uint32_t* b) {
    asm volatile("mma.sync.aligned.m16n8k16.row.col.f32.f16.f16.f32 "
                 "{%0,%1,%2,%3}, {%4,%5,%6,%7}, {%8,%9}, {%0,%1,%2,%3};"
                 : "+f"(d[0]), "+f"(d[1]), "+f"(d[2]), "+f"(d[3])
                 : "r"(a[0]), "r"(a[1]), "r"(a[2]), "r"(a[3]), "r"(b[0]), "r"(b[1]));
}

__device__ __forceinline__ float silu_f(float x) { return x / (1.0f + __expf(-x)); }

// Cubic B-splines (Cox-de Boor recursion)
__device__ __forceinline__ void bsplines7(float x, float* out) {
    float b0[10];
#pragma unroll
    for (int i = 0; i < 10; i++) {
        float g0 = 0.5f * (float)i - 2.5f;
        b0[i] = (x >= g0 && x < g0 + 0.5f) ? 1.0f : 0.0f;
    }
    float b1[9];
#pragma unroll
    for (int i = 0; i < 9; i++) {
        float gi = 0.5f * (float)i - 2.5f;
        b1[i] = (x - gi) * 2.0f * b0[i] + ((gi + 1.0f) - x) * 2.0f * b0[i + 1];
    }
    float b2[8];
#pragma unroll
    for (int i = 0; i < 8; i++) {
        float gi = 0.5f * (float)i - 2.5f;
        b2[i] = (x - gi) * b1[i] + ((gi + 1.5f) - x) * b1[i + 1];
    }
#pragma unroll
    for (int i = 0; i < 7; i++) {
        float gi = 0.5f * (float)i - 2.5f;
        out[i] = ((x - gi) * b2[i] + ((gi + 2.0f) - x) * b2[i + 1]) * (1.0f / 1.5f);
    }
}

__device__ __forceinline__ uint32_t pack_f16x2(float a, float b) {
    uint32_t r;
    asm("cvt.rn.f16x2.f32 %0, %1, %2;" : "=r"(r) : "f"(b), "f"(a));
    return r;
}

// ---------------- CSR build ----------------
__global__ void deg_count_kernel(const int* __restrict__ ei) {
    int e = blockIdx.x * blockDim.x + threadIdx.x;
    if (e >= ETOT) return;
    int d = (e < NEDGE) ? __ldg(&ei[NEDGE + e]) : (e - NEDGE);
    atomicAdd(&g_deg[d], 1);
}

__global__ void scan1_kernel() {
    __shared__ int sh[1024];
    int t = threadIdx.x, b = blockIdx.x;
    int i = b * 1024 + t;
    int v = (i < NNODES) ? g_deg[i] : 0;
    sh[t] = v;
    __syncthreads();
#pragma unroll
    for (int off = 1; off < 1024; off <<= 1) {
        int add = (t >= off) ? sh[t - off] : 0;
        __syncthreads();
        sh[t] += add;
        __syncthreads();
    }
    if (i < NNODES) g_ptr[i] = sh[t] - v;
    if (t == 1023) g_bsum[b] = sh[t];
}

__global__ void scan2_kernel() {
    if (threadIdx.x == 0) {
        int run = 0;
        for (int b = 0; b < SCAN_BLOCKS; b++) { g_boff[b] = run; run += g_bsum[b]; }
        g_ptr[NNODES] = run;
    }
}

__global__ void scan3_kernel() {
    int t = threadIdx.x, b = blockIdx.x;
    int i = b * 1024 + t;
    if (i < NNODES) {
        int p = g_ptr[i] + g_boff[b];
        g_ptr[i] = p;
        g_cur[i] = p;
    }
}

__global__ void scatter_kernel(const int* __restrict__ ei) {
    int e = blockIdx.x * blockDim.x + threadIdx.x;
    if (e >= ETOT) return;
    int s, d;
    if (e < NEDGE) { s = __ldg(&ei[e]); d = __ldg(&ei[NEDGE + e]); }
    else           { s = e - NEDGE; d = s; }
    int pos = atomicAdd(&g_cur[d], 1);
    g_csrc[pos] = s;
}

// ---------------- weight pack (all 3 layers, once, fp16) ----------------
__global__ void pack_w_kernel(const float* __restrict__ bw,
                              const float* __restrict__ sw,
                              const float* __restrict__ sc) {
    int idx = blockIdx.x * blockDim.x + threadIdx.x;
    if (idx >= NLAYER * KDIM * DIM) return;
    int l = idx >> 17;
    int rem = idx & (KDIM * DIM - 1);
    int n = rem >> 10, k = rem & 1023;
    int j = k >> 3, f = k & 7;
    const float* bwl = bw + (size_t)l * DIM * DIM;
    const float* swl = sw + (size_t)l * DIM * DIM * NB;
    const float* scl = sc + (size_t)l * DIM * DIM;
    float v;
    if (f == 0) v = bwl[n * DIM + j];
    else        v = swl[(n * DIM + j) * NB + (f - 1)] * scl[n * DIM + j];
    g_W16[idx] = __float2half_rn(v);
}

// ---------------- fused KAN-GEMM: pipelined double-buffered fp16 mma (single product) ----
// Buffer layout (per 16KB buffer): A[0,8K) B[8K,16K)
// Tiles: 128 rows x 32 k (64B/row, 4 swizzled 16B chunks).
#define SMEM_BYTES 32768

__device__ __forceinline__ void build_chunk(const float* __restrict__ in,
                                            const __half* __restrict__ W16,
                                            char* buf, int m0, int tid, int cc, bool rvalid) {
    char* Ab = buf;
    char* Bb = buf + 8192;

    // B weights: LDG first (latency hidden behind feature math)
    int n = tid >> 1, half = tid & 1;
    const uint4* wh = (const uint4*)(W16 + (size_t)n * KDIM + cc * 32 + half * 16);
    uint4 bh0 = wh[0], bh1 = wh[1];

    // A features: 2 evals per thread (row, cols jp*2 + {0,1}), fp16
    int row = tid & 127, jp = tid >> 7;
    float2 xv2 = rvalid ? *(const float2*)(in + (size_t)(m0 + row) * DIM + cc * 4 + jp * 2)
                        : make_float2(0.f, 0.f);
#pragma unroll
    for (int q = 0; q < 2; q++) {
        float xv = q ? xv2.y : xv2.x;
        float fv[8];
        fv[0] = silu_f(xv);
        bsplines7(xv, fv + 1);
        uint4 uh;
        uh.x = pack_f16x2(fv[0], fv[1]);
        uh.y = pack_f16x2(fv[2], fv[3]);
        uh.z = pack_f16x2(fv[4], fv[5]);
        uh.w = pack_f16x2(fv[6], fv[7]);
        int c = jp * 2 + q;
        uint32_t off = row * 64 + (SWZ32(c, row) << 4);
        *(uint4*)(Ab + off) = uh;
    }
#pragma unroll
    for (int q = 0; q < 2; q++) {
        int c = half * 2 + q;
        uint32_t off = n * 64 + (SWZ32(c, n) << 4);
        *(uint4*)(Bb + off) = q ? bh1 : bh0;
    }
}

__global__ void __launch_bounds__(256, 2) fkan_gemm_mma(const float* __restrict__ in,
                                                        const float* __restrict__ attS,
                                                        const float* __restrict__ attD,
                                                        const __half* __restrict__ W16) {
    extern __shared__ char dsm[];
    int tid = threadIdx.x;
    int wid = tid >> 5, lane = tid & 31;
    int m0 = blockIdx.x * 128;
    int warpM = wid & 3, warpN = wid >> 2;
    uint32_t ubase = smem_u32(dsm);

    bool rvalid = (m0 + (tid & 127)) < NNODES;
    int tg = lane >> 3, tr = lane & 7;

    float acc[2][8][4];
#pragma unroll
    for (int f = 0; f < 2; f++)
#pragma unroll
        for (int j = 0; j < 8; j++)
#pragma unroll
            for (int q = 0; q < 4; q++) acc[f][j][q] = 0.0f;

    // prologue: build chunk 0 into buffer 0
    build_chunk(in, W16, dsm, m0, tid, 0, rvalid);
    __syncthreads();

    for (int cc = 0; cc < 32; cc++) {
        int p = cc & 1;
        uint32_t uA = ubase + p * 16384;
        uint32_t uB = uA + 8192;

        // ---- mma for chunk cc (tensor pipe) ----
#pragma unroll
        for (int ks = 0; ks < 2; ks++) {
            uint32_t ah[2][4];
#pragma unroll
            for (int f = 0; f < 2; f++) {
                int arow = warpM * 32 + f * 16 + (tg & 1) * 8 + tr;
                int ac = ks * 2 + (tg >> 1);
                uint32_t aoff = arow * 64 + (SWZ32(ac, arow) << 4);
                ldsm4(uA + aoff, ah[f][0], ah[f][1], ah[f][2], ah[f][3]);
            }
#pragma unroll
            for (int gh = 0; gh < 2; gh++) {
                uint32_t bh[2][4];
#pragma unroll
                for (int gg = 0; gg < 2; gg++) {
                    int g = gh * 2 + gg;
                    int brow = warpN * 64 + g * 16 + (tg >> 1) * 8 + tr;
                    int bc = ks * 2 + (tg & 1);
                    uint32_t boff = brow * 64 + (SWZ32(bc, brow) << 4);
                    ldsm4(uB + boff, bh[gg][0], bh[gg][1], bh[gg][2], bh[gg][3]);
                }
#pragma unroll
                for (int f = 0; f < 2; f++)
#pragma unroll
                    for (int gg = 0; gg < 2; gg++) {
                        int g = gh * 2 + gg;
                        mma16816(acc[f][2 * g],     ah[f], &bh[gg][0]);
                        mma16816(acc[f][2 * g + 1], ah[f], &bh[gg][2]);
                    }
            }
        }

        // ---- build chunk cc+1 into the other buffer (fma pipe, overlaps tensor) ----
        if (cc < 31)
            build_chunk(in, W16, dsm + (p ^ 1) * 16384, m0, tid, cc + 1, rvalid);
        __syncthreads();
    }

    // ---- epilogue: store h (fp16) + fused attention dots (fp32 regs) ----
    int qd = lane >> 2, ql = lane & 3;
#pragma unroll
    for (int f = 0; f < 2; f++)
#pragma unroll
        for (int hh = 0; hh < 2; hh++) {
            int row = m0 + warpM * 32 + f * 16 + hh * 8 + qd;
            bool ok = row < NNODES;
            float ps0 = 0.f, pd0 = 0.f, ps1 = 0.f, pd1 = 0.f;
#pragma unroll
            for (int j = 0; j < 8; j++) {
                int col = warpN * 64 + j * 8 + ql * 2;
                float v0 = acc[f][j][hh * 2 + 0];
                float v1 = acc[f][j][hh * 2 + 1];
                if (ok) {
                    __half2 hv = __floats2half2_rn(v0, v1);
                    *(__half2*)&g_hl16[(size_t)row * DIM + col] = hv;
                }
                float s0 = __ldg(&attS[col]), s1 = __ldg(&attS[col + 1]);
                float d0 = __ldg(&attD[col]), d1 = __ldg(&attD[col + 1]);
                float ps = v0 * s0 + v1 * s1;
                float pd = v0 * d0 + v1 * d1;
                if (j < 4) { ps0 += ps; pd0 += pd; } else { ps1 += ps; pd1 += pd; }
            }
#pragma unroll
            for (int o = 1; o <= 2; o <<= 1) {
                ps0 += __shfl_xor_sync(0xffffffffu, ps0, o);
                pd0 += __shfl_xor_sync(0xffffffffu, pd0, o);
                ps1 += __shfl_xor_sync(0xffffffffu, ps1, o);
                pd1 += __shfl_xor_sync(0xffffffffu, pd1, o);
            }
            if (ql == 0 && ok) {
                int hbase = warpN * 2;
                g_asrc[row * 4 + hbase]     = ps0;
                g_asrc[row * 4 + hbase + 1] = ps1;
                g_adst[row * 4 + hbase]     = pd0;
                g_adst[row * 4 + hbase + 1] = pd1;
            }
        }
}

// ---------------- fused pull-mode edge phase (fp16 h gather) ----------------
__global__ void __launch_bounds__(256) edge_fused_kernel(const float* __restrict__ bias) {
    int gid = blockIdx.x * blockDim.x + threadIdx.x;
    int n = gid >> 5, lane = gid & 31;
    if (n >= NNODES) return;
    int start = __ldg(&g_ptr[n]);
    int end   = __ldg(&g_ptr[n + 1]);
    int hh = lane >> 3;
    float bd = g_adst[n * 4 + hh];

    float4 acc = make_float4(0.f, 0.f, 0.f, 0.f);
    float sumex = 0.0f;

    for (int j0 = start; j0 < end; j0 += 32) {
        int m = min(32, end - j0);
        int s_pref = (j0 + lane < end) ? __ldg(&g_csrc[j0 + lane]) : 0;
#pragma unroll 4
        for (int i = 0; i < m; i++) {
            int s = __shfl_sync(0xffffffffu, s_pref, i);
            float a = __ldg(&g_asrc[s * 4 + hh]);
            float e = a + bd;
            e = (e > 0.f) ? e : 0.2f * e;
            float ex = __expf(e);
            sumex += ex;
            uint2 hv = *(const uint2*)&g_hl16[(size_t)s * DIM + lane * 4];
            float2 p0 = __half22float2(*(const __half2*)&hv.x);
            float2 p1 = __half22float2(*(const __half2*)&hv.y);
            acc.x = fmaf(ex, p0.x, acc.x);
            acc.y = fmaf(ex, p0.y, acc.y);
            acc.z = fmaf(ex, p1.x, acc.z);
            acc.w = fmaf(ex, p1.y, acc.w);
        }
    }
    float inv = 1.0f / (sumex + 1e-16f);
    float4 b4 = *(const float4*)&bias[lane * 4];
    float4 o;
    o.x = silu_f(acc.x * inv + b4.x);
    o.y = silu_f(acc.y * inv + b4.y);
    o.z = silu_f(acc.z * inv + b4.z);
    o.w = silu_f(acc.w * inv + b4.w);
    *(float4*)&g_h[(size_t)n * DIM + lane * 4] = o;
}

// ---------------- pooling + readout ----------------
__global__ void pool_kernel(const int* __restrict__ batch) {
    int d0 = threadIdx.x;
    int r0 = blockIdx.x * 512;
    if (r0 >= NNODES) return;
    int rend = min(r0 + 512, NNODES);
    int cur = __ldg(&batch[r0]);
    float sum = 0.0f;
    for (int n = r0; n < rend; n++) {
        int g = __ldg(&batch[n]);
        if (g != cur) {
            atomicAdd(&g_pooled[cur * DIM + d0], sum);
            sum = 0.0f;
            cur = g;
        }
        sum += g_h[(size_t)n * DIM + d0];
    }
    atomicAdd(&g_pooled[cur * DIM + d0], sum);
}

__global__ void readout_kernel(const float* __restrict__ bw,
                               const float* __restrict__ sw,
                               const float* __restrict__ sc,
                               float* __restrict__ out) {
    __shared__ float feat[KDIM];
    __shared__ float sred[NCLS * 4];
    int g = blockIdx.x, t = threadIdx.x;
    float xv = g_pooled[g * DIM + t];
    feat[t] = xv / (1.0f + expf(-xv));
    float bs[7];
    bsplines7(xv, bs);
#pragma unroll
    for (int b = 0; b < 7; b++) feat[DIM + t * 7 + b] = bs[b];
    __syncthreads();

    float accv[NCLS];
#pragma unroll
    for (int o = 0; o < NCLS; o++) accv[o] = 0.0f;
#pragma unroll
    for (int kk = 0; kk < 8; kk++) {
        int k = kk * DIM + t;
        float f = feat[k];
        if (k < DIM) {
#pragma unroll
            for (int o = 0; o < NCLS; o++) accv[o] += f * bw[o * DIM + k];
        } else {
            int j = (k - DIM) / 7, b = (k - DIM) % 7;
#pragma unroll
            for (int o = 0; o < NCLS; o++)
                accv[o] += f * sw[o * DIM * NB + j * NB + b] * sc[o * DIM + j];
        }
    }
    int lane = t & 31, warp = t >> 5;
#pragma unroll
    for (int o = 0; o < NCLS; o++) {
        float v = accv[o];
#pragma unroll
        for (int off = 16; off >= 1; off >>= 1) v += __shfl_xor_sync(0xffffffffu, v, off);
        if (lane == 0) sred[o * 4 + warp] = v;
    }
    __syncthreads();
    if (t == 0) {
        float lg[NCLS];
        float mx = -1e30f;
#pragma unroll
        for (int o = 0; o < NCLS; o++) {
            lg[o] = sred[o * 4] + sred[o * 4 + 1] + sred[o * 4 + 2] + sred[o * 4 + 3];
            mx = fmaxf(mx, lg[o]);
        }
        float se = 0.0f;
#pragma unroll
        for (int o = 0; o < NCLS; o++) se += expf(lg[o] - mx);
        float lse = logf(se) + mx;
#pragma unroll
        for (int o = 0; o < NCLS; o++) out[g * NCLS + o] = lg[o] - lse;
    }
}

// ---------------- launch ----------------
extern "C" void kernel_launch(void* const* d_in, const int* in_sizes, int n_in,
                              void* d_out, int out_size) {
    const float* x        = (const float*)d_in[0];
    const int*   ei       = (const int*)d_in[1];
    const int*   batch    = (const int*)d_in[2];
    const float* base_w   = (const float*)d_in[3];
    const float* spline_w = (const float*)d_in[4];
    const float* scaler   = (const float*)d_in[5];
    const float* att_src  = (const float*)d_in[6];
    const float* att_dst  = (const float*)d_in[7];
    const float* bias     = (const float*)d_in[8];
    const float* ro_bw    = (const float*)d_in[9];
    const float* ro_sw    = (const float*)d_in[10];
    const float* ro_sc    = (const float*)d_in[11];
    float* out = (float*)d_out;

    cudaFuncSetAttribute(fkan_gemm_mma, cudaFuncAttributeMaxDynamicSharedMemorySize, SMEM_BYTES);

    float *hbuf = nullptr, *poolp = nullptr;
    int* degp = nullptr;
    __half* wp = nullptr;
    cudaGetSymbolAddress((void**)&hbuf, g_h);
    cudaGetSymbolAddress((void**)&poolp, g_pooled);
    cudaGetSymbolAddress((void**)&degp, g_deg);
    cudaGetSymbolAddress((void**)&wp, g_W16);

    // side stream + events (created once, on the uncaptured correctness call;
    // reused inside graph capture as a fork/join — no allocation thereafter)
    static cudaStream_t s_side = nullptr;
    static cudaEvent_t ev_fork = nullptr, ev_join = nullptr;
    if (s_side == nullptr) {
        cudaStreamCreateWithFlags(&s_side, cudaStreamNonBlocking);
        cudaEventCreateWithFlags(&ev_fork, cudaEventDisableTiming);
        cudaEventCreateWithFlags(&ev_join, cudaEventDisableTiming);
    }

    const int E_BLOCKS = (ETOT + 255) / 256;

    // ---- fork: CSR build + pooled zero on side stream ----
    cudaEventRecord(ev_fork, 0);
    cudaStreamWaitEvent(s_side, ev_fork, 0);
    cudaMemsetAsync(degp, 0, NNODES * sizeof(int), s_side);
    deg_count_kernel<<<E_BLOCKS, 256, 0, s_side>>>(ei);
    scan1_kernel<<<SCAN_BLOCKS, 1024, 0, s_side>>>();
    scan2_kernel<<<1, 32, 0, s_side>>>();
    scan3_kernel<<<SCAN_BLOCKS, 1024, 0, s_side>>>();
    scatter_kernel<<<E_BLOCKS, 256, 0, s_side>>>(ei);
    cudaMemsetAsync(poolp, 0, (size_t)NGR * DIM * sizeof(float), s_side);
    cudaEventRecord(ev_join, s_side);

    // ---- main stream: pack all layers, layer-0 GEMM (independent of CSR) ----
    pack_w_kernel<<<(NLAYER * KDIM * DIM + 255) / 256, 256>>>(base_w, spline_w, scaler);
    fkan_gemm_mma<<<MTILES, 256, SMEM_BYTES>>>(x, att_src, att_dst, wp);

    // join: edge phase needs the CSR
    cudaStreamWaitEvent(0, ev_join, 0);
    edge_fused_kernel<<<(NNODES * 32 + 255) / 256, 256>>>(bias);

    for (int l = 1; l < NLAYER; l++) {
        fkan_gemm_mma<<<MTILES, 256, SMEM_BYTES>>>(
            hbuf, att_src + (size_t)l * DIM, att_dst + (size_t)l * DIM,
            wp + (size_t)l * KDIM * DIM);
        edge_fused_kernel<<<(NNODES * 32 + 255) / 256, 256>>>(bias + (size_t)l * DIM);
    }
    pool_kernel<<<(NNODES + 511) / 512, DIM>>>(batch);
    readout_kernel<<<NGR, DIM>>>(ro_bw, ro_sw, ro_sc, out);
}

// round 14
// speedup vs baseline: 1.6847x; 1.0390x over previous
#include <cuda_runtime.h>
#include <cuda_fp16.h>
#include <cstdint>

#define NNODES 50000
#define NEDGE  800000
#define ETOT   850000
#define DIM    128
#define NH     4
#define NB     7
#define KDIM   1024
#define NGR    64
#define NCLS   10
#define NLAYER 3

#define MTILES ((NNODES + 127) / 128)   // 391
#define SCAN_BLOCKS ((NNODES + 1023) / 1024)  // 49

// ---------------- device scratch ----------------
__device__ __align__(16) __half g_W16[NLAYER * KDIM * DIM];   // packed fp16 weights [l][n][k]
__device__ __align__(16) float g_h[NNODES * DIM];
__device__ __align__(16) __half g_hl16[NNODES * DIM];         // GEMM output, fp16 (edge gather)
__device__ __align__(16) float g_asrc[NNODES * NH];
__device__ __align__(16) float g_adst[NNODES * NH];
__device__ __align__(16) float g_pooled[NGR * DIM];
// CSR
__device__ int g_deg[NNODES];
__device__ int g_ptr[NNODES + 1];
__device__ int g_cur[NNODES];
__device__ int g_csrc[ETOT];
__device__ int g_bsum[SCAN_BLOCKS];
__device__ int g_boff[SCAN_BLOCKS];

// ---------------- helpers ----------------
__device__ __forceinline__ uint32_t smem_u32(const void* p) {
    uint32_t a;
    asm("{ .reg .u64 t; cvta.to.shared.u64 t, %1; cvt.u32.u64 %0, t; }" : "=r"(a) : "l"(p));
    return a;
}

// 16B-chunk swizzle within a 64B row (4 chunks): conflict-free for stores + ldmatrix
#define SWZ32(c, r) (((c) ^ ((r) >> 1)) & 3)

__device__ __forceinline__ void ldsm4(uint32_t a, uint32_t& r0, uint32_t& r1,
                                      uint32_t& r2, uint32_t& r3) {
    asm volatile("ldmatrix.sync.aligned.m8n8.x4.shared.b16 {%0,%1,%2,%3}, [%4];"
                 : "=r"(r0), "=r"(r1), "=r"(r2), "=r"(r3) : "r"(a));
}

__device__ __forceinline__ void mma16816(float* d, const uint32_t* a, const uint32_t* b) {
    asm volatile("mma.sync.aligned.m16n8k16.row.col.f32.f16.f16.f32 "
                 "{%0,%1,%2,%3}, {%4,%5,%6,%7}, {%8,%9}, {%0,%1,%2,%3};"
                 : "+f"(d[0]), "+f"(d[1]), "+f"(d[2]), "+f"(d[3])
                 : "r"(a[0]), "r"(a[1]), "r"(a[2]), "r"(a[3]), "r"(b[0]), "r"(b[1]));
}

__device__ __forceinline__ float silu_f(float x) { return x / (1.0f + __expf(-x)); }

// Cubic B-splines (Cox-de Boor recursion) — used only in small readout kernel.
__device__ __forceinline__ void bsplines7(float x, float* out) {
    float b0[10];
#pragma unroll
    for (int i = 0; i < 10; i++) {
        float g0 = 0.5f * (float)i - 2.5f;
        b0[i] = (x >= g0 && x < g0 + 0.5f) ? 1.0f : 0.0f;
    }
    float b1[9];
#pragma unroll
    for (int i = 0; i < 9; i++) {
        float gi = 0.5f * (float)i - 2.5f;
        b1[i] = (x - gi) * 2.0f * b0[i] + ((gi + 1.0f) - x) * 2.0f * b0[i + 1];
    }
    float b2[8];
#pragma unroll
    for (int i = 0; i < 8; i++) {
        float gi = 0.5f * (float)i - 2.5f;
        b2[i] = (x - gi) * b1[i] + ((gi + 1.5f) - x) * b1[i + 1];
    }
#pragma unroll
    for (int i = 0; i < 7; i++) {
        float gi = 0.5f * (float)i - 2.5f;
        out[i] = ((x - gi) * b2[i] + ((gi + 2.0f) - x) * b2[i + 1]) * (1.0f / 1.5f);
    }
}

__device__ __forceinline__ uint32_t pack_f16x2(float a, float b) {
    uint32_t r;
    asm("cvt.rn.f16x2.f32 %0, %1, %2;" : "=r"(r) : "f"(b), "f"(a));
    return r;
}

// ---------------- CSR build ----------------
__global__ void deg_count_kernel(const int* __restrict__ ei) {
    int e = blockIdx.x * blockDim.x + threadIdx.x;
    if (e >= ETOT) return;
    int d = (e < NEDGE) ? __ldg(&ei[NEDGE + e]) : (e - NEDGE);
    atomicAdd(&g_deg[d], 1);
}

__global__ void scan1_kernel() {
    __shared__ int sh[1024];
    int t = threadIdx.x, b = blockIdx.x;
    int i = b * 1024 + t;
    int v = (i < NNODES) ? g_deg[i] : 0;
    sh[t] = v;
    __syncthreads();
#pragma unroll
    for (int off = 1; off < 1024; off <<= 1) {
        int add = (t >= off) ? sh[t - off] : 0;
        __syncthreads();
        sh[t] += add;
        __syncthreads();
    }
    if (i < NNODES) g_ptr[i] = sh[t] - v;
    if (t == 1023) g_bsum[b] = sh[t];
}

__global__ void scan2_kernel() {
    if (threadIdx.x == 0) {
        int run = 0;
        for (int b = 0; b < SCAN_BLOCKS; b++) { g_boff[b] = run; run += g_bsum[b]; }
        g_ptr[NNODES] = run;
    }
}

__global__ void scan3_kernel() {
    int t = threadIdx.x, b = blockIdx.x;
    int i = b * 1024 + t;
    if (i < NNODES) {
        int p = g_ptr[i] + g_boff[b];
        g_ptr[i] = p;
        g_cur[i] = p;
    }
}

__global__ void scatter_kernel(const int* __restrict__ ei) {
    int e = blockIdx.x * blockDim.x + threadIdx.x;
    if (e >= ETOT) return;
    int s, d;
    if (e < NEDGE) { s = __ldg(&ei[e]); d = __ldg(&ei[NEDGE + e]); }
    else           { s = e - NEDGE; d = s; }
    int pos = atomicAdd(&g_cur[d], 1);
    g_csrc[pos] = s;
}

// ---------------- weight pack (all 3 layers, once, fp16) ----------------
__global__ void pack_w_kernel(const float* __restrict__ bw,
                              const float* __restrict__ sw,
                              const float* __restrict__ sc) {
    int idx = blockIdx.x * blockDim.x + threadIdx.x;
    if (idx >= NLAYER * KDIM * DIM) return;
    int l = idx >> 17;
    int rem = idx & (KDIM * DIM - 1);
    int n = rem >> 10, k = rem & 1023;
    int j = k >> 3, f = k & 7;
    const float* bwl = bw + (size_t)l * DIM * DIM;
    const float* swl = sw + (size_t)l * DIM * DIM * NB;
    const float* scl = sc + (size_t)l * DIM * DIM;
    float v;
    if (f == 0) v = bwl[n * DIM + j];
    else        v = swl[(n * DIM + j) * NB + (f - 1)] * scl[n * DIM + j];
    g_W16[idx] = __float2half_rn(v);
}

// ---------------- fused KAN-GEMM: pipelined double-buffered fp16 mma (single product) ----
// Buffer layout (per 16KB buffer): A[0,8K) B[8K,16K)
// Tiles: 128 rows x 32 k (64B/row, 4 swizzled 16B chunks).
#define SMEM_BYTES 32768

__device__ __forceinline__ void build_chunk(const float* __restrict__ in,
                                            const __half* __restrict__ W16,
                                            char* buf, int m0, int tid, int cc, bool rvalid) {
    char* Ab = buf;
    char* Bb = buf + 8192;

    // B weights: LDG first (latency hidden behind feature math)
    int n = tid >> 1, half = tid & 1;
    const uint4* wh = (const uint4*)(W16 + (size_t)n * KDIM + cc * 32 + half * 16);
    uint4 bh0 = wh[0], bh1 = wh[1];

    // A features: 2 evals per thread. Closed-form cardinal cubic B-spline with
    // direct scatter of the <=4 nonzero bases — no select chain, no packing of zeros.
    int row = tid & 127, jp = tid >> 7;
    float2 xv2 = rvalid ? *(const float2*)(in + (size_t)(m0 + row) * DIM + cc * 4 + jp * 2)
                        : make_float2(0.f, 0.f);
#pragma unroll
    for (int q = 0; q < 2; q++) {
        float xv = q ? xv2.y : xv2.x;
        int cch = jp * 2 + q;
        uint32_t off = row * 64 + (SWZ32(cch, row) << 4);

        // silu (fp16) in slot 0, zero-fill rest of the 16B chunk
        float sv = silu_f(xv);
        uint32_t sp = pack_f16x2(sv, 0.0f);   // low half = silu, high = 0
        *(uint4*)(Ab + off) = make_uint4(sp & 0xFFFFu, 0u, 0u, 0u);

        // spline cell + 4 nonzero weights (closed form)
        float u = fmaf(2.0f, xv, 5.0f);
        float cf = floorf(u);
        float t = u - cf;
        bool inr = (u >= 0.0f) && (u < 10.0f);
        int c = (int)cf;
        float t2 = t * t, t3 = t2 * t, s1 = 1.0f - t;
        const float i6 = 1.0f / 6.0f;
        float w[4];
        w[0] = t3 * i6;                                                    // j == c
        w[1] = fmaf(-3.0f, t3, fmaf(3.0f, t2, fmaf(3.0f, t, 1.0f))) * i6; // j == c-1
        w[2] = fmaf(3.0f, t3, fmaf(-6.0f, t2, 4.0f)) * i6;                // j == c-2
        w[3] = s1 * s1 * s1 * i6;                                         // j == c-3
#pragma unroll
        for (int m = 0; m < 4; m++) {
            int j = c - m;
            if (inr && j >= 0 && j <= 6) {
                __half hw = __float2half_rn(w[m]);
                *(uint16_t*)(Ab + off + 2 * (j + 1)) = __half_as_ushort(hw);
            }
        }
    }
#pragma unroll
    for (int q = 0; q < 2; q++) {
        int c = half * 2 + q;
        uint32_t off = n * 64 + (SWZ32(c, n) << 4);
        *(uint4*)(Bb + off) = q ? bh1 : bh0;
    }
}

__global__ void __launch_bounds__(256, 2) fkan_gemm_mma(const float* __restrict__ in,
                                                        const float* __restrict__ attS,
                                                        const float* __restrict__ attD,
                                                        const __half* __restrict__ W16) {
    extern __shared__ char dsm[];
    int tid = threadIdx.x;
    int wid = tid >> 5, lane = tid & 31;
    int m0 = blockIdx.x * 128;
    int warpM = wid & 3, warpN = wid >> 2;
    uint32_t ubase = smem_u32(dsm);

    bool rvalid = (m0 + (tid & 127)) < NNODES;
    int tg = lane >> 3, tr = lane & 7;

    float acc[2][8][4];
#pragma unroll
    for (int f = 0; f < 2; f++)
#pragma unroll
        for (int j = 0; j < 8; j++)
#pragma unroll
            for (int q = 0; q < 4; q++) acc[f][j][q] = 0.0f;

    // prologue: build chunk 0 into buffer 0
    build_chunk(in, W16, dsm, m0, tid, 0, rvalid);
    __syncthreads();

    for (int cc = 0; cc < 32; cc++) {
        int p = cc & 1;
        uint32_t uA = ubase + p * 16384;
        uint32_t uB = uA + 8192;

        // ---- mma for chunk cc (tensor pipe) ----
#pragma unroll
        for (int ks = 0; ks < 2; ks++) {
            uint32_t ah[2][4];
#pragma unroll
            for (int f = 0; f < 2; f++) {
                int arow = warpM * 32 + f * 16 + (tg & 1) * 8 + tr;
                int ac = ks * 2 + (tg >> 1);
                uint32_t aoff = arow * 64 + (SWZ32(ac, arow) << 4);
                ldsm4(uA + aoff, ah[f][0], ah[f][1], ah[f][2], ah[f][3]);
            }
#pragma unroll
            for (int gh = 0; gh < 2; gh++) {
                uint32_t bh[2][4];
#pragma unroll
                for (int gg = 0; gg < 2; gg++) {
                    int g = gh * 2 + gg;
                    int brow = warpN * 64 + g * 16 + (tg >> 1) * 8 + tr;
                    int bc = ks * 2 + (tg & 1);
                    uint32_t boff = brow * 64 + (SWZ32(bc, brow) << 4);
                    ldsm4(uB + boff, bh[gg][0], bh[gg][1], bh[gg][2], bh[gg][3]);
                }
#pragma unroll
                for (int f = 0; f < 2; f++)
#pragma unroll
                    for (int gg = 0; gg < 2; gg++) {
                        int g = gh * 2 + gg;
                        mma16816(acc[f][2 * g],     ah[f], &bh[gg][0]);
                        mma16816(acc[f][2 * g + 1], ah[f], &bh[gg][2]);
                    }
            }
        }

        // ---- build chunk cc+1 into the other buffer (fma pipe, overlaps tensor) ----
        if (cc < 31)
            build_chunk(in, W16, dsm + (p ^ 1) * 16384, m0, tid, cc + 1, rvalid);
        __syncthreads();
    }

    // ---- epilogue: store h (fp16) + fused attention dots (fp32 regs) ----
    int qd = lane >> 2, ql = lane & 3;
#pragma unroll
    for (int f = 0; f < 2; f++)
#pragma unroll
        for (int hh = 0; hh < 2; hh++) {
            int row = m0 + warpM * 32 + f * 16 + hh * 8 + qd;
            bool ok = row < NNODES;
            float ps0 = 0.f, pd0 = 0.f, ps1 = 0.f, pd1 = 0.f;
#pragma unroll
            for (int j = 0; j < 8; j++) {
                int col = warpN * 64 + j * 8 + ql * 2;
                float v0 = acc[f][j][hh * 2 + 0];
                float v1 = acc[f][j][hh * 2 + 1];
                if (ok) {
                    __half2 hv = __floats2half2_rn(v0, v1);
                    *(__half2*)&g_hl16[(size_t)row * DIM + col] = hv;
                }
                float s0 = __ldg(&attS[col]), s1 = __ldg(&attS[col + 1]);
                float d0 = __ldg(&attD[col]), d1 = __ldg(&attD[col + 1]);
                float ps = v0 * s0 + v1 * s1;
                float pd = v0 * d0 + v1 * d1;
                if (j < 4) { ps0 += ps; pd0 += pd; } else { ps1 += ps; pd1 += pd; }
            }
#pragma unroll
            for (int o = 1; o <= 2; o <<= 1) {
                ps0 += __shfl_xor_sync(0xffffffffu, ps0, o);
                pd0 += __shfl_xor_sync(0xffffffffu, pd0, o);
                ps1 += __shfl_xor_sync(0xffffffffu, ps1, o);
                pd1 += __shfl_xor_sync(0xffffffffu, pd1, o);
            }
            if (ql == 0 && ok) {
                int hbase = warpN * 2;
                g_asrc[row * 4 + hbase]     = ps0;
                g_asrc[row * 4 + hbase + 1] = ps1;
                g_adst[row * 4 + hbase]     = pd0;
                g_adst[row * 4 + hbase + 1] = pd1;
            }
        }
}

// ---------------- fused pull-mode edge phase (fp16 h gather) ----------------
__global__ void __launch_bounds__(256) edge_fused_kernel(const float* __restrict__ bias) {
    int gid = blockIdx.x * blockDim.x + threadIdx.x;
    int n = gid >> 5, lane = gid & 31;
    if (n >= NNODES) return;
    int start = __ldg(&g_ptr[n]);
    int end   = __ldg(&g_ptr[n + 1]);
    int hh = lane >> 3;
    float bd = g_adst[n * 4 + hh];

    float4 acc = make_float4(0.f, 0.f, 0.f, 0.f);
    float sumex = 0.0f;

    for (int j0 = start; j0 < end; j0 += 32) {
        int m = min(32, end - j0);
        int s_pref = (j0 + lane < end) ? __ldg(&g_csrc[j0 + lane]) : 0;
#pragma unroll 4
        for (int i = 0; i < m; i++) {
            int s = __shfl_sync(0xffffffffu, s_pref, i);
            float a = __ldg(&g_asrc[s * 4 + hh]);
            float e = a + bd;
            e = (e > 0.f) ? e : 0.2f * e;
            float ex = __expf(e);
            sumex += ex;
            uint2 hv = *(const uint2*)&g_hl16[(size_t)s * DIM + lane * 4];
            float2 p0 = __half22float2(*(const __half2*)&hv.x);
            float2 p1 = __half22float2(*(const __half2*)&hv.y);
            acc.x = fmaf(ex, p0.x, acc.x);
            acc.y = fmaf(ex, p0.y, acc.y);
            acc.z = fmaf(ex, p1.x, acc.z);
            acc.w = fmaf(ex, p1.y, acc.w);
        }
    }
    float inv = 1.0f / (sumex + 1e-16f);
    float4 b4 = *(const float4*)&bias[lane * 4];
    float4 o;
    o.x = silu_f(acc.x * inv + b4.x);
    o.y = silu_f(acc.y * inv + b4.y);
    o.z = silu_f(acc.z * inv + b4.z);
    o.w = silu_f(acc.w * inv + b4.w);
    *(float4*)&g_h[(size_t)n * DIM + lane * 4] = o;
}

// ---------------- pooling + readout ----------------
__global__ void pool_kernel(const int* __restrict__ batch) {
    int d0 = threadIdx.x;
    int r0 = blockIdx.x * 512;
    if (r0 >= NNODES) return;
    int rend = min(r0 + 512, NNODES);
    int cur = __ldg(&batch[r0]);
    float sum = 0.0f;
    for (int n = r0; n < rend; n++) {
        int g = __ldg(&batch[n]);
        if (g != cur) {
            atomicAdd(&g_pooled[cur * DIM + d0], sum);
            sum = 0.0f;
            cur = g;
        }
        sum += g_h[(size_t)n * DIM + d0];
    }
    atomicAdd(&g_pooled[cur * DIM + d0], sum);
}

__global__ void readout_kernel(const float* __restrict__ bw,
                               const float* __restrict__ sw,
                               const float* __restrict__ sc,
                               float* __restrict__ out) {
    __shared__ float feat[KDIM];
    __shared__ float sred[NCLS * 4];
    int g = blockIdx.x, t = threadIdx.x;
    float xv = g_pooled[g * DIM + t];
    feat[t] = xv / (1.0f + expf(-xv));
    float bs[7];
    bsplines7(xv, bs);
#pragma unroll
    for (int b = 0; b < 7; b++) feat[DIM + t * 7 + b] = bs[b];
    __syncthreads();

    float accv[NCLS];
#pragma unroll
    for (int o = 0; o < NCLS; o++) accv[o] = 0.0f;
#pragma unroll
    for (int kk = 0; kk < 8; kk++) {
        int k = kk * DIM + t;
        float f = feat[k];
        if (k < DIM) {
#pragma unroll
            for (int o = 0; o < NCLS; o++) accv[o] += f * bw[o * DIM + k];
        } else {
            int j = (k - DIM) / 7, b = (k - DIM) % 7;
#pragma unroll
            for (int o = 0; o < NCLS; o++)
                accv[o] += f * sw[o * DIM * NB + j * NB + b] * sc[o * DIM + j];
        }
    }
    int lane = t & 31, warp = t >> 5;
#pragma unroll
    for (int o = 0; o < NCLS; o++) {
        float v = accv[o];
#pragma unroll
        for (int off = 16; off >= 1; off >>= 1) v += __shfl_xor_sync(0xffffffffu, v, off);
        if (lane == 0) sred[o * 4 + warp] = v;
    }
    __syncthreads();
    if (t == 0) {
        float lg[NCLS];
        float mx = -1e30f;
#pragma unroll
        for (int o = 0; o < NCLS; o++) {
            lg[o] = sred[o * 4] + sred[o * 4 + 1] + sred[o * 4 + 2] + sred[o * 4 + 3];
            mx = fmaxf(mx, lg[o]);
        }
        float se = 0.0f;
#pragma unroll
        for (int o = 0; o < NCLS; o++) se += expf(lg[o] - mx);
        float lse = logf(se) + mx;
#pragma unroll
        for (int o = 0; o < NCLS; o++) out[g * NCLS + o] = lg[o] - lse;
    }
}

// ---------------- launch ----------------
extern "C" void kernel_launch(void* const* d_in, const int* in_sizes, int n_in,
                              void* d_out, int out_size) {
    const float* x        = (const float*)d_in[0];
    const int*   ei       = (const int*)d_in[1];
    const int*   batch    = (const int*)d_in[2];
    const float* base_w   = (const float*)d_in[3];
    const float* spline_w = (const float*)d_in[4];
    const float* scaler   = (const float*)d_in[5];
    const float* att_src  = (const float*)d_in[6];
    const float* att_dst  = (const float*)d_in[7];
    const float* bias     = (const float*)d_in[8];
    const float* ro_bw    = (const float*)d_in[9];
    const float* ro_sw    = (const float*)d_in[10];
    const float* ro_sc    = (const float*)d_in[11];
    float* out = (float*)d_out;

    cudaFuncSetAttribute(fkan_gemm_mma, cudaFuncAttributeMaxDynamicSharedMemorySize, SMEM_BYTES);

    float *hbuf = nullptr, *poolp = nullptr;
    int* degp = nullptr;
    __half* wp = nullptr;
    cudaGetSymbolAddress((void**)&hbuf, g_h);
    cudaGetSymbolAddress((void**)&poolp, g_pooled);
    cudaGetSymbolAddress((void**)&degp, g_deg);
    cudaGetSymbolAddress((void**)&wp, g_W16);

    // side stream + events (created once, on the uncaptured correctness call;
    // reused inside graph capture as a fork/join — no allocation thereafter)
    static cudaStream_t s_side = nullptr;
    static cudaEvent_t ev_fork = nullptr, ev_join = nullptr;
    if (s_side == nullptr) {
        cudaStreamCreateWithFlags(&s_side, cudaStreamNonBlocking);
        cudaEventCreateWithFlags(&ev_fork, cudaEventDisableTiming);
        cudaEventCreateWithFlags(&ev_join, cudaEventDisableTiming);
    }

    const int E_BLOCKS = (ETOT + 255) / 256;

    // ---- fork: CSR build + pooled zero on side stream ----
    cudaEventRecord(ev_fork, 0);
    cudaStreamWaitEvent(s_side, ev_fork, 0);
    cudaMemsetAsync(degp, 0, NNODES * sizeof(int), s_side);
    deg_count_kernel<<<E_BLOCKS, 256, 0, s_side>>>(ei);
    scan1_kernel<<<SCAN_BLOCKS, 1024, 0, s_side>>>();
    scan2_kernel<<<1, 32, 0, s_side>>>();
    scan3_kernel<<<SCAN_BLOCKS, 1024, 0, s_side>>>();
    scatter_kernel<<<E_BLOCKS, 256, 0, s_side>>>(ei);
    cudaMemsetAsync(poolp, 0, (size_t)NGR * DIM * sizeof(float), s_side);
    cudaEventRecord(ev_join, s_side);

    // ---- main stream: pack all layers, layer-0 GEMM (independent of CSR) ----
    pack_w_kernel<<<(NLAYER * KDIM * DIM + 255) / 256, 256>>>(base_w, spline_w, scaler);
    fkan_gemm_mma<<<MTILES, 256, SMEM_BYTES>>>(x, att_src, att_dst, wp);

    // join: edge phase needs the CSR
    cudaStreamWaitEvent(0, ev_join, 0);
    edge_fused_kernel<<<(NNODES * 32 + 255) / 256, 256>>>(bias);

    for (int l = 1; l < NLAYER; l++) {
        fkan_gemm_mma<<<MTILES, 256, SMEM_BYTES>>>(
            hbuf, att_src + (size_t)l * DIM, att_dst + (size_t)l * DIM,
            wp + (size_t)l * KDIM * DIM);
        edge_fused_kernel<<<(NNODES * 32 + 255) / 256, 256>>>(bias + (size_t)l * DIM);
    }
    pool_kernel<<<(NNODES + 511) / 512, DIM>>>(batch);
    readout_kernel<<<NGR, DIM>>>(ro_bw, ro_sw, ro_sc, out);
}

// round 15
// speedup vs baseline: 1.6867x; 1.0012x over previous
#include <cuda_runtime.h>
#include <cuda_fp16.h>
#include <cstdint>

#define NNODES 50000
#define NEDGE  800000
#define ETOT   850000
#define DIM    128
#define NH     4
#define NB     7
#define KDIM   1024
#define NGR    64
#define NCLS   10
#define NLAYER 3

#define MTILES ((NNODES + 127) / 128)   // 391
#define SCAN_BLOCKS ((NNODES + 1023) / 1024)  // 49

// ---------------- device scratch ----------------
__device__ __align__(16) __half g_W16[NLAYER * KDIM * DIM];   // packed fp16 weights [l][n][k]
__device__ __align__(16) float g_h[NNODES * DIM];
__device__ __align__(16) __half g_hl16[NNODES * DIM];         // GEMM output, fp16 (edge gather)
__device__ __align__(16) float g_asrc[NNODES * NH];
__device__ __align__(16) float g_adst[NNODES * NH];
__device__ __align__(16) float g_pooled[NGR * DIM];
// CSR
__device__ int g_deg[NNODES];
__device__ int g_ptr[NNODES + 1];
__device__ int g_cur[NNODES];
__device__ int g_csrc[ETOT];
__device__ int g_bsum[SCAN_BLOCKS];
__device__ int g_boff[SCAN_BLOCKS];

// ---------------- helpers ----------------
__device__ __forceinline__ uint32_t smem_u32(const void* p) {
    uint32_t a;
    asm("{ .reg .u64 t; cvta.to.shared.u64 t, %1; cvt.u32.u64 %0, t; }" : "=r"(a) : "l"(p));
    return a;
}

// 16B-chunk swizzle within a 64B row (4 chunks): conflict-free for stores + ldmatrix
#define SWZ32(c, r) (((c) ^ ((r) >> 1)) & 3)

__device__ __forceinline__ void ldsm4(uint32_t a, uint32_t& r0, uint32_t& r1,
                                      uint32_t& r2, uint32_t& r3) {
    asm volatile("ldmatrix.sync.aligned.m8n8.x4.shared.b16 {%0,%1,%2,%3}, [%4];"
                 : "=r"(r0), "=r"(r1), "=r"(r2), "=r"(r3) : "r"(a));
}

__device__ __forceinline__ void mma16816(float* d, const uint32_t* a, const uint32_t* b) {
    asm volatile("mma.sync.aligned.m16n8k16.row.col.f32.f16.f16.f32 "
                 "{%0,%1,%2,%3}, {%4,%5,%6,%7}, {%8,%9}, {%0,%1,%2,%3};"
                 : "+f"(d[0]), "+f"(d[1]), "+f"(d[2]), "+f"(d[3])
                 : "r"(a[0]), "r"(a[1]), "r"(a[2]), "r"(a[3]), "r"(b[0]), "r"(b[1]));
}

__device__ __forceinline__ float silu_f(float x) { return x / (1.0f + __expf(-x)); }

// Cubic B-splines (Cox-de Boor recursion) — used only in small readout kernel.
__device__ __forceinline__ void bsplines7(float x, float* out) {
    float b0[10];
#pragma unroll
    for (int i = 0; i < 10; i++) {
        float g0 = 0.5f * (float)i - 2.5f;
        b0[i] = (x >= g0 && x < g0 + 0.5f) ? 1.0f : 0.0f;
    }
    float b1[9];
#pragma unroll
    for (int i = 0; i < 9; i++) {
        float gi = 0.5f * (float)i - 2.5f;
        b1[i] = (x - gi) * 2.0f * b0[i] + ((gi + 1.0f) - x) * 2.0f * b0[i + 1];
    }
    float b2[8];
#pragma unroll
    for (int i = 0; i < 8; i++) {
        float gi = 0.5f * (float)i - 2.5f;
        b2[i] = (x - gi) * b1[i] + ((gi + 1.5f) - x) * b1[i + 1];
    }
#pragma unroll
    for (int i = 0; i < 7; i++) {
        float gi = 0.5f * (float)i - 2.5f;
        out[i] = ((x - gi) * b2[i] + ((gi + 2.0f) - x) * b2[i + 1]) * (1.0f / 1.5f);
    }
}

__device__ __forceinline__ uint32_t pack_f16x2(float a, float b) {
    uint32_t r;
    asm("cvt.rn.f16x2.f32 %0, %1, %2;" : "=r"(r) : "f"(b), "f"(a));
    return r;
}

// ---------------- CSR build ----------------
__global__ void deg_count_kernel(const int* __restrict__ ei) {
    int e = blockIdx.x * blockDim.x + threadIdx.x;
    if (e >= ETOT) return;
    int d = (e < NEDGE) ? __ldg(&ei[NEDGE + e]) : (e - NEDGE);
    atomicAdd(&g_deg[d], 1);
}

__global__ void scan1_kernel() {
    __shared__ int sh[1024];
    int t = threadIdx.x, b = blockIdx.x;
    int i = b * 1024 + t;
    int v = (i < NNODES) ? g_deg[i] : 0;
    sh[t] = v;
    __syncthreads();
#pragma unroll
    for (int off = 1; off < 1024; off <<= 1) {
        int add = (t >= off) ? sh[t - off] : 0;
        __syncthreads();
        sh[t] += add;
        __syncthreads();
    }
    if (i < NNODES) g_ptr[i] = sh[t] - v;
    if (t == 1023) g_bsum[b] = sh[t];
}

__global__ void scan2_kernel() {
    if (threadIdx.x == 0) {
        int run = 0;
        for (int b = 0; b < SCAN_BLOCKS; b++) { g_boff[b] = run; run += g_bsum[b]; }
        g_ptr[NNODES] = run;
    }
}

__global__ void scan3_kernel() {
    int t = threadIdx.x, b = blockIdx.x;
    int i = b * 1024 + t;
    if (i < NNODES) {
        int p = g_ptr[i] + g_boff[b];
        g_ptr[i] = p;
        g_cur[i] = p;
    }
}

__global__ void scatter_kernel(const int* __restrict__ ei) {
    int e = blockIdx.x * blockDim.x + threadIdx.x;
    if (e >= ETOT) return;
    int s, d;
    if (e < NEDGE) { s = __ldg(&ei[e]); d = __ldg(&ei[NEDGE + e]); }
    else           { s = e - NEDGE; d = s; }
    int pos = atomicAdd(&g_cur[d], 1);
    g_csrc[pos] = s;
}

// ---------------- weight pack (all 3 layers, once, fp16) ----------------
__global__ void pack_w_kernel(const float* __restrict__ bw,
                              const float* __restrict__ sw,
                              const float* __restrict__ sc) {
    int idx = blockIdx.x * blockDim.x + threadIdx.x;
    if (idx >= NLAYER * KDIM * DIM) return;
    int l = idx >> 17;
    int rem = idx & (KDIM * DIM - 1);
    int n = rem >> 10, k = rem & 1023;
    int j = k >> 3, f = k & 7;
    const float* bwl = bw + (size_t)l * DIM * DIM;
    const float* swl = sw + (size_t)l * DIM * DIM * NB;
    const float* scl = sc + (size_t)l * DIM * DIM;
    float v;
    if (f == 0) v = bwl[n * DIM + j];
    else        v = swl[(n * DIM + j) * NB + (f - 1)] * scl[n * DIM + j];
    g_W16[idx] = __float2half_rn(v);
}

// ---------------- fused KAN-GEMM: pipelined double-buffered fp16 mma (single product) ----
// Buffer layout (per 16KB buffer): A[0,8K) B[8K,16K)
// Tiles: 128 rows x 32 k (64B/row, 4 swizzled 16B chunks).
#define SMEM_BYTES 32768

__device__ __forceinline__ void build_chunk(const float* __restrict__ in,
                                            const __half* __restrict__ W16,
                                            char* buf, int m0, int tid, int cc, bool rvalid) {
    char* Ab = buf;
    char* Bb = buf + 8192;

    // B weights: LDG first (latency hidden behind feature math)
    int n = tid >> 1, half = tid & 1;
    const uint4* wh = (const uint4*)(W16 + (size_t)n * KDIM + cc * 32 + half * 16);
    uint4 bh0 = wh[0], bh1 = wh[1];

    // A features: 2 evals per thread. Closed-form cardinal cubic B-spline with
    // direct scatter of the <=4 nonzero bases — no select chain, no packing of zeros.
    int row = tid & 127, jp = tid >> 7;
    float2 xv2 = rvalid ? *(const float2*)(in + (size_t)(m0 + row) * DIM + cc * 4 + jp * 2)
                        : make_float2(0.f, 0.f);
#pragma unroll
    for (int q = 0; q < 2; q++) {
        float xv = q ? xv2.y : xv2.x;
        int cch = jp * 2 + q;
        uint32_t off = row * 64 + (SWZ32(cch, row) << 4);

        // silu (fp16) in slot 0, zero-fill rest of the 16B chunk
        float sv = silu_f(xv);
        uint32_t sp = pack_f16x2(sv, 0.0f);   // low half = silu, high = 0
        *(uint4*)(Ab + off) = make_uint4(sp & 0xFFFFu, 0u, 0u, 0u);

        // spline cell + 4 nonzero weights (closed form)
        float u = fmaf(2.0f, xv, 5.0f);
        float cf = floorf(u);
        float t = u - cf;
        bool inr = (u >= 0.0f) && (u < 10.0f);
        int c = (int)cf;
        float t2 = t * t, t3 = t2 * t, s1 = 1.0f - t;
        const float i6 = 1.0f / 6.0f;
        float w[4];
        w[0] = t3 * i6;                                                    // j == c
        w[1] = fmaf(-3.0f, t3, fmaf(3.0f, t2, fmaf(3.0f, t, 1.0f))) * i6; // j == c-1
        w[2] = fmaf(3.0f, t3, fmaf(-6.0f, t2, 4.0f)) * i6;                // j == c-2
        w[3] = s1 * s1 * s1 * i6;                                         // j == c-3
#pragma unroll
        for (int m = 0; m < 4; m++) {
            int j = c - m;
            if (inr && j >= 0 && j <= 6) {
                __half hw = __float2half_rn(w[m]);
                *(uint16_t*)(Ab + off + 2 * (j + 1)) = __half_as_ushort(hw);
            }
        }
    }
#pragma unroll
    for (int q = 0; q < 2; q++) {
        int c = half * 2 + q;
        uint32_t off = n * 64 + (SWZ32(c, n) << 4);
        *(uint4*)(Bb + off) = q ? bh1 : bh0;
    }
}

__global__ void __launch_bounds__(256, 2) fkan_gemm_mma(const float* __restrict__ in,
                                                        const float* __restrict__ attS,
                                                        const float* __restrict__ attD,
                                                        const __half* __restrict__ W16) {
    extern __shared__ char dsm[];
    int tid = threadIdx.x;
    int wid = tid >> 5, lane = tid & 31;
    int m0 = blockIdx.x * 128;
    int warpM = wid & 3, warpN = wid >> 2;
    uint32_t ubase = smem_u32(dsm);

    bool rvalid = (m0 + (tid & 127)) < NNODES;
    int tg = lane >> 3, tr = lane & 7;

    float acc[2][8][4];
#pragma unroll
    for (int f = 0; f < 2; f++)
#pragma unroll
        for (int j = 0; j < 8; j++)
#pragma unroll
            for (int q = 0; q < 4; q++) acc[f][j][q] = 0.0f;

    // prologue: build chunk 0 into buffer 0
    build_chunk(in, W16, dsm, m0, tid, 0, rvalid);
    __syncthreads();

    for (int cc = 0; cc < 32; cc++) {
        int p = cc & 1;
        uint32_t uA = ubase + p * 16384;
        uint32_t uB = uA + 8192;

        // ---- mma for chunk cc (tensor pipe) ----
#pragma unroll
        for (int ks = 0; ks < 2; ks++) {
            uint32_t ah[2][4];
#pragma unroll
            for (int f = 0; f < 2; f++) {
                int arow = warpM * 32 + f * 16 + (tg & 1) * 8 + tr;
                int ac = ks * 2 + (tg >> 1);
                uint32_t aoff = arow * 64 + (SWZ32(ac, arow) << 4);
                ldsm4(uA + aoff, ah[f][0], ah[f][1], ah[f][2], ah[f][3]);
            }
#pragma unroll
            for (int gh = 0; gh < 2; gh++) {
                uint32_t bh[2][4];
#pragma unroll
                for (int gg = 0; gg < 2; gg++) {
                    int g = gh * 2 + gg;
                    int brow = warpN * 64 + g * 16 + (tg >> 1) * 8 + tr;
                    int bc = ks * 2 + (tg & 1);
                    uint32_t boff = brow * 64 + (SWZ32(bc, brow) << 4);
                    ldsm4(uB + boff, bh[gg][0], bh[gg][1], bh[gg][2], bh[gg][3]);
                }
#pragma unroll
                for (int f = 0; f < 2; f++)
#pragma unroll
                    for (int gg = 0; gg < 2; gg++) {
                        int g = gh * 2 + gg;
                        mma16816(acc[f][2 * g],     ah[f], &bh[gg][0]);
                        mma16816(acc[f][2 * g + 1], ah[f], &bh[gg][2]);
                    }
            }
        }

        // ---- build chunk cc+1 into the other buffer (fma pipe, overlaps tensor) ----
        if (cc < 31)
            build_chunk(in, W16, dsm + (p ^ 1) * 16384, m0, tid, cc + 1, rvalid);
        __syncthreads();
    }

    // ---- epilogue: store h (fp16) + fused attention dots (fp32 regs) ----
    int qd = lane >> 2, ql = lane & 3;
#pragma unroll
    for (int f = 0; f < 2; f++)
#pragma unroll
        for (int hh = 0; hh < 2; hh++) {
            int row = m0 + warpM * 32 + f * 16 + hh * 8 + qd;
            bool ok = row < NNODES;
            float ps0 = 0.f, pd0 = 0.f, ps1 = 0.f, pd1 = 0.f;
#pragma unroll
            for (int j = 0; j < 8; j++) {
                int col = warpN * 64 + j * 8 + ql * 2;
                float v0 = acc[f][j][hh * 2 + 0];
                float v1 = acc[f][j][hh * 2 + 1];
                if (ok) {
                    __half2 hv = __floats2half2_rn(v0, v1);
                    *(__half2*)&g_hl16[(size_t)row * DIM + col] = hv;
                }
                float s0 = __ldg(&attS[col]), s1 = __ldg(&attS[col + 1]);
                float d0 = __ldg(&attD[col]), d1 = __ldg(&attD[col + 1]);
                float ps = v0 * s0 + v1 * s1;
                float pd = v0 * d0 + v1 * d1;
                if (j < 4) { ps0 += ps; pd0 += pd; } else { ps1 += ps; pd1 += pd; }
            }
#pragma unroll
            for (int o = 1; o <= 2; o <<= 1) {
                ps0 += __shfl_xor_sync(0xffffffffu, ps0, o);
                pd0 += __shfl_xor_sync(0xffffffffu, pd0, o);
                ps1 += __shfl_xor_sync(0xffffffffu, ps1, o);
                pd1 += __shfl_xor_sync(0xffffffffu, pd1, o);
            }
            if (ql == 0 && ok) {
                int hbase = warpN * 2;
                g_asrc[row * 4 + hbase]     = ps0;
                g_asrc[row * 4 + hbase + 1] = ps1;
                g_adst[row * 4 + hbase]     = pd0;
                g_adst[row * 4 + hbase + 1] = pd1;
            }
        }
}

// ---------------- fused pull-mode edge phase: 2 edges per warp iteration ----------------
// Half-warp hw processes edge i+hw; 16 lanes x 16B (8 fp16 channels) per edge.
__global__ void __launch_bounds__(256) edge_fused_kernel(const float* __restrict__ bias) {
    int gid = blockIdx.x * blockDim.x + threadIdx.x;
    int n = gid >> 5, lane = gid & 31;
    if (n >= NNODES) return;
    int start = __ldg(&g_ptr[n]);
    int end   = __ldg(&g_ptr[n + 1]);
    int hw = lane >> 4;        // which edge of the pair
    int lw = lane & 15;        // channels lw*8 .. lw*8+7
    int hh = lw >> 2;          // head of this channel block
    float bd = g_adst[n * 4 + hh];

    float acc[8];
#pragma unroll
    for (int j = 0; j < 8; j++) acc[j] = 0.0f;
    float sumex = 0.0f;

    for (int j0 = start; j0 < end; j0 += 32) {
        int m = min(32, end - j0);
        int s_pref = (j0 + lane < end) ? __ldg(&g_csrc[j0 + lane]) : 0;
#pragma unroll 4
        for (int i = 0; i < m; i += 2) {
            int idx = i + hw;
            int s = __shfl_sync(0xffffffffu, s_pref, idx & 31);
            if (idx < m) {
                float a = __ldg(&g_asrc[s * 4 + hh]);
                float e = a + bd;
                e = (e > 0.f) ? e : 0.2f * e;
                float ex = __expf(e);
                sumex += ex;
                uint4 hv = *(const uint4*)&g_hl16[(size_t)s * DIM + lw * 8];
                const __half2* hp = (const __half2*)&hv;
#pragma unroll
                for (int q = 0; q < 4; q++) {
                    float2 pp = __half22float2(hp[q]);
                    acc[q * 2]     = fmaf(ex, pp.x, acc[q * 2]);
                    acc[q * 2 + 1] = fmaf(ex, pp.y, acc[q * 2 + 1]);
                }
            }
        }
    }
    // combine the two half-warps
    sumex += __shfl_xor_sync(0xffffffffu, sumex, 16);
#pragma unroll
    for (int j = 0; j < 8; j++) acc[j] += __shfl_xor_sync(0xffffffffu, acc[j], 16);

    if (hw == 0) {
        float inv = 1.0f / (sumex + 1e-16f);
        float4 b0 = *(const float4*)&bias[lw * 8];
        float4 b1 = *(const float4*)&bias[lw * 8 + 4];
        float4 o0, o1;
        o0.x = silu_f(acc[0] * inv + b0.x);
        o0.y = silu_f(acc[1] * inv + b0.y);
        o0.z = silu_f(acc[2] * inv + b0.z);
        o0.w = silu_f(acc[3] * inv + b0.w);
        o1.x = silu_f(acc[4] * inv + b1.x);
        o1.y = silu_f(acc[5] * inv + b1.y);
        o1.z = silu_f(acc[6] * inv + b1.z);
        o1.w = silu_f(acc[7] * inv + b1.w);
        *(float4*)&g_h[(size_t)n * DIM + lw * 8]     = o0;
        *(float4*)&g_h[(size_t)n * DIM + lw * 8 + 4] = o1;
    }
}

// ---------------- pooling + readout ----------------
__global__ void pool_kernel(const int* __restrict__ batch) {
    int d0 = threadIdx.x;
    int r0 = blockIdx.x * 512;
    if (r0 >= NNODES) return;
    int rend = min(r0 + 512, NNODES);
    int cur = __ldg(&batch[r0]);
    float sum = 0.0f;
    for (int n = r0; n < rend; n++) {
        int g = __ldg(&batch[n]);
        if (g != cur) {
            atomicAdd(&g_pooled[cur * DIM + d0], sum);
            sum = 0.0f;
            cur = g;
        }
        sum += g_h[(size_t)n * DIM + d0];
    }
    atomicAdd(&g_pooled[cur * DIM + d0], sum);
}

__global__ void readout_kernel(const float* __restrict__ bw,
                               const float* __restrict__ sw,
                               const float* __restrict__ sc,
                               float* __restrict__ out) {
    __shared__ float feat[KDIM];
    __shared__ float sred[NCLS * 4];
    int g = blockIdx.x, t = threadIdx.x;
    float xv = g_pooled[g * DIM + t];
    feat[t] = xv / (1.0f + expf(-xv));
    float bs[7];
    bsplines7(xv, bs);
#pragma unroll
    for (int b = 0; b < 7; b++) feat[DIM + t * 7 + b] = bs[b];
    __syncthreads();

    float accv[NCLS];
#pragma unroll
    for (int o = 0; o < NCLS; o++) accv[o] = 0.0f;
#pragma unroll
    for (int kk = 0; kk < 8; kk++) {
        int k = kk * DIM + t;
        float f = feat[k];
        if (k < DIM) {
#pragma unroll
            for (int o = 0; o < NCLS; o++) accv[o] += f * bw[o * DIM + k];
        } else {
            int j = (k - DIM) / 7, b = (k - DIM) % 7;
#pragma unroll
            for (int o = 0; o < NCLS; o++)
                accv[o] += f * sw[o * DIM * NB + j * NB + b] * sc[o * DIM + j];
        }
    }
    int lane = t & 31, warp = t >> 5;
#pragma unroll
    for (int o = 0; o < NCLS; o++) {
        float v = accv[o];
#pragma unroll
        for (int off = 16; off >= 1; off >>= 1) v += __shfl_xor_sync(0xffffffffu, v, off);
        if (lane == 0) sred[o * 4 + warp] = v;
    }
    __syncthreads();
    if (t == 0) {
        float lg[NCLS];
        float mx = -1e30f;
#pragma unroll
        for (int o = 0; o < NCLS; o++) {
            lg[o] = sred[o * 4] + sred[o * 4 + 1] + sred[o * 4 + 2] + sred[o * 4 + 3];
            mx = fmaxf(mx, lg[o]);
        }
        float se = 0.0f;
#pragma unroll
        for (int o = 0; o < NCLS; o++) se += expf(lg[o] - mx);
        float lse = logf(se) + mx;
#pragma unroll
        for (int o = 0; o < NCLS; o++) out[g * NCLS + o] = lg[o] - lse;
    }
}

// ---------------- launch ----------------
extern "C" void kernel_launch(void* const* d_in, const int* in_sizes, int n_in,
                              void* d_out, int out_size) {
    const float* x        = (const float*)d_in[0];
    const int*   ei       = (const int*)d_in[1];
    const int*   batch    = (const int*)d_in[2];
    const float* base_w   = (const float*)d_in[3];
    const float* spline_w = (const float*)d_in[4];
    const float* scaler   = (const float*)d_in[5];
    const float* att_src  = (const float*)d_in[6];
    const float* att_dst  = (const float*)d_in[7];
    const float* bias     = (const float*)d_in[8];
    const float* ro_bw    = (const float*)d_in[9];
    const float* ro_sw    = (const float*)d_in[10];
    const float* ro_sc    = (const float*)d_in[11];
    float* out = (float*)d_out;

    cudaFuncSetAttribute(fkan_gemm_mma, cudaFuncAttributeMaxDynamicSharedMemorySize, SMEM_BYTES);

    float *hbuf = nullptr, *poolp = nullptr;
    int* degp = nullptr;
    __half* wp = nullptr;
    cudaGetSymbolAddress((void**)&hbuf, g_h);
    cudaGetSymbolAddress((void**)&poolp, g_pooled);
    cudaGetSymbolAddress((void**)&degp, g_deg);
    cudaGetSymbolAddress((void**)&wp, g_W16);

    // side stream + events (created once, on the uncaptured correctness call;
    // reused inside graph capture as a fork/join — no allocation thereafter)
    static cudaStream_t s_side = nullptr;
    static cudaEvent_t ev_fork = nullptr, ev_join = nullptr;
    if (s_side == nullptr) {
        cudaStreamCreateWithFlags(&s_side, cudaStreamNonBlocking);
        cudaEventCreateWithFlags(&ev_fork, cudaEventDisableTiming);
        cudaEventCreateWithFlags(&ev_join, cudaEventDisableTiming);
    }

    const int E_BLOCKS = (ETOT + 255) / 256;

    // ---- fork: CSR build + pooled zero on side stream ----
    cudaEventRecord(ev_fork, 0);
    cudaStreamWaitEvent(s_side, ev_fork, 0);
    cudaMemsetAsync(degp, 0, NNODES * sizeof(int), s_side);
    deg_count_kernel<<<E_BLOCKS, 256, 0, s_side>>>(ei);
    scan1_kernel<<<SCAN_BLOCKS, 1024, 0, s_side>>>();
    scan2_kernel<<<1, 32, 0, s_side>>>();
    scan3_kernel<<<SCAN_BLOCKS, 1024, 0, s_side>>>();
    scatter_kernel<<<E_BLOCKS, 256, 0, s_side>>>(ei);
    cudaMemsetAsync(poolp, 0, (size_t)NGR * DIM * sizeof(float), s_side);
    cudaEventRecord(ev_join, s_side);

    // ---- main stream: pack all layers, layer-0 GEMM (independent of CSR) ----
    pack_w_kernel<<<(NLAYER * KDIM * DIM + 255) / 256, 256>>>(base_w, spline_w, scaler);
    fkan_gemm_mma<<<MTILES, 256, SMEM_BYTES>>>(x, att_src, att_dst, wp);

    // join: edge phase needs the CSR
    cudaStreamWaitEvent(0, ev_join, 0);
    edge_fused_kernel<<<(NNODES * 32 + 255) / 256, 256>>>(bias);

    for (int l = 1; l < NLAYER; l++) {
        fkan_gemm_mma<<<MTILES, 256, SMEM_BYTES>>>(
            hbuf, att_src + (size_t)l * DIM, att_dst + (size_t)l * DIM,
            wp + (size_t)l * KDIM * DIM);
        edge_fused_kernel<<<(NNODES * 32 + 255) / 256, 256>>>(bias + (size_t)l * DIM);
    }
    pool_kernel<<<(NNODES + 511) / 512, DIM>>>(batch);
    readout_kernel<<<NGR, DIM>>>(ro_bw, ro_sw, ro_sc, out);
}